// round 6
// baseline (speedup 1.0000x reference)
#include <cuda_runtime.h>
#include <cuda_bf16.h>
#include <cstdint>

#define BATCH 4
#define SEQ   2048
#define DIM   1024

typedef __nv_bfloat16 bf16;

// ---------------- scratch (device globals; allocation-free) ----------------
__device__ __align__(128) bf16  g_xh[(long)BATCH*SEQ*DIM];
__device__ __align__(128) bf16  g_xl[(long)BATCH*SEQ*DIM];
__device__ __align__(128) bf16  g_wh[3][(long)DIM*DIM];
__device__ __align__(128) bf16  g_wl[3][(long)DIM*DIM];
__device__ __align__(128) bf16  g_qh[(long)BATCH*SEQ*DIM];
__device__ __align__(128) bf16  g_ql[(long)BATCH*SEQ*DIM];
__device__ __align__(128) bf16  g_kh[(long)BATCH*SEQ*DIM];
__device__ __align__(128) bf16  g_kl[(long)BATCH*SEQ*DIM];
__device__ __align__(128) bf16  g_vth[(long)BATCH*SEQ*DIM];   // V^T: [b][e][s]
__device__ __align__(128) bf16  g_vtl[(long)BATCH*SEQ*DIM];
__device__ __align__(128) float g_sc [(long)BATCH*SEQ*SEQ];
__device__ __align__(128) bf16  g_ph [(long)BATCH*SEQ*SEQ];
__device__ __align__(128) bf16  g_pl [(long)BATCH*SEQ*SEQ];

// ---------------- PTX helpers (arch-generic; NO tcgen05) ----------------
__device__ __forceinline__ uint32_t smem_u32(const void* p) {
    uint32_t a;
    asm("{ .reg .u64 t; cvta.to.shared.u64 t, %1; cvt.u32.u64 %0, t; }" : "=r"(a) : "l"(p));
    return a;
}
__device__ __forceinline__ void cp16(uint32_t saddr, const void* g) {
    asm volatile("cp.async.cg.shared.global [%0], [%1], 16;" :: "r"(saddr), "l"(g) : "memory");
}
#define CP_COMMIT() asm volatile("cp.async.commit_group;" ::: "memory")

__device__ __forceinline__ void ldsm_x4(uint32_t* r, uint32_t addr) {
    asm volatile("ldmatrix.sync.aligned.m8n8.x4.shared.b16 {%0,%1,%2,%3}, [%4];"
        : "=r"(r[0]), "=r"(r[1]), "=r"(r[2]), "=r"(r[3]) : "r"(addr));
}
__device__ __forceinline__ void mma16816(float* c, const uint32_t* a, const uint32_t* b) {
    asm volatile("mma.sync.aligned.m16n8k16.row.col.f32.bf16.bf16.f32 "
        "{%0,%1,%2,%3}, {%4,%5,%6,%7}, {%8,%9}, {%0,%1,%2,%3};"
        : "+f"(c[0]), "+f"(c[1]), "+f"(c[2]), "+f"(c[3])
        : "r"(a[0]), "r"(a[1]), "r"(a[2]), "r"(a[3]), "r"(b[0]), "r"(b[1]));
}

// byte offset inside an 8KB tile of [128 rows][32 bf16], 64B rows,
// 16B chunks XOR-swizzled for conflict-free ldmatrix + stores
__device__ __forceinline__ uint32_t swz(int row, int kc) {
    return (uint32_t)(row * 64 + ((kc ^ ((row >> 1) & 3)) << 4));
}

// ---------------- SMEM layout ----------------
// mainloop: 3 stages x 32KB: [Ahi 8K | Alo 8K | Bhi 8K | Blo 8K]
// epilogue: float buf[128][EPI_LD] overlaps stage memory
#define STAGES 3
#define STAGE_BYTES 32768
#define EPI_LD 132
#define SMEM_TOTAL (STAGES * STAGE_BYTES)   // 98304 >= 128*132*4 = 67584

// =====================================================================
// bf16x3 NT GEMM via mma.sync:  C_tile[128,128] = A[128,K] @ B[128,K]^T
// mode 0: fp32 C;  mode 1: bf16 hi/lo C;  mode 2: bf16 hi/lo C transposed
// =====================================================================
__global__ void __launch_bounds__(256, 2) gemm_bf16x3(
    const bf16* __restrict__ Ahi, const bf16* __restrict__ Alo,
    const bf16* __restrict__ Bhi, const bf16* __restrict__ Blo,
    float* __restrict__ Cf, bf16* __restrict__ Chi, bf16* __restrict__ Clo,
    int K, int ldA, int ldB, int ldC,
    long strideA, long strideB, long strideC,
    int causal, int kclamp, int mode)
{
    const int bx = blockIdx.x, by = blockIdx.y, bz = blockIdx.z;
    if (causal && bx > by) return;

    extern __shared__ char smem[];
    const uint32_t sbase = smem_u32(smem);
    const int tid  = threadIdx.x;
    const int lane = tid & 31;
    const int wid  = tid >> 5;
    const int wm   = wid >> 2;   // 0..1 : 64 rows
    const int wn   = wid & 3;    // 0..3 : 32 cols

    const int kmax    = kclamp ? min(K, (by + 1) * 128) : K;
    const int nchunks = kmax >> 5;                // BK = 32

    const bf16* pAh = Ahi + bz * strideA + (long)by * 128 * ldA;
    const bf16* pAl = Alo + bz * strideA + (long)by * 128 * ldA;
    const bf16* pBh = Bhi + bz * strideB + (long)bx * 128 * ldB;
    const bf16* pBl = Blo + bz * strideB + (long)bx * 128 * ldB;

    // per-thread load coords: 512 16B-chunks per 8KB tile, 2 per thread
    const int l_row0 = tid >> 2,         l_kc0 = tid & 3;
    const int l_row1 = (tid + 256) >> 2, l_kc1 = (tid + 256) & 3;

    auto load_chunk = [&](int c) {
        const uint32_t st = sbase + (uint32_t)(c % STAGES) * STAGE_BYTES;
        const int k0 = c << 5;
        {
            long gA = (long)l_row0 * ldA + k0 + l_kc0 * 8;
            long gB = (long)l_row0 * ldB + k0 + l_kc0 * 8;
            uint32_t so = swz(l_row0, l_kc0);
            cp16(st +         so, pAh + gA);
            cp16(st +  8192 + so, pAl + gA);
            cp16(st + 16384 + so, pBh + gB);
            cp16(st + 24576 + so, pBl + gB);
        }
        {
            long gA = (long)l_row1 * ldA + k0 + l_kc1 * 8;
            long gB = (long)l_row1 * ldB + k0 + l_kc1 * 8;
            uint32_t so = swz(l_row1, l_kc1);
            cp16(st +         so, pAh + gA);
            cp16(st +  8192 + so, pAl + gA);
            cp16(st + 16384 + so, pBh + gB);
            cp16(st + 24576 + so, pBl + gB);
        }
        CP_COMMIT();
    };

    float acc[4][4][4];
    #pragma unroll
    for (int i = 0; i < 4; i++)
        #pragma unroll
        for (int j = 0; j < 4; j++)
            #pragma unroll
            for (int p = 0; p < 4; p++) acc[i][j][p] = 0.f;

    // prologue: fill 2 of 3 stages
    load_chunk(0);
    if (nchunks > 1) load_chunk(1);

    const int lrow = lane & 15;
    const int lsel = lane >> 4;
    const int arow = wm * 64 + lrow;   // base A row for this lane

    for (int c = 0; c < nchunks; c++) {
        if (c + 1 < nchunks) asm volatile("cp.async.wait_group 1;" ::: "memory");
        else                 asm volatile("cp.async.wait_group 0;" ::: "memory");
        __syncthreads();   // single barrier per chunk: also retires all reads
                           // of stage (c-1)%3, which load_chunk(c+2) overwrites.

        if (c + 2 < nchunks) load_chunk(c + 2);

        const uint32_t st  = sbase + (uint32_t)(c % STAGES) * STAGE_BYTES;
        const uint32_t sAh = st, sAl = st + 8192, sBh = st + 16384, sBl = st + 24576;

        #pragma unroll
        for (int ks = 0; ks < 2; ks++) {
            const int kc = ks * 2 + lsel;
            uint32_t bh[4][2], bl[4][2];
            #pragma unroll
            for (int np = 0; np < 2; np++) {
                int r = wn * 32 + np * 16 + lrow;
                uint32_t t4[4];
                ldsm_x4(t4, sBh + swz(r, kc));
                bh[np*2][0] = t4[0]; bh[np*2][1] = t4[2];
                bh[np*2+1][0] = t4[1]; bh[np*2+1][1] = t4[3];
                ldsm_x4(t4, sBl + swz(r, kc));
                bl[np*2][0] = t4[0]; bl[np*2][1] = t4[2];
                bl[np*2+1][0] = t4[1]; bl[np*2+1][1] = t4[3];
            }
            // double-buffered A fragments: prefetch mt+1 before mt's MMAs
            uint32_t aH[2][4], aL[2][4];
            ldsm_x4(aH[0], sAh + swz(arow, kc));
            ldsm_x4(aL[0], sAl + swz(arow, kc));
            #pragma unroll
            for (int mt = 0; mt < 4; mt++) {
                const int cur = mt & 1, nxt = cur ^ 1;
                if (mt < 3) {
                    ldsm_x4(aH[nxt], sAh + swz(arow + (mt + 1) * 16, kc));
                    ldsm_x4(aL[nxt], sAl + swz(arow + (mt + 1) * 16, kc));
                }
                #pragma unroll
                for (int nt = 0; nt < 4; nt++) {
                    mma16816(acc[mt][nt], aH[cur], bh[nt]);
                    mma16816(acc[mt][nt], aH[cur], bl[nt]);
                    mma16816(acc[mt][nt], aL[cur], bh[nt]);
                }
            }
        }
    }

    // ---- epilogue: stage fp32 tile in smem, then coalesced global writes ----
    __syncthreads();   // protect stage memory before reuse as epilogue buffer
    float* buf = (float*)smem;
    {
        const int rq = lane >> 2;          // 0..7
        const int cq = (lane & 3) * 2;     // 0,2,4,6
        #pragma unroll
        for (int mt = 0; mt < 4; mt++)
            #pragma unroll
            for (int nt = 0; nt < 4; nt++) {
                int r0 = wm * 64 + mt * 16 + rq;
                int c0 = wn * 32 + nt * 8 + cq;
                *(float2*)&buf[r0 * EPI_LD + c0]       = make_float2(acc[mt][nt][0], acc[mt][nt][1]);
                *(float2*)&buf[(r0 + 8) * EPI_LD + c0] = make_float2(acc[mt][nt][2], acc[mt][nt][3]);
            }
    }
    __syncthreads();

    if (mode == 0) {
        int r = tid >> 1, c0 = (tid & 1) * 64;
        long row = (long)by * 128 + r;
        float4* dst = (float4*)(Cf + bz * strideC + row * ldC + (long)bx * 128 + c0);
        #pragma unroll
        for (int i = 0; i < 16; i++)
            dst[i] = *(float4*)&buf[r * EPI_LD + c0 + i * 4];
    } else if (mode == 1) {
        int r = tid >> 1, c0 = (tid & 1) * 64;
        long row = (long)by * 128 + r;
        bf16* dh = Chi + bz * strideC + row * ldC + (long)bx * 128 + c0;
        bf16* dl = Clo + bz * strideC + row * ldC + (long)bx * 128 + c0;
        #pragma unroll
        for (int v = 0; v < 8; v++) {
            uint4 uh, ul;
            uint32_t* ph = (uint32_t*)&uh; uint32_t* pl = (uint32_t*)&ul;
            #pragma unroll
            for (int p = 0; p < 4; p++) {
                float f0 = buf[r * EPI_LD + c0 + v * 8 + p * 2];
                float f1 = buf[r * EPI_LD + c0 + v * 8 + p * 2 + 1];
                bf16 h0 = __float2bfloat16(f0), h1 = __float2bfloat16(f1);
                bf16 l0 = __float2bfloat16(f0 - __bfloat162float(h0));
                bf16 l1 = __float2bfloat16(f1 - __bfloat162float(h1));
                ph[p] = (uint32_t)*(uint16_t*)&h0 | ((uint32_t)*(uint16_t*)&h1 << 16);
                pl[p] = (uint32_t)*(uint16_t*)&l0 | ((uint32_t)*(uint16_t*)&l1 << 16);
            }
            *(uint4*)(dh + v * 8) = uh;
            *(uint4*)(dl + v * 8) = ul;
        }
    } else {
        // transposed hi/lo out: Ct[e][s_local], batch derived from global row
        int cc = tid >> 1, s0 = (tid & 1) * 64;
        int rowbase = by * 128;
        int b = rowbase / SEQ;
        int sloc = (rowbase % SEQ) + s0;
        long e = (long)bx * 128 + cc;
        bf16* dh = Chi + b * strideC + e * ldC + sloc;
        bf16* dl = Clo + b * strideC + e * ldC + sloc;
        #pragma unroll
        for (int v = 0; v < 8; v++) {
            uint4 uh, ul;
            uint32_t* ph = (uint32_t*)&uh; uint32_t* pl = (uint32_t*)&ul;
            #pragma unroll
            for (int p = 0; p < 4; p++) {
                float f0 = buf[(s0 + v * 8 + p * 2)     * EPI_LD + cc];
                float f1 = buf[(s0 + v * 8 + p * 2 + 1) * EPI_LD + cc];
                bf16 h0 = __float2bfloat16(f0), h1 = __float2bfloat16(f1);
                bf16 l0 = __float2bfloat16(f0 - __bfloat162float(h0));
                bf16 l1 = __float2bfloat16(f1 - __bfloat162float(h1));
                ph[p] = (uint32_t)*(uint16_t*)&h0 | ((uint32_t)*(uint16_t*)&h1 << 16);
                pl[p] = (uint32_t)*(uint16_t*)&l0 | ((uint32_t)*(uint16_t*)&l1 << 16);
            }
            *(uint4*)(dh + v * 8) = uh;
            *(uint4*)(dl + v * 8) = ul;
        }
    }
}

// ---------------- fp32 -> bf16 hi/lo split ----------------
__device__ __forceinline__ void split4(const float* __restrict__ src,
                                       bf16* __restrict__ hi, bf16* __restrict__ lo, long i)
{
    float4 v = *(const float4*)(src + i);
    float f[4] = {v.x, v.y, v.z, v.w};
    uint32_t h2[2], l2[2];
    #pragma unroll
    for (int p = 0; p < 2; p++) {
        bf16 h0 = __float2bfloat16(f[p*2]),   h1 = __float2bfloat16(f[p*2+1]);
        bf16 l0 = __float2bfloat16(f[p*2]   - __bfloat162float(h0));
        bf16 l1 = __float2bfloat16(f[p*2+1] - __bfloat162float(h1));
        h2[p] = (uint32_t)*(uint16_t*)&h0 | ((uint32_t)*(uint16_t*)&h1 << 16);
        l2[p] = (uint32_t)*(uint16_t*)&l0 | ((uint32_t)*(uint16_t*)&l1 << 16);
    }
    *(uint2*)(hi + i) = make_uint2(h2[0], h2[1]);
    *(uint2*)(lo + i) = make_uint2(l2[0], l2[1]);
}

__global__ void __launch_bounds__(256) split_f32(
    const float* __restrict__ src, bf16* __restrict__ hi, bf16* __restrict__ lo, long n)
{
    long i = ((long)blockIdx.x * 256 + threadIdx.x) * 4;
    if (i >= n) return;
    split4(src, hi, lo, i);
}

// one launch for all 3 weight matrices
__global__ void __launch_bounds__(256) split_w3(
    const float* __restrict__ w0, const float* __restrict__ w1, const float* __restrict__ w2,
    bf16* __restrict__ hi, bf16* __restrict__ lo, long n)
{
    const float* src = (blockIdx.y == 0) ? w0 : (blockIdx.y == 1) ? w1 : w2;
    long off = (long)blockIdx.y * n;
    long i = ((long)blockIdx.x * 256 + threadIdx.x) * 4;
    if (i >= n) return;
    split4(src, hi + off, lo + off, i);
}

// ---------------- causal softmax: fp32 scores -> bf16 hi/lo probs ----------------
__global__ void __launch_bounds__(256) softmax_causal(
    const float* __restrict__ Sc, bf16* __restrict__ Ph, bf16* __restrict__ Pl)
{
    const long r = blockIdx.x;
    const int  q = (int)(r & (SEQ - 1));
    const float* row = Sc + r * SEQ;
    bf16* ph = Ph + r * SEQ;
    bf16* pl = Pl + r * SEQ;

    __shared__ float bufr[SEQ];
    __shared__ float red[256];

    const int tid = threadIdx.x;
    const int len = q + 1;
    const float scale = 0.03125f;  // 1/sqrt(1024)

    float m = -1e30f;
    for (int k = tid; k < len; k += 256) {
        float v = row[k] * scale;
        bufr[k] = v;
        m = fmaxf(m, v);
    }
    red[tid] = m;
    __syncthreads();
    #pragma unroll
    for (int s = 128; s > 0; s >>= 1) {
        if (tid < s) red[tid] = fmaxf(red[tid], red[tid + s]);
        __syncthreads();
    }
    m = red[0];
    __syncthreads();

    float sum = 0.f;
    for (int k = tid; k < len; k += 256) {
        float e = __expf(bufr[k] - m);
        bufr[k] = e;
        sum += e;
    }
    red[tid] = sum;
    __syncthreads();
    #pragma unroll
    for (int s = 128; s > 0; s >>= 1) {
        if (tid < s) red[tid] += red[tid + s];
        __syncthreads();
    }
    const float inv = 1.0f / red[0];
    __syncthreads();

    for (int k = tid; k < len; k += 256) {
        float p = bufr[k] * inv;
        bf16 h = __float2bfloat16(p);
        bf16 l = __float2bfloat16(p - __bfloat162float(h));
        ph[k] = h; pl[k] = l;
    }
    const bf16 z = __float2bfloat16(0.f);
    for (int k = len + tid; k < SEQ; k += 256) { ph[k] = z; pl[k] = z; }
}

// ---------------------------------------------------------------------------
extern "C" void kernel_launch(void* const* d_in, const int* in_sizes, int n_in,
                              void* d_out, int out_size)
{
    const float* X  = (const float*)d_in[0];
    const float* Wq = (const float*)d_in[1];
    const float* Wk = (const float*)d_in[2];
    const float* Wv = (const float*)d_in[3];
    float* out = (float*)d_out;

    bf16 *xh, *xl, *wh, *wl, *qh, *ql, *kh, *kl, *vth, *vtl, *ph, *pl;
    float *sc;
    cudaGetSymbolAddress((void**)&xh,  g_xh);  cudaGetSymbolAddress((void**)&xl,  g_xl);
    cudaGetSymbolAddress((void**)&wh,  g_wh);  cudaGetSymbolAddress((void**)&wl,  g_wl);
    cudaGetSymbolAddress((void**)&qh,  g_qh);  cudaGetSymbolAddress((void**)&ql,  g_ql);
    cudaGetSymbolAddress((void**)&kh,  g_kh);  cudaGetSymbolAddress((void**)&kl,  g_kl);
    cudaGetSymbolAddress((void**)&vth, g_vth); cudaGetSymbolAddress((void**)&vtl, g_vtl);
    cudaGetSymbolAddress((void**)&sc,  g_sc);
    cudaGetSymbolAddress((void**)&ph,  g_ph);  cudaGetSymbolAddress((void**)&pl,  g_pl);

    cudaFuncSetAttribute(gemm_bf16x3, cudaFuncAttributeMaxDynamicSharedMemorySize, SMEM_TOTAL);

    const long nX = (long)BATCH * SEQ * DIM;
    const long nW = (long)DIM * DIM;
    const long WW = nW;

    dim3 thr(256);
    // launch 0
    split_f32<<<(unsigned)(nX / 1024), thr>>>(X, xh, xl, nX);
    // launch 1 (all three weights)
    dim3 gW((unsigned)(nW / 1024), 3, 1);
    split_w3<<<gW, thr>>>(Wq, Wk, Wv, wh, wl, nW);

    const int M = BATCH * SEQ;  // 8192

    // launches 2-4: projections  (Q,K: mode 1; V: mode 2 transposed)
    dim3 gProj(DIM / 128, M / 128, 1);
    gemm_bf16x3<<<gProj, thr, SMEM_TOTAL>>>(xh, xl, wh + 0*WW, wl + 0*WW,
        nullptr, qh, ql, DIM, DIM, DIM, DIM, 0, 0, 0, 0, 0, 1);
    gemm_bf16x3<<<gProj, thr, SMEM_TOTAL>>>(xh, xl, wh + 1*WW, wl + 1*WW,
        nullptr, kh, kl, DIM, DIM, DIM, DIM, 0, 0, 0, 0, 0, 1);
    gemm_bf16x3<<<gProj, thr, SMEM_TOTAL>>>(xh, xl, wh + 2*WW, wl + 2*WW,
        nullptr, vth, vtl, DIM, DIM, DIM, SEQ, 0, 0, (long)DIM * SEQ, 0, 0, 2);

    // launch 5: scores = Q @ K^T per batch (causal tile skip), fp32 out
    dim3 gScore(SEQ / 128, SEQ / 128, BATCH);
    gemm_bf16x3<<<gScore, thr, SMEM_TOTAL>>>(qh, ql, kh, kl,
        sc, nullptr, nullptr, DIM, DIM, DIM, SEQ,
        (long)SEQ * DIM, (long)SEQ * DIM, (long)SEQ * SEQ, 1, 0, 0);

    // launch 6: softmax -> bf16 hi/lo probs
    softmax_causal<<<BATCH * SEQ, thr>>>(sc, ph, pl);

    // launch 7: out = P @ V^T per batch (causal k clamp), fp32 out
    dim3 gAV(DIM / 128, SEQ / 128, BATCH);
    gemm_bf16x3<<<gAV, thr, SMEM_TOTAL>>>(ph, pl, vth, vtl,
        out, nullptr, nullptr, SEQ, SEQ, SEQ, DIM,
        (long)SEQ * SEQ, (long)DIM * SEQ, (long)SEQ * DIM, 0, 1, 0);
}

// round 7
// speedup vs baseline: 1.0138x; 1.0138x over previous
#include <cuda_runtime.h>
#include <cuda_bf16.h>
#include <cstdint>

#define BATCH 4
#define SEQ   2048
#define DIM   1024

typedef __nv_bfloat16 bf16;

// ---------------- scratch (device globals; allocation-free) ----------------
__device__ __align__(128) bf16  g_xh[(long)BATCH*SEQ*DIM];
__device__ __align__(128) bf16  g_xl[(long)BATCH*SEQ*DIM];
__device__ __align__(128) bf16  g_wh[3][(long)DIM*DIM];
__device__ __align__(128) bf16  g_wl[3][(long)DIM*DIM];
__device__ __align__(128) bf16  g_qh[(long)BATCH*SEQ*DIM];
__device__ __align__(128) bf16  g_ql[(long)BATCH*SEQ*DIM];
__device__ __align__(128) bf16  g_kh[(long)BATCH*SEQ*DIM];
__device__ __align__(128) bf16  g_kl[(long)BATCH*SEQ*DIM];
__device__ __align__(128) bf16  g_vth[(long)BATCH*SEQ*DIM];   // V^T: [b][e][s]
__device__ __align__(128) bf16  g_vtl[(long)BATCH*SEQ*DIM];
__device__ __align__(128) float g_sc [(long)BATCH*SEQ*SEQ];
__device__ __align__(128) bf16  g_ph [(long)BATCH*SEQ*SEQ];
__device__ __align__(128) bf16  g_pl [(long)BATCH*SEQ*SEQ];

// ---------------- PTX helpers (arch-generic; NO tcgen05) ----------------
__device__ __forceinline__ uint32_t smem_u32(const void* p) {
    uint32_t a;
    asm("{ .reg .u64 t; cvta.to.shared.u64 t, %1; cvt.u32.u64 %0, t; }" : "=r"(a) : "l"(p));
    return a;
}
__device__ __forceinline__ void cp16(uint32_t saddr, const void* g) {
    asm volatile("cp.async.cg.shared.global [%0], [%1], 16;" :: "r"(saddr), "l"(g) : "memory");
}
#define CP_COMMIT() asm volatile("cp.async.commit_group;" ::: "memory")

__device__ __forceinline__ void ldsm_x4(uint32_t* r, uint32_t addr) {
    asm volatile("ldmatrix.sync.aligned.m8n8.x4.shared.b16 {%0,%1,%2,%3}, [%4];"
        : "=r"(r[0]), "=r"(r[1]), "=r"(r[2]), "=r"(r[3]) : "r"(addr));
}
__device__ __forceinline__ void mma16816(float* c, const uint32_t* a, const uint32_t* b) {
    asm volatile("mma.sync.aligned.m16n8k16.row.col.f32.bf16.bf16.f32 "
        "{%0,%1,%2,%3}, {%4,%5,%6,%7}, {%8,%9}, {%0,%1,%2,%3};"
        : "+f"(c[0]), "+f"(c[1]), "+f"(c[2]), "+f"(c[3])
        : "r"(a[0]), "r"(a[1]), "r"(a[2]), "r"(a[3]), "r"(b[0]), "r"(b[1]));
}

// byte offset inside an 8KB tile of [128 rows][32 bf16], 64B rows,
// 16B chunks XOR-swizzled for conflict-free ldmatrix + stores
__device__ __forceinline__ uint32_t swz(int row, int kc) {
    return (uint32_t)(row * 64 + ((kc ^ ((row >> 1) & 3)) << 4));
}

// ---------------- SMEM layout ----------------
// mainloop: 3 stages x 32KB: [Ahi 8K | Alo 8K | Bhi 8K | Blo 8K]
// epilogue: float buf[128][EPI_LD] overlaps stage memory
#define STAGES 3
#define STAGE_BYTES 32768
#define EPI_LD 132
#define SMEM_TOTAL (STAGES * STAGE_BYTES)   // 98304 >= 128*132*4 = 67584

// =====================================================================
// bf16x3 NT GEMM via mma.sync:  C_tile[128,128] = A[128,K] @ B[128,K]^T
// mode 0: fp32 C;  mode 1: bf16 hi/lo C;  mode 2: bf16 hi/lo C transposed
// =====================================================================
__global__ void __launch_bounds__(256, 2) gemm_bf16x3(
    const bf16* __restrict__ Ahi, const bf16* __restrict__ Alo,
    const bf16* __restrict__ Bhi, const bf16* __restrict__ Blo,
    float* __restrict__ Cf, bf16* __restrict__ Chi, bf16* __restrict__ Clo,
    int K, int ldA, int ldB, int ldC,
    long strideA, long strideB, long strideC,
    int causal, int kclamp, int mode)
{
    const int bx = blockIdx.x, by = blockIdx.y, bz = blockIdx.z;
    if (causal && bx > by) return;

    extern __shared__ char smem[];
    const uint32_t sbase = smem_u32(smem);
    const int tid  = threadIdx.x;
    const int lane = tid & 31;
    const int wid  = tid >> 5;
    const int wm   = wid >> 2;   // 0..1 : 64 rows
    const int wn   = wid & 3;    // 0..3 : 32 cols

    const int kmax    = kclamp ? min(K, (by + 1) * 128) : K;
    const int nchunks = kmax >> 5;                // BK = 32

    const bf16* pAh = Ahi + bz * strideA + (long)by * 128 * ldA;
    const bf16* pAl = Alo + bz * strideA + (long)by * 128 * ldA;
    const bf16* pBh = Bhi + bz * strideB + (long)bx * 128 * ldB;
    const bf16* pBl = Blo + bz * strideB + (long)bx * 128 * ldB;

    // per-thread load coords: 512 16B-chunks per 8KB tile, 2 per thread
    const int l_row0 = tid >> 2,         l_kc0 = tid & 3;
    const int l_row1 = (tid + 256) >> 2, l_kc1 = (tid + 256) & 3;

    auto load_chunk = [&](int c) {
        const uint32_t st = sbase + (uint32_t)(c % STAGES) * STAGE_BYTES;
        const int k0 = c << 5;
        {
            long gA = (long)l_row0 * ldA + k0 + l_kc0 * 8;
            long gB = (long)l_row0 * ldB + k0 + l_kc0 * 8;
            uint32_t so = swz(l_row0, l_kc0);
            cp16(st +         so, pAh + gA);
            cp16(st +  8192 + so, pAl + gA);
            cp16(st + 16384 + so, pBh + gB);
            cp16(st + 24576 + so, pBl + gB);
        }
        {
            long gA = (long)l_row1 * ldA + k0 + l_kc1 * 8;
            long gB = (long)l_row1 * ldB + k0 + l_kc1 * 8;
            uint32_t so = swz(l_row1, l_kc1);
            cp16(st +         so, pAh + gA);
            cp16(st +  8192 + so, pAl + gA);
            cp16(st + 16384 + so, pBh + gB);
            cp16(st + 24576 + so, pBl + gB);
        }
        CP_COMMIT();
    };

    float acc[4][4][4];
    #pragma unroll
    for (int i = 0; i < 4; i++)
        #pragma unroll
        for (int j = 0; j < 4; j++)
            #pragma unroll
            for (int p = 0; p < 4; p++) acc[i][j][p] = 0.f;

    // prologue: fill 2 of 3 stages
    load_chunk(0);
    if (nchunks > 1) load_chunk(1);

    const int lrow = lane & 15;
    const int lsel = lane >> 4;
    const int arow = wm * 64 + lrow;   // base A row for this lane

    for (int c = 0; c < nchunks; c++) {
        if (c + 1 < nchunks) asm volatile("cp.async.wait_group 1;" ::: "memory");
        else                 asm volatile("cp.async.wait_group 0;" ::: "memory");
        __syncthreads();   // single barrier per chunk: also retires all reads
                           // of stage (c-1)%3, which load_chunk(c+2) overwrites.

        if (c + 2 < nchunks) load_chunk(c + 2);

        const uint32_t st  = sbase + (uint32_t)(c % STAGES) * STAGE_BYTES;
        const uint32_t sAh = st, sAl = st + 8192, sBh = st + 16384, sBl = st + 24576;

        #pragma unroll
        for (int ks = 0; ks < 2; ks++) {
            const int kc = ks * 2 + lsel;
            uint32_t bh[4][2], bl[4][2];
            #pragma unroll
            for (int np = 0; np < 2; np++) {
                int r = wn * 32 + np * 16 + lrow;
                uint32_t t4[4];
                ldsm_x4(t4, sBh + swz(r, kc));
                bh[np*2][0] = t4[0]; bh[np*2][1] = t4[2];
                bh[np*2+1][0] = t4[1]; bh[np*2+1][1] = t4[3];
                ldsm_x4(t4, sBl + swz(r, kc));
                bl[np*2][0] = t4[0]; bl[np*2][1] = t4[2];
                bl[np*2+1][0] = t4[1]; bl[np*2+1][1] = t4[3];
            }
            // all 4 A-hi fragments resident
            uint32_t aH[4][4];
            #pragma unroll
            for (int mt = 0; mt < 4; mt++)
                ldsm_x4(aH[mt], sAh + swz(arow + mt * 16, kc));

            // pass 1: aH x bh — 16 independent MMAs
            #pragma unroll
            for (int mt = 0; mt < 4; mt++)
                #pragma unroll
                for (int nt = 0; nt < 4; nt++)
                    mma16816(acc[mt][nt], aH[mt], bh[nt]);

            // pass 2: aH x bl — 16 independent MMAs (acc reuse distance = 16)
            #pragma unroll
            for (int mt = 0; mt < 4; mt++)
                #pragma unroll
                for (int nt = 0; nt < 4; nt++)
                    mma16816(acc[mt][nt], aH[mt], bl[nt]);

            // pass 3: aL x bh — aL streamed with 2-deep fragment buffer
            uint32_t aL[2][4];
            ldsm_x4(aL[0], sAl + swz(arow, kc));
            #pragma unroll
            for (int mt = 0; mt < 4; mt++) {
                const int cur = mt & 1;
                if (mt < 3)
                    ldsm_x4(aL[cur ^ 1], sAl + swz(arow + (mt + 1) * 16, kc));
                #pragma unroll
                for (int nt = 0; nt < 4; nt++)
                    mma16816(acc[mt][nt], aL[cur], bh[nt]);
            }
        }
    }

    // ---- epilogue: stage fp32 tile in smem, then coalesced global writes ----
    __syncthreads();   // protect stage memory before reuse as epilogue buffer
    float* buf = (float*)smem;
    {
        const int rq = lane >> 2;          // 0..7
        const int cq = (lane & 3) * 2;     // 0,2,4,6
        #pragma unroll
        for (int mt = 0; mt < 4; mt++)
            #pragma unroll
            for (int nt = 0; nt < 4; nt++) {
                int r0 = wm * 64 + mt * 16 + rq;
                int c0 = wn * 32 + nt * 8 + cq;
                *(float2*)&buf[r0 * EPI_LD + c0]       = make_float2(acc[mt][nt][0], acc[mt][nt][1]);
                *(float2*)&buf[(r0 + 8) * EPI_LD + c0] = make_float2(acc[mt][nt][2], acc[mt][nt][3]);
            }
    }
    __syncthreads();

    if (mode == 0) {
        int r = tid >> 1, c0 = (tid & 1) * 64;
        long row = (long)by * 128 + r;
        float4* dst = (float4*)(Cf + bz * strideC + row * ldC + (long)bx * 128 + c0);
        #pragma unroll
        for (int i = 0; i < 16; i++)
            dst[i] = *(float4*)&buf[r * EPI_LD + c0 + i * 4];
    } else if (mode == 1) {
        int r = tid >> 1, c0 = (tid & 1) * 64;
        long row = (long)by * 128 + r;
        bf16* dh = Chi + bz * strideC + row * ldC + (long)bx * 128 + c0;
        bf16* dl = Clo + bz * strideC + row * ldC + (long)bx * 128 + c0;
        #pragma unroll
        for (int v = 0; v < 8; v++) {
            uint4 uh, ul;
            uint32_t* ph = (uint32_t*)&uh; uint32_t* pl = (uint32_t*)&ul;
            #pragma unroll
            for (int p = 0; p < 4; p++) {
                float f0 = buf[r * EPI_LD + c0 + v * 8 + p * 2];
                float f1 = buf[r * EPI_LD + c0 + v * 8 + p * 2 + 1];
                bf16 h0 = __float2bfloat16(f0), h1 = __float2bfloat16(f1);
                bf16 l0 = __float2bfloat16(f0 - __bfloat162float(h0));
                bf16 l1 = __float2bfloat16(f1 - __bfloat162float(h1));
                ph[p] = (uint32_t)*(uint16_t*)&h0 | ((uint32_t)*(uint16_t*)&h1 << 16);
                pl[p] = (uint32_t)*(uint16_t*)&l0 | ((uint32_t)*(uint16_t*)&l1 << 16);
            }
            *(uint4*)(dh + v * 8) = uh;
            *(uint4*)(dl + v * 8) = ul;
        }
    } else {
        // transposed hi/lo out: Ct[e][s_local], batch derived from global row
        int cc = tid >> 1, s0 = (tid & 1) * 64;
        int rowbase = by * 128;
        int b = rowbase / SEQ;
        int sloc = (rowbase % SEQ) + s0;
        long e = (long)bx * 128 + cc;
        bf16* dh = Chi + b * strideC + e * ldC + sloc;
        bf16* dl = Clo + b * strideC + e * ldC + sloc;
        #pragma unroll
        for (int v = 0; v < 8; v++) {
            uint4 uh, ul;
            uint32_t* ph = (uint32_t*)&uh; uint32_t* pl = (uint32_t*)&ul;
            #pragma unroll
            for (int p = 0; p < 4; p++) {
                float f0 = buf[(s0 + v * 8 + p * 2)     * EPI_LD + cc];
                float f1 = buf[(s0 + v * 8 + p * 2 + 1) * EPI_LD + cc];
                bf16 h0 = __float2bfloat16(f0), h1 = __float2bfloat16(f1);
                bf16 l0 = __float2bfloat16(f0 - __bfloat162float(h0));
                bf16 l1 = __float2bfloat16(f1 - __bfloat162float(h1));
                ph[p] = (uint32_t)*(uint16_t*)&h0 | ((uint32_t)*(uint16_t*)&h1 << 16);
                pl[p] = (uint32_t)*(uint16_t*)&l0 | ((uint32_t)*(uint16_t*)&l1 << 16);
            }
            *(uint4*)(dh + v * 8) = uh;
            *(uint4*)(dl + v * 8) = ul;
        }
    }
}

// ---------------- fp32 -> bf16 hi/lo split ----------------
__device__ __forceinline__ void split4(const float* __restrict__ src,
                                       bf16* __restrict__ hi, bf16* __restrict__ lo, long i)
{
    float4 v = *(const float4*)(src + i);
    float f[4] = {v.x, v.y, v.z, v.w};
    uint32_t h2[2], l2[2];
    #pragma unroll
    for (int p = 0; p < 2; p++) {
        bf16 h0 = __float2bfloat16(f[p*2]),   h1 = __float2bfloat16(f[p*2+1]);
        bf16 l0 = __float2bfloat16(f[p*2]   - __bfloat162float(h0));
        bf16 l1 = __float2bfloat16(f[p*2+1] - __bfloat162float(h1));
        h2[p] = (uint32_t)*(uint16_t*)&h0 | ((uint32_t)*(uint16_t*)&h1 << 16);
        l2[p] = (uint32_t)*(uint16_t*)&l0 | ((uint32_t)*(uint16_t*)&l1 << 16);
    }
    *(uint2*)(hi + i) = make_uint2(h2[0], h2[1]);
    *(uint2*)(lo + i) = make_uint2(l2[0], l2[1]);
}

__global__ void __launch_bounds__(256) split_f32(
    const float* __restrict__ src, bf16* __restrict__ hi, bf16* __restrict__ lo, long n)
{
    long i = ((long)blockIdx.x * 256 + threadIdx.x) * 4;
    if (i >= n) return;
    split4(src, hi, lo, i);
}

// one launch for all 3 weight matrices
__global__ void __launch_bounds__(256) split_w3(
    const float* __restrict__ w0, const float* __restrict__ w1, const float* __restrict__ w2,
    bf16* __restrict__ hi, bf16* __restrict__ lo, long n)
{
    const float* src = (blockIdx.y == 0) ? w0 : (blockIdx.y == 1) ? w1 : w2;
    long off = (long)blockIdx.y * n;
    long i = ((long)blockIdx.x * 256 + threadIdx.x) * 4;
    if (i >= n) return;
    split4(src, hi + off, lo + off, i);
}

// ---------------- causal softmax: fp32 scores -> bf16 hi/lo probs ----------------
__global__ void __launch_bounds__(256) softmax_causal(
    const float* __restrict__ Sc, bf16* __restrict__ Ph, bf16* __restrict__ Pl)
{
    const long r = blockIdx.x;
    const int  q = (int)(r & (SEQ - 1));
    const float* row = Sc + r * SEQ;
    bf16* ph = Ph + r * SEQ;
    bf16* pl = Pl + r * SEQ;

    __shared__ float bufr[SEQ];
    __shared__ float red[256];

    const int tid = threadIdx.x;
    const int len = q + 1;
    const float scale = 0.03125f;  // 1/sqrt(1024)

    float m = -1e30f;
    for (int k = tid; k < len; k += 256) {
        float v = row[k] * scale;
        bufr[k] = v;
        m = fmaxf(m, v);
    }
    red[tid] = m;
    __syncthreads();
    #pragma unroll
    for (int s = 128; s > 0; s >>= 1) {
        if (tid < s) red[tid] = fmaxf(red[tid], red[tid + s]);
        __syncthreads();
    }
    m = red[0];
    __syncthreads();

    float sum = 0.f;
    for (int k = tid; k < len; k += 256) {
        float e = __expf(bufr[k] - m);
        bufr[k] = e;
        sum += e;
    }
    red[tid] = sum;
    __syncthreads();
    #pragma unroll
    for (int s = 128; s > 0; s >>= 1) {
        if (tid < s) red[tid] += red[tid + s];
        __syncthreads();
    }
    const float inv = 1.0f / red[0];
    __syncthreads();

    for (int k = tid; k < len; k += 256) {
        float p = bufr[k] * inv;
        bf16 h = __float2bfloat16(p);
        bf16 l = __float2bfloat16(p - __bfloat162float(h));
        ph[k] = h; pl[k] = l;
    }
    const bf16 z = __float2bfloat16(0.f);
    for (int k = len + tid; k < SEQ; k += 256) { ph[k] = z; pl[k] = z; }
}

// ---------------------------------------------------------------------------
extern "C" void kernel_launch(void* const* d_in, const int* in_sizes, int n_in,
                              void* d_out, int out_size)
{
    const float* X  = (const float*)d_in[0];
    const float* Wq = (const float*)d_in[1];
    const float* Wk = (const float*)d_in[2];
    const float* Wv = (const float*)d_in[3];
    float* out = (float*)d_out;

    bf16 *xh, *xl, *wh, *wl, *qh, *ql, *kh, *kl, *vth, *vtl, *ph, *pl;
    float *sc;
    cudaGetSymbolAddress((void**)&xh,  g_xh);  cudaGetSymbolAddress((void**)&xl,  g_xl);
    cudaGetSymbolAddress((void**)&wh,  g_wh);  cudaGetSymbolAddress((void**)&wl,  g_wl);
    cudaGetSymbolAddress((void**)&qh,  g_qh);  cudaGetSymbolAddress((void**)&ql,  g_ql);
    cudaGetSymbolAddress((void**)&kh,  g_kh);  cudaGetSymbolAddress((void**)&kl,  g_kl);
    cudaGetSymbolAddress((void**)&vth, g_vth); cudaGetSymbolAddress((void**)&vtl, g_vtl);
    cudaGetSymbolAddress((void**)&sc,  g_sc);
    cudaGetSymbolAddress((void**)&ph,  g_ph);  cudaGetSymbolAddress((void**)&pl,  g_pl);

    cudaFuncSetAttribute(gemm_bf16x3, cudaFuncAttributeMaxDynamicSharedMemorySize, SMEM_TOTAL);

    const long nX = (long)BATCH * SEQ * DIM;
    const long nW = (long)DIM * DIM;
    const long WW = nW;

    dim3 thr(256);
    // launch 0
    split_f32<<<(unsigned)(nX / 1024), thr>>>(X, xh, xl, nX);
    // launch 1 (all three weights)
    dim3 gW((unsigned)(nW / 1024), 3, 1);
    split_w3<<<gW, thr>>>(Wq, Wk, Wv, wh, wl, nW);

    const int M = BATCH * SEQ;  // 8192

    // launches 2-4: projections  (Q,K: mode 1; V: mode 2 transposed)
    dim3 gProj(DIM / 128, M / 128, 1);
    gemm_bf16x3<<<gProj, thr, SMEM_TOTAL>>>(xh, xl, wh + 0*WW, wl + 0*WW,
        nullptr, qh, ql, DIM, DIM, DIM, DIM, 0, 0, 0, 0, 0, 1);
    gemm_bf16x3<<<gProj, thr, SMEM_TOTAL>>>(xh, xl, wh + 1*WW, wl + 1*WW,
        nullptr, kh, kl, DIM, DIM, DIM, DIM, 0, 0, 0, 0, 0, 1);
    gemm_bf16x3<<<gProj, thr, SMEM_TOTAL>>>(xh, xl, wh + 2*WW, wl + 2*WW,
        nullptr, vth, vtl, DIM, DIM, DIM, SEQ, 0, 0, (long)DIM * SEQ, 0, 0, 2);

    // launch 5: scores = Q @ K^T per batch (causal tile skip), fp32 out
    dim3 gScore(SEQ / 128, SEQ / 128, BATCH);
    gemm_bf16x3<<<gScore, thr, SMEM_TOTAL>>>(qh, ql, kh, kl,
        sc, nullptr, nullptr, DIM, DIM, DIM, SEQ,
        (long)SEQ * DIM, (long)SEQ * DIM, (long)SEQ * SEQ, 1, 0, 0);

    // launch 6: softmax -> bf16 hi/lo probs
    softmax_causal<<<BATCH * SEQ, thr>>>(sc, ph, pl);

    // launch 7: out = P @ V^T per batch (causal k clamp), fp32 out
    dim3 gAV(DIM / 128, SEQ / 128, BATCH);
    gemm_bf16x3<<<gAV, thr, SMEM_TOTAL>>>(ph, pl, vth, vtl,
        out, nullptr, nullptr, SEQ, SEQ, SEQ, DIM,
        (long)SEQ * SEQ, (long)DIM * SEQ, (long)SEQ * DIM, 0, 1, 0);
}

// round 8
// speedup vs baseline: 1.0615x; 1.0471x over previous
#include <cuda_runtime.h>
#include <cuda_bf16.h>
#include <cstdint>

#define BATCH 4
#define SEQ   2048
#define DIM   1024

typedef __nv_bfloat16 bf16;

static const long NX = (long)BATCH * SEQ * DIM;   // 8388608
static const long NW = (long)DIM * DIM;           // 1048576

// ---------------- scratch (device globals; allocation-free) ----------------
__device__ __align__(128) bf16  g_xh[(long)BATCH*SEQ*DIM];
__device__ __align__(128) bf16  g_xl[(long)BATCH*SEQ*DIM];
__device__ __align__(128) bf16  g_wh[3][(long)DIM*DIM];
__device__ __align__(128) bf16  g_wl[3][(long)DIM*DIM];
// stacked outputs: [0]=Q, [1]=K, [2]=V^T ([b][e][s])
__device__ __align__(128) bf16  g_oh[3*(long)BATCH*SEQ*DIM];
__device__ __align__(128) bf16  g_ol[3*(long)BATCH*SEQ*DIM];
__device__ __align__(128) float g_sc [(long)BATCH*SEQ*SEQ];
__device__ __align__(128) bf16  g_ph [(long)BATCH*SEQ*SEQ];
__device__ __align__(128) bf16  g_pl [(long)BATCH*SEQ*SEQ];

// ---------------- PTX helpers (arch-generic; NO tcgen05) ----------------
__device__ __forceinline__ uint32_t smem_u32(const void* p) {
    uint32_t a;
    asm("{ .reg .u64 t; cvta.to.shared.u64 t, %1; cvt.u32.u64 %0, t; }" : "=r"(a) : "l"(p));
    return a;
}
__device__ __forceinline__ void cp16(uint32_t saddr, const void* g) {
    asm volatile("cp.async.cg.shared.global [%0], [%1], 16;" :: "r"(saddr), "l"(g) : "memory");
}
#define CP_COMMIT() asm volatile("cp.async.commit_group;" ::: "memory")

__device__ __forceinline__ void ldsm_x4(uint32_t* r, uint32_t addr) {
    asm volatile("ldmatrix.sync.aligned.m8n8.x4.shared.b16 {%0,%1,%2,%3}, [%4];"
        : "=r"(r[0]), "=r"(r[1]), "=r"(r[2]), "=r"(r[3]) : "r"(addr));
}
__device__ __forceinline__ void mma16816(float* c, const uint32_t* a, const uint32_t* b) {
    asm volatile("mma.sync.aligned.m16n8k16.row.col.f32.bf16.bf16.f32 "
        "{%0,%1,%2,%3}, {%4,%5,%6,%7}, {%8,%9}, {%0,%1,%2,%3};"
        : "+f"(c[0]), "+f"(c[1]), "+f"(c[2]), "+f"(c[3])
        : "r"(a[0]), "r"(a[1]), "r"(a[2]), "r"(a[3]), "r"(b[0]), "r"(b[1]));
}

// byte offset inside an 8KB tile of [128 rows][32 bf16], 64B rows,
// 16B chunks XOR-swizzled for conflict-free ldmatrix + stores
__device__ __forceinline__ uint32_t swz(int row, int kc) {
    return (uint32_t)(row * 64 + ((kc ^ ((row >> 1) & 3)) << 4));
}

// ---------------- SMEM layout ----------------
#define STAGES 3
#define STAGE_BYTES 32768
#define EPI_LD 132
#define SMEM_TOTAL (STAGES * STAGE_BYTES)   // 98304 >= 128*132*4 = 67584

// =====================================================================
// bf16x3 NT GEMM via mma.sync: 128x128 CTA tile, 128 threads,
// 4 warps x (64x64) warp tile.
// mode 0: fp32 C;  mode 1: bf16 hi/lo C;  mode 2: bf16 hi/lo C transposed
// mode 3: fused QKV projection (bz selects weight + output submode)
// =====================================================================
__global__ void __launch_bounds__(128, 2) gemm_bf16x3(
    const bf16* __restrict__ Ahi, const bf16* __restrict__ Alo,
    const bf16* __restrict__ Bhi, const bf16* __restrict__ Blo,
    float* __restrict__ Cf, bf16* __restrict__ Chi, bf16* __restrict__ Clo,
    int K, int ldA, int ldB, int ldC,
    long strideA, long strideB, long strideC,
    int causal, int kclamp, int mode)
{
    const int bx = blockIdx.x, by = blockIdx.y, bz = blockIdx.z;
    if (causal && bx > by) return;

    // resolve fused-projection submode
    int  eff_mode = mode;
    int  ldC_e = ldC;
    long sC_e  = strideC;
    long cOff  = 0;
    if (mode == 3) {
        cOff = (long)bz * ((long)BATCH * SEQ * DIM);
        if (bz == 2) { eff_mode = 2; ldC_e = SEQ; sC_e = (long)DIM * SEQ; }
        else         { eff_mode = 1; ldC_e = DIM; sC_e = 0; }
    }

    extern __shared__ char smem[];
    const uint32_t sbase = smem_u32(smem);
    const int tid  = threadIdx.x;        // 0..127
    const int lane = tid & 31;
    const int wid  = tid >> 5;           // 0..3
    const int wm   = wid >> 1;           // 0..1 : 64 rows
    const int wn   = wid & 1;            // 0..1 : 64 cols

    const int kmax    = kclamp ? min(K, (by + 1) * 128) : K;
    const int nchunks = kmax >> 5;       // BK = 32

    const bf16* pAh = Ahi + bz * strideA + (long)by * 128 * ldA;
    const bf16* pAl = Alo + bz * strideA + (long)by * 128 * ldA;
    const bf16* pBh = Bhi + bz * strideB + (long)bx * 128 * ldB;
    const bf16* pBl = Blo + bz * strideB + (long)bx * 128 * ldB;

    auto load_chunk = [&](int c) {
        const uint32_t st = sbase + (uint32_t)(c % STAGES) * STAGE_BYTES;
        const int k0 = c << 5;
        #pragma unroll
        for (int i = 0; i < 4; i++) {
            int id  = tid + i * 128;       // 0..511
            int row = id >> 2, kc = id & 3;
            uint32_t so = swz(row, kc);
            long gA = (long)row * ldA + k0 + kc * 8;
            long gB = (long)row * ldB + k0 + kc * 8;
            cp16(st +         so, pAh + gA);
            cp16(st +  8192 + so, pAl + gA);
            cp16(st + 16384 + so, pBh + gB);
            cp16(st + 24576 + so, pBl + gB);
        }
        CP_COMMIT();
    };

    float acc[4][8][4];
    #pragma unroll
    for (int i = 0; i < 4; i++)
        #pragma unroll
        for (int j = 0; j < 8; j++)
            #pragma unroll
            for (int p = 0; p < 4; p++) acc[i][j][p] = 0.f;

    load_chunk(0);
    if (nchunks > 1) load_chunk(1);

    const int lrow = lane & 15;
    const int lsel = lane >> 4;
    const int arow = wm * 64 + lrow;
    const int brow = wn * 64 + lrow;

    for (int c = 0; c < nchunks; c++) {
        if (c + 1 < nchunks) asm volatile("cp.async.wait_group 1;" ::: "memory");
        else                 asm volatile("cp.async.wait_group 0;" ::: "memory");
        __syncthreads();

        if (c + 2 < nchunks) load_chunk(c + 2);

        const uint32_t st  = sbase + (uint32_t)(c % STAGES) * STAGE_BYTES;
        const uint32_t sAh = st, sAl = st + 8192, sBh = st + 16384, sBl = st + 24576;

        #pragma unroll
        for (int ks = 0; ks < 2; ks++) {
            const int kc = ks * 2 + lsel;
            uint32_t bh[8][2], bl[8][2];
            #pragma unroll
            for (int np = 0; np < 4; np++) {
                int r = brow + np * 16;
                uint32_t t4[4];
                ldsm_x4(t4, sBh + swz(r, kc));
                bh[np*2][0] = t4[0]; bh[np*2][1] = t4[2];
                bh[np*2+1][0] = t4[1]; bh[np*2+1][1] = t4[3];
                ldsm_x4(t4, sBl + swz(r, kc));
                bl[np*2][0] = t4[0]; bl[np*2][1] = t4[2];
                bl[np*2+1][0] = t4[1]; bl[np*2+1][1] = t4[3];
            }
            uint32_t aH[4][4];
            #pragma unroll
            for (int mt = 0; mt < 4; mt++)
                ldsm_x4(aH[mt], sAh + swz(arow + mt * 16, kc));

            // pass 1: aH x bh
            #pragma unroll
            for (int mt = 0; mt < 4; mt++)
                #pragma unroll
                for (int nt = 0; nt < 8; nt++)
                    mma16816(acc[mt][nt], aH[mt], bh[nt]);
            // pass 2: aH x bl
            #pragma unroll
            for (int mt = 0; mt < 4; mt++)
                #pragma unroll
                for (int nt = 0; nt < 8; nt++)
                    mma16816(acc[mt][nt], aH[mt], bl[nt]);
            // pass 3: aL x bh (aL streamed)
            uint32_t aL[2][4];
            ldsm_x4(aL[0], sAl + swz(arow, kc));
            #pragma unroll
            for (int mt = 0; mt < 4; mt++) {
                const int cur = mt & 1;
                if (mt < 3)
                    ldsm_x4(aL[cur ^ 1], sAl + swz(arow + (mt + 1) * 16, kc));
                #pragma unroll
                for (int nt = 0; nt < 8; nt++)
                    mma16816(acc[mt][nt], aL[cur], bh[nt]);
            }
        }
    }

    // ---- epilogue: stage fp32 tile in smem, then coalesced global writes ----
    __syncthreads();
    float* buf = (float*)smem;
    {
        const int rq = lane >> 2;          // 0..7
        const int cq = (lane & 3) * 2;     // 0,2,4,6
        #pragma unroll
        for (int mt = 0; mt < 4; mt++)
            #pragma unroll
            for (int nt = 0; nt < 8; nt++) {
                int r0 = wm * 64 + mt * 16 + rq;
                int c0 = wn * 64 + nt * 8 + cq;
                *(float2*)&buf[r0 * EPI_LD + c0]       = make_float2(acc[mt][nt][0], acc[mt][nt][1]);
                *(float2*)&buf[(r0 + 8) * EPI_LD + c0] = make_float2(acc[mt][nt][2], acc[mt][nt][3]);
            }
    }
    __syncthreads();

    if (eff_mode == 0) {
        int r = tid;                              // one row per thread
        long row = (long)by * 128 + r;
        float4* dst = (float4*)(Cf + bz * sC_e + row * ldC_e + (long)bx * 128);
        #pragma unroll
        for (int i = 0; i < 32; i++)
            dst[i] = *(float4*)&buf[r * EPI_LD + i * 4];
    } else if (eff_mode == 1) {
        int r = tid;
        long row = (long)by * 128 + r;
        bf16* dh = Chi + cOff + bz * sC_e + row * ldC_e + (long)bx * 128;
        bf16* dl = Clo + cOff + bz * sC_e + row * ldC_e + (long)bx * 128;
        #pragma unroll
        for (int v = 0; v < 16; v++) {
            uint4 uh, ul;
            uint32_t* ph = (uint32_t*)&uh; uint32_t* pl = (uint32_t*)&ul;
            #pragma unroll
            for (int p = 0; p < 4; p++) {
                float f0 = buf[r * EPI_LD + v * 8 + p * 2];
                float f1 = buf[r * EPI_LD + v * 8 + p * 2 + 1];
                bf16 h0 = __float2bfloat16(f0), h1 = __float2bfloat16(f1);
                bf16 l0 = __float2bfloat16(f0 - __bfloat162float(h0));
                bf16 l1 = __float2bfloat16(f1 - __bfloat162float(h1));
                ph[p] = (uint32_t)*(uint16_t*)&h0 | ((uint32_t)*(uint16_t*)&h1 << 16);
                pl[p] = (uint32_t)*(uint16_t*)&l0 | ((uint32_t)*(uint16_t*)&l1 << 16);
            }
            *(uint4*)(dh + v * 8) = uh;
            *(uint4*)(dl + v * 8) = ul;
        }
    } else {
        // transposed hi/lo out: Ct[e][s_local], batch derived from global row
        int cc = tid;                              // one output row (e) per thread
        int rowbase = by * 128;
        int b = rowbase / SEQ;
        int sloc = rowbase % SEQ;
        long e = (long)bx * 128 + cc;
        bf16* dh = Chi + cOff + b * sC_e + e * ldC_e + sloc;
        bf16* dl = Clo + cOff + b * sC_e + e * ldC_e + sloc;
        #pragma unroll
        for (int v = 0; v < 16; v++) {
            uint4 uh, ul;
            uint32_t* ph = (uint32_t*)&uh; uint32_t* pl = (uint32_t*)&ul;
            #pragma unroll
            for (int p = 0; p < 4; p++) {
                float f0 = buf[(v * 8 + p * 2)     * EPI_LD + cc];
                float f1 = buf[(v * 8 + p * 2 + 1) * EPI_LD + cc];
                bf16 h0 = __float2bfloat16(f0), h1 = __float2bfloat16(f1);
                bf16 l0 = __float2bfloat16(f0 - __bfloat162float(h0));
                bf16 l1 = __float2bfloat16(f1 - __bfloat162float(h1));
                ph[p] = (uint32_t)*(uint16_t*)&h0 | ((uint32_t)*(uint16_t*)&h1 << 16);
                pl[p] = (uint32_t)*(uint16_t*)&l0 | ((uint32_t)*(uint16_t*)&l1 << 16);
            }
            *(uint4*)(dh + v * 8) = uh;
            *(uint4*)(dl + v * 8) = ul;
        }
    }
}

// ---------------- fp32 -> bf16 hi/lo split ----------------
__device__ __forceinline__ void split4(const float* __restrict__ src,
                                       bf16* __restrict__ hi, bf16* __restrict__ lo, long i)
{
    float4 v = *(const float4*)(src + i);
    float f[4] = {v.x, v.y, v.z, v.w};
    uint32_t h2[2], l2[2];
    #pragma unroll
    for (int p = 0; p < 2; p++) {
        bf16 h0 = __float2bfloat16(f[p*2]),   h1 = __float2bfloat16(f[p*2+1]);
        bf16 l0 = __float2bfloat16(f[p*2]   - __bfloat162float(h0));
        bf16 l1 = __float2bfloat16(f[p*2+1] - __bfloat162float(h1));
        h2[p] = (uint32_t)*(uint16_t*)&h0 | ((uint32_t)*(uint16_t*)&h1 << 16);
        l2[p] = (uint32_t)*(uint16_t*)&l0 | ((uint32_t)*(uint16_t*)&l1 << 16);
    }
    *(uint2*)(hi + i) = make_uint2(h2[0], h2[1]);
    *(uint2*)(lo + i) = make_uint2(l2[0], l2[1]);
}

__global__ void __launch_bounds__(256) split_f32(
    const float* __restrict__ src, bf16* __restrict__ hi, bf16* __restrict__ lo, long n)
{
    long i = ((long)blockIdx.x * 256 + threadIdx.x) * 4;
    if (i >= n) return;
    split4(src, hi, lo, i);
}

__global__ void __launch_bounds__(256) split_w3(
    const float* __restrict__ w0, const float* __restrict__ w1, const float* __restrict__ w2,
    bf16* __restrict__ hi, bf16* __restrict__ lo, long n)
{
    const float* src = (blockIdx.y == 0) ? w0 : (blockIdx.y == 1) ? w1 : w2;
    long off = (long)blockIdx.y * n;
    long i = ((long)blockIdx.x * 256 + threadIdx.x) * 4;
    if (i >= n) return;
    split4(src, hi + off, lo + off, i);
}

// ---------------- causal softmax: fp32 scores -> bf16 hi/lo probs ----------------
__global__ void __launch_bounds__(256) softmax_causal(
    const float* __restrict__ Sc, bf16* __restrict__ Ph, bf16* __restrict__ Pl)
{
    const long r = blockIdx.x;
    const int  q = (int)(r & (SEQ - 1));
    const float* row = Sc + r * SEQ;
    bf16* ph = Ph + r * SEQ;
    bf16* pl = Pl + r * SEQ;

    __shared__ float bufr[SEQ];
    __shared__ float red[256];

    const int tid = threadIdx.x;
    const int len = q + 1;
    const float scale = 0.03125f;  // 1/sqrt(1024)

    float m = -1e30f;
    for (int k = tid; k < len; k += 256) {
        float v = row[k] * scale;
        bufr[k] = v;
        m = fmaxf(m, v);
    }
    red[tid] = m;
    __syncthreads();
    #pragma unroll
    for (int s = 128; s > 0; s >>= 1) {
        if (tid < s) red[tid] = fmaxf(red[tid], red[tid + s]);
        __syncthreads();
    }
    m = red[0];
    __syncthreads();

    float sum = 0.f;
    for (int k = tid; k < len; k += 256) {
        float e = __expf(bufr[k] - m);
        bufr[k] = e;
        sum += e;
    }
    red[tid] = sum;
    __syncthreads();
    #pragma unroll
    for (int s = 128; s > 0; s >>= 1) {
        if (tid < s) red[tid] += red[tid + s];
        __syncthreads();
    }
    const float inv = 1.0f / red[0];
    __syncthreads();

    for (int k = tid; k < len; k += 256) {
        float p = bufr[k] * inv;
        bf16 h = __float2bfloat16(p);
        bf16 l = __float2bfloat16(p - __bfloat162float(h));
        ph[k] = h; pl[k] = l;
    }
    const bf16 z = __float2bfloat16(0.f);
    for (int k = len + tid; k < SEQ; k += 256) { ph[k] = z; pl[k] = z; }
}

// ---------------------------------------------------------------------------
extern "C" void kernel_launch(void* const* d_in, const int* in_sizes, int n_in,
                              void* d_out, int out_size)
{
    const float* X  = (const float*)d_in[0];
    const float* Wq = (const float*)d_in[1];
    const float* Wk = (const float*)d_in[2];
    const float* Wv = (const float*)d_in[3];
    float* out = (float*)d_out;

    bf16 *xh, *xl, *wh, *wl, *oh, *ol, *ph, *pl;
    float *sc;
    cudaGetSymbolAddress((void**)&xh, g_xh);  cudaGetSymbolAddress((void**)&xl, g_xl);
    cudaGetSymbolAddress((void**)&wh, g_wh);  cudaGetSymbolAddress((void**)&wl, g_wl);
    cudaGetSymbolAddress((void**)&oh, g_oh);  cudaGetSymbolAddress((void**)&ol, g_ol);
    cudaGetSymbolAddress((void**)&sc, g_sc);
    cudaGetSymbolAddress((void**)&ph, g_ph);  cudaGetSymbolAddress((void**)&pl, g_pl);

    cudaFuncSetAttribute(gemm_bf16x3, cudaFuncAttributeMaxDynamicSharedMemorySize, SMEM_TOTAL);

    const long nX = NX, nW = NW;
    const int M = BATCH * SEQ;  // 8192

    dim3 thr256(256);
    dim3 thr128(128);

    split_f32<<<(unsigned)(nX / 1024), thr256>>>(X, xh, xl, nX);
    dim3 gW((unsigned)(nW / 1024), 3, 1);
    split_w3<<<gW, thr256>>>(Wq, Wk, Wv, wh, wl, nW);

    // fused QKV projections: z = 0(Q),1(K),2(V^T)
    dim3 gProj(DIM / 128, M / 128, 3);
    gemm_bf16x3<<<gProj, thr128, SMEM_TOTAL>>>(xh, xl, wh, wl,
        nullptr, oh, ol, DIM, DIM, DIM, DIM,
        0, nW, 0, 0, 0, 3);

    // scores = Q @ K^T per batch (causal tile skip), fp32 out
    dim3 gScore(SEQ / 128, SEQ / 128, BATCH);
    gemm_bf16x3<<<gScore, thr128, SMEM_TOTAL>>>(oh, ol, oh + nX, ol + nX,
        sc, nullptr, nullptr, DIM, DIM, DIM, SEQ,
        (long)SEQ * DIM, (long)SEQ * DIM, (long)SEQ * SEQ, 1, 0, 0);

    // softmax -> bf16 hi/lo probs
    softmax_causal<<<BATCH * SEQ, thr256>>>(sc, ph, pl);

    // out = P @ V^T per batch (causal k clamp), fp32 out
    dim3 gAV(DIM / 128, SEQ / 128, BATCH);
    gemm_bf16x3<<<gAV, thr128, SMEM_TOTAL>>>(ph, pl, oh + 2 * nX, ol + 2 * nX,
        out, nullptr, nullptr, SEQ, SEQ, SEQ, DIM,
        (long)SEQ * SEQ, (long)DIM * SEQ, (long)SEQ * DIM, 0, 1, 0);
}

// round 9
// speedup vs baseline: 1.1818x; 1.1133x over previous
#include <cuda_runtime.h>
#include <cuda_bf16.h>
#include <cstdint>

#define BATCH 4
#define SEQ   2048
#define DIM   1024

typedef __nv_bfloat16 bf16;

static const long NX = (long)BATCH * SEQ * DIM;   // 8388608
static const long NW = (long)DIM * DIM;           // 1048576

// ---------------- scratch (device globals; allocation-free) ----------------
__device__ __align__(128) bf16  g_xh[(long)BATCH*SEQ*DIM];
__device__ __align__(128) bf16  g_xl[(long)BATCH*SEQ*DIM];
// [0]=Wq^T, [1]=Wk^T, [2]=Wv (row-major as given)
__device__ __align__(128) bf16  g_wh[3][(long)DIM*DIM];
__device__ __align__(128) bf16  g_wl[3][(long)DIM*DIM];
// M' split-K fp32 partials and final bf16 hi/lo
__device__ __align__(128) float g_mpart[8*(long)DIM*DIM];
__device__ __align__(128) bf16  g_mh[(long)DIM*DIM];
__device__ __align__(128) bf16  g_ml[(long)DIM*DIM];
// stacked outputs: [0]=T, [2]=V^T ([b][e][s])
__device__ __align__(128) bf16  g_oh[3*(long)BATCH*SEQ*DIM];
__device__ __align__(128) bf16  g_ol[3*(long)BATCH*SEQ*DIM];
__device__ __align__(128) float g_sc [(long)BATCH*SEQ*SEQ];
__device__ __align__(128) bf16  g_ph [(long)BATCH*SEQ*SEQ];
__device__ __align__(128) bf16  g_pl [(long)BATCH*SEQ*SEQ];

// ---------------- PTX helpers (arch-generic; NO tcgen05) ----------------
__device__ __forceinline__ uint32_t smem_u32(const void* p) {
    uint32_t a;
    asm("{ .reg .u64 t; cvta.to.shared.u64 t, %1; cvt.u32.u64 %0, t; }" : "=r"(a) : "l"(p));
    return a;
}
__device__ __forceinline__ void cp16(uint32_t saddr, const void* g) {
    asm volatile("cp.async.cg.shared.global [%0], [%1], 16;" :: "r"(saddr), "l"(g) : "memory");
}
#define CP_COMMIT() asm volatile("cp.async.commit_group;" ::: "memory")

__device__ __forceinline__ void ldsm_x4(uint32_t* r, uint32_t addr) {
    asm volatile("ldmatrix.sync.aligned.m8n8.x4.shared.b16 {%0,%1,%2,%3}, [%4];"
        : "=r"(r[0]), "=r"(r[1]), "=r"(r[2]), "=r"(r[3]) : "r"(addr));
}
__device__ __forceinline__ void mma16816(float* c, const uint32_t* a, const uint32_t* b) {
    asm volatile("mma.sync.aligned.m16n8k16.row.col.f32.bf16.bf16.f32 "
        "{%0,%1,%2,%3}, {%4,%5,%6,%7}, {%8,%9}, {%0,%1,%2,%3};"
        : "+f"(c[0]), "+f"(c[1]), "+f"(c[2]), "+f"(c[3])
        : "r"(a[0]), "r"(a[1]), "r"(a[2]), "r"(a[3]), "r"(b[0]), "r"(b[1]));
}

__device__ __forceinline__ uint32_t swz(int row, int kc) {
    return (uint32_t)(row * 64 + ((kc ^ ((row >> 1) & 3)) << 4));
}

// ---------------- SMEM layout ----------------
#define STAGES 3
#define STAGE_BYTES 32768
#define EPI_LD 132
#define SMEM_TOTAL (STAGES * STAGE_BYTES)

// =====================================================================
// bf16x3 NT GEMM via mma.sync: 128x128 CTA tile, 128 threads,
// 4 warps x (64x64) warp tile.
// mode 0: fp32 C;  mode 1: bf16 hi/lo C;  mode 2: bf16 hi/lo C transposed
// ksplit: when 1, this block computes K-window [bz*K, (bz+1)*K)
// =====================================================================
__global__ void __launch_bounds__(128, 2) gemm_bf16x3(
    const bf16* __restrict__ Ahi, const bf16* __restrict__ Alo,
    const bf16* __restrict__ Bhi, const bf16* __restrict__ Blo,
    float* __restrict__ Cf, bf16* __restrict__ Chi, bf16* __restrict__ Clo,
    int K, int ldA, int ldB, int ldC,
    long strideA, long strideB, long strideC,
    int causal, int kclamp, int mode, int ksplit)
{
    const int bx = blockIdx.x, by = blockIdx.y, bz = blockIdx.z;
    if (causal && bx > by) return;

    extern __shared__ char smem[];
    const uint32_t sbase = smem_u32(smem);
    const int tid  = threadIdx.x;        // 0..127
    const int lane = tid & 31;
    const int wid  = tid >> 5;           // 0..3
    const int wm   = wid >> 1;           // 0..1 : 64 rows
    const int wn   = wid & 1;            // 0..1 : 64 cols

    const int kbase   = ksplit ? bz * K : 0;
    const int kmax    = kclamp ? min(K, (by + 1) * 128) : K;
    const int nchunks = kmax >> 5;       // BK = 32

    const bf16* pAh = Ahi + bz * strideA + (long)by * 128 * ldA;
    const bf16* pAl = Alo + bz * strideA + (long)by * 128 * ldA;
    const bf16* pBh = Bhi + bz * strideB + (long)bx * 128 * ldB;
    const bf16* pBl = Blo + bz * strideB + (long)bx * 128 * ldB;

    auto load_chunk = [&](int c) {
        const uint32_t st = sbase + (uint32_t)(c % STAGES) * STAGE_BYTES;
        const int k0 = kbase + (c << 5);
        #pragma unroll
        for (int i = 0; i < 4; i++) {
            int id  = tid + i * 128;       // 0..511
            int row = id >> 2, kc = id & 3;
            uint32_t so = swz(row, kc);
            long gA = (long)row * ldA + k0 + kc * 8;
            long gB = (long)row * ldB + k0 + kc * 8;
            cp16(st +         so, pAh + gA);
            cp16(st +  8192 + so, pAl + gA);
            cp16(st + 16384 + so, pBh + gB);
            cp16(st + 24576 + so, pBl + gB);
        }
        CP_COMMIT();
    };

    float acc[4][8][4];
    #pragma unroll
    for (int i = 0; i < 4; i++)
        #pragma unroll
        for (int j = 0; j < 8; j++)
            #pragma unroll
            for (int p = 0; p < 4; p++) acc[i][j][p] = 0.f;

    load_chunk(0);
    if (nchunks > 1) load_chunk(1);

    const int lrow = lane & 15;
    const int lsel = lane >> 4;
    const int arow = wm * 64 + lrow;
    const int brow = wn * 64 + lrow;

    for (int c = 0; c < nchunks; c++) {
        if (c + 1 < nchunks) asm volatile("cp.async.wait_group 1;" ::: "memory");
        else                 asm volatile("cp.async.wait_group 0;" ::: "memory");
        __syncthreads();

        if (c + 2 < nchunks) load_chunk(c + 2);

        const uint32_t st  = sbase + (uint32_t)(c % STAGES) * STAGE_BYTES;
        const uint32_t sAh = st, sAl = st + 8192, sBh = st + 16384, sBl = st + 24576;

        #pragma unroll
        for (int ks = 0; ks < 2; ks++) {
            const int kc = ks * 2 + lsel;
            uint32_t bh[8][2], bl[8][2];
            #pragma unroll
            for (int np = 0; np < 4; np++) {
                int r = brow + np * 16;
                uint32_t t4[4];
                ldsm_x4(t4, sBh + swz(r, kc));
                bh[np*2][0] = t4[0]; bh[np*2][1] = t4[2];
                bh[np*2+1][0] = t4[1]; bh[np*2+1][1] = t4[3];
                ldsm_x4(t4, sBl + swz(r, kc));
                bl[np*2][0] = t4[0]; bl[np*2][1] = t4[2];
                bl[np*2+1][0] = t4[1]; bl[np*2+1][1] = t4[3];
            }
            uint32_t aH[4][4];
            #pragma unroll
            for (int mt = 0; mt < 4; mt++)
                ldsm_x4(aH[mt], sAh + swz(arow + mt * 16, kc));

            #pragma unroll
            for (int mt = 0; mt < 4; mt++)
                #pragma unroll
                for (int nt = 0; nt < 8; nt++)
                    mma16816(acc[mt][nt], aH[mt], bh[nt]);
            #pragma unroll
            for (int mt = 0; mt < 4; mt++)
                #pragma unroll
                for (int nt = 0; nt < 8; nt++)
                    mma16816(acc[mt][nt], aH[mt], bl[nt]);
            uint32_t aL[2][4];
            ldsm_x4(aL[0], sAl + swz(arow, kc));
            #pragma unroll
            for (int mt = 0; mt < 4; mt++) {
                const int cur = mt & 1;
                if (mt < 3)
                    ldsm_x4(aL[cur ^ 1], sAl + swz(arow + (mt + 1) * 16, kc));
                #pragma unroll
                for (int nt = 0; nt < 8; nt++)
                    mma16816(acc[mt][nt], aL[cur], bh[nt]);
            }
        }
    }

    // ---- epilogue: stage fp32 tile in smem, then coalesced global writes ----
    __syncthreads();
    float* buf = (float*)smem;
    {
        const int rq = lane >> 2;
        const int cq = (lane & 3) * 2;
        #pragma unroll
        for (int mt = 0; mt < 4; mt++)
            #pragma unroll
            for (int nt = 0; nt < 8; nt++) {
                int r0 = wm * 64 + mt * 16 + rq;
                int c0 = wn * 64 + nt * 8 + cq;
                *(float2*)&buf[r0 * EPI_LD + c0]       = make_float2(acc[mt][nt][0], acc[mt][nt][1]);
                *(float2*)&buf[(r0 + 8) * EPI_LD + c0] = make_float2(acc[mt][nt][2], acc[mt][nt][3]);
            }
    }
    __syncthreads();

    if (mode == 0) {
        int r = tid;
        long row = (long)by * 128 + r;
        float4* dst = (float4*)(Cf + bz * strideC + row * ldC + (long)bx * 128);
        #pragma unroll
        for (int i = 0; i < 32; i++)
            dst[i] = *(float4*)&buf[r * EPI_LD + i * 4];
    } else if (mode == 1) {
        int r = tid;
        long row = (long)by * 128 + r;
        bf16* dh = Chi + bz * strideC + row * ldC + (long)bx * 128;
        bf16* dl = Clo + bz * strideC + row * ldC + (long)bx * 128;
        #pragma unroll
        for (int v = 0; v < 16; v++) {
            uint4 uh, ul;
            uint32_t* ph = (uint32_t*)&uh; uint32_t* pl = (uint32_t*)&ul;
            #pragma unroll
            for (int p = 0; p < 4; p++) {
                float f0 = buf[r * EPI_LD + v * 8 + p * 2];
                float f1 = buf[r * EPI_LD + v * 8 + p * 2 + 1];
                bf16 h0 = __float2bfloat16(f0), h1 = __float2bfloat16(f1);
                bf16 l0 = __float2bfloat16(f0 - __bfloat162float(h0));
                bf16 l1 = __float2bfloat16(f1 - __bfloat162float(h1));
                ph[p] = (uint32_t)*(uint16_t*)&h0 | ((uint32_t)*(uint16_t*)&h1 << 16);
                pl[p] = (uint32_t)*(uint16_t*)&l0 | ((uint32_t)*(uint16_t*)&l1 << 16);
            }
            *(uint4*)(dh + v * 8) = uh;
            *(uint4*)(dl + v * 8) = ul;
        }
    } else {
        // transposed hi/lo out: Ct[e][s_local], batch derived from global row
        int cc = tid;
        int rowbase = by * 128;
        int b = rowbase / SEQ;
        int sloc = rowbase % SEQ;
        long e = (long)bx * 128 + cc;
        bf16* dh = Chi + b * strideC + e * ldC + sloc;
        bf16* dl = Clo + b * strideC + e * ldC + sloc;
        #pragma unroll
        for (int v = 0; v < 16; v++) {
            uint4 uh, ul;
            uint32_t* ph = (uint32_t*)&uh; uint32_t* pl = (uint32_t*)&ul;
            #pragma unroll
            for (int p = 0; p < 4; p++) {
                float f0 = buf[(v * 8 + p * 2)     * EPI_LD + cc];
                float f1 = buf[(v * 8 + p * 2 + 1) * EPI_LD + cc];
                bf16 h0 = __float2bfloat16(f0), h1 = __float2bfloat16(f1);
                bf16 l0 = __float2bfloat16(f0 - __bfloat162float(h0));
                bf16 l1 = __float2bfloat16(f1 - __bfloat162float(h1));
                ph[p] = (uint32_t)*(uint16_t*)&h0 | ((uint32_t)*(uint16_t*)&h1 << 16);
                pl[p] = (uint32_t)*(uint16_t*)&l0 | ((uint32_t)*(uint16_t*)&l1 << 16);
            }
            *(uint4*)(dh + v * 8) = uh;
            *(uint4*)(dl + v * 8) = ul;
        }
    }
}

// ---------------- fp32 -> bf16 hi/lo split ----------------
__device__ __forceinline__ void split4(const float* __restrict__ src,
                                       bf16* __restrict__ hi, bf16* __restrict__ lo, long i)
{
    float4 v = *(const float4*)(src + i);
    float f[4] = {v.x, v.y, v.z, v.w};
    uint32_t h2[2], l2[2];
    #pragma unroll
    for (int p = 0; p < 2; p++) {
        bf16 h0 = __float2bfloat16(f[p*2]),   h1 = __float2bfloat16(f[p*2+1]);
        bf16 l0 = __float2bfloat16(f[p*2]   - __bfloat162float(h0));
        bf16 l1 = __float2bfloat16(f[p*2+1] - __bfloat162float(h1));
        h2[p] = (uint32_t)*(uint16_t*)&h0 | ((uint32_t)*(uint16_t*)&h1 << 16);
        l2[p] = (uint32_t)*(uint16_t*)&l0 | ((uint32_t)*(uint16_t*)&l1 << 16);
    }
    *(uint2*)(hi + i) = make_uint2(h2[0], h2[1]);
    *(uint2*)(lo + i) = make_uint2(l2[0], l2[1]);
}

__global__ void __launch_bounds__(256) split_f32(
    const float* __restrict__ src, bf16* __restrict__ hi, bf16* __restrict__ lo, long n)
{
    long i = ((long)blockIdx.x * 256 + threadIdx.x) * 4;
    if (i >= n) return;
    split4(src, hi, lo, i);
}

// transpose + split for Wq (z=0) and Wk (z=1): out[d][e] = in[e][d]
__global__ void __launch_bounds__(256) tsplit_w(
    const float* __restrict__ w0, const float* __restrict__ w1,
    bf16* __restrict__ hi, bf16* __restrict__ lo)
{
    const float* src = (blockIdx.z == 0) ? w0 : w1;
    bf16* dh = hi + (long)blockIdx.z * NW;
    bf16* dl = lo + (long)blockIdx.z * NW;

    __shared__ float t[32][33];
    const int tx = threadIdx.x & 31;
    const int ty = threadIdx.x >> 5;   // 0..7
    int x = blockIdx.x * 32 + tx;
    #pragma unroll
    for (int j = 0; j < 4; j++) {
        int y = blockIdx.y * 32 + ty + j * 8;
        t[ty + j * 8][tx] = src[(long)y * DIM + x];
    }
    __syncthreads();
    int xo = blockIdx.y * 32 + tx;
    #pragma unroll
    for (int j = 0; j < 4; j++) {
        int yo = blockIdx.x * 32 + ty + j * 8;
        float f = t[tx][ty + j * 8];
        bf16 h = __float2bfloat16(f);
        bf16 l = __float2bfloat16(f - __bfloat162float(h));
        dh[(long)yo * DIM + xo] = h;
        dl[(long)yo * DIM + xo] = l;
    }
}

// reduce 8 fp32 partials -> bf16 hi/lo
__global__ void __launch_bounds__(256) reduce8_split(
    const float* __restrict__ part, bf16* __restrict__ hi, bf16* __restrict__ lo)
{
    long i = ((long)blockIdx.x * 256 + threadIdx.x) * 4;
    if (i >= NW) return;
    float4 s = *(const float4*)(part + i);
    #pragma unroll
    for (int j = 1; j < 8; j++) {
        float4 v = *(const float4*)(part + j * NW + i);
        s.x += v.x; s.y += v.y; s.z += v.z; s.w += v.w;
    }
    float f[4] = {s.x, s.y, s.z, s.w};
    uint32_t h2[2], l2[2];
    #pragma unroll
    for (int p = 0; p < 2; p++) {
        bf16 h0 = __float2bfloat16(f[p*2]),   h1 = __float2bfloat16(f[p*2+1]);
        bf16 l0 = __float2bfloat16(f[p*2]   - __bfloat162float(h0));
        bf16 l1 = __float2bfloat16(f[p*2+1] - __bfloat162float(h1));
        h2[p] = (uint32_t)*(uint16_t*)&h0 | ((uint32_t)*(uint16_t*)&h1 << 16);
        l2[p] = (uint32_t)*(uint16_t*)&l0 | ((uint32_t)*(uint16_t*)&l1 << 16);
    }
    *(uint2*)(hi + i) = make_uint2(h2[0], h2[1]);
    *(uint2*)(lo + i) = make_uint2(l2[0], l2[1]);
}

// ---------------- causal softmax: fp32 scores -> bf16 hi/lo probs ----------------
__global__ void __launch_bounds__(256) softmax_causal(
    const float* __restrict__ Sc, bf16* __restrict__ Ph, bf16* __restrict__ Pl)
{
    const long r = blockIdx.x;
    const int  q = (int)(r & (SEQ - 1));
    const float* row = Sc + r * SEQ;
    bf16* ph = Ph + r * SEQ;
    bf16* pl = Pl + r * SEQ;

    __shared__ float bufr[SEQ];
    __shared__ float red[256];

    const int tid = threadIdx.x;
    const int len = q + 1;
    const float scale = 0.03125f;  // 1/sqrt(1024)

    float m = -1e30f;
    for (int k = tid; k < len; k += 256) {
        float v = row[k] * scale;
        bufr[k] = v;
        m = fmaxf(m, v);
    }
    red[tid] = m;
    __syncthreads();
    #pragma unroll
    for (int s = 128; s > 0; s >>= 1) {
        if (tid < s) red[tid] = fmaxf(red[tid], red[tid + s]);
        __syncthreads();
    }
    m = red[0];
    __syncthreads();

    float sum = 0.f;
    for (int k = tid; k < len; k += 256) {
        float e = __expf(bufr[k] - m);
        bufr[k] = e;
        sum += e;
    }
    red[tid] = sum;
    __syncthreads();
    #pragma unroll
    for (int s = 128; s > 0; s >>= 1) {
        if (tid < s) red[tid] += red[tid + s];
        __syncthreads();
    }
    const float inv = 1.0f / red[0];
    __syncthreads();

    for (int k = tid; k < len; k += 256) {
        float p = bufr[k] * inv;
        bf16 h = __float2bfloat16(p);
        bf16 l = __float2bfloat16(p - __bfloat162float(h));
        ph[k] = h; pl[k] = l;
    }
    const bf16 z = __float2bfloat16(0.f);
    for (int k = len + tid; k < SEQ; k += 256) { ph[k] = z; pl[k] = z; }
}

// ---------------------------------------------------------------------------
extern "C" void kernel_launch(void* const* d_in, const int* in_sizes, int n_in,
                              void* d_out, int out_size)
{
    const float* X  = (const float*)d_in[0];
    const float* Wq = (const float*)d_in[1];
    const float* Wk = (const float*)d_in[2];
    const float* Wv = (const float*)d_in[3];
    float* out = (float*)d_out;

    bf16 *xh, *xl, *wh, *wl, *mh, *ml, *oh, *ol, *ph, *pl;
    float *mpart, *sc;
    cudaGetSymbolAddress((void**)&xh, g_xh);  cudaGetSymbolAddress((void**)&xl, g_xl);
    cudaGetSymbolAddress((void**)&wh, g_wh);  cudaGetSymbolAddress((void**)&wl, g_wl);
    cudaGetSymbolAddress((void**)&mh, g_mh);  cudaGetSymbolAddress((void**)&ml, g_ml);
    cudaGetSymbolAddress((void**)&mpart, g_mpart);
    cudaGetSymbolAddress((void**)&oh, g_oh);  cudaGetSymbolAddress((void**)&ol, g_ol);
    cudaGetSymbolAddress((void**)&sc, g_sc);
    cudaGetSymbolAddress((void**)&ph, g_ph);  cudaGetSymbolAddress((void**)&pl, g_pl);

    cudaFuncSetAttribute(gemm_bf16x3, cudaFuncAttributeMaxDynamicSharedMemorySize, SMEM_TOTAL);

    const long nX = NX, nW = NW;
    const int M = BATCH * SEQ;  // 8192

    dim3 thr256(256);
    dim3 thr128(128);

    // splits: X (hi/lo), Wq^T -> wh[0], Wk^T -> wh[1], Wv -> wh[2]
    split_f32<<<(unsigned)(nX / 1024), thr256>>>(X, xh, xl, nX);
    dim3 gT(DIM / 32, DIM / 32, 2);
    tsplit_w<<<gT, thr256>>>(Wq, Wk, wh, wl);
    split_f32<<<(unsigned)(nW / 1024), thr256>>>(Wv, wh + 2 * nW, wl + 2 * nW, nW);

    // M' = Wk^T-rows x Wq^T-rows (NT), split-K over z=8, fp32 partials
    dim3 gM(DIM / 128, DIM / 128, 8);
    gemm_bf16x3<<<gM, thr128, SMEM_TOTAL>>>(wh + nW, wl + nW, wh, wl,
        mpart, nullptr, nullptr, DIM / 8, DIM, DIM, DIM,
        0, 0, nW, 0, 0, 0, 1);
    reduce8_split<<<(unsigned)(nW / 1024), thr256>>>(mpart, mh, ml);

    // V^T projection: mode 2 -> oh+2nX  ([b][e][s])
    dim3 gProj(DIM / 128, M / 128, 1);
    gemm_bf16x3<<<gProj, thr128, SMEM_TOTAL>>>(xh, xl, wh + 2 * nW, wl + 2 * nW,
        nullptr, oh + 2 * nX, ol + 2 * nX, DIM, DIM, DIM, SEQ,
        0, 0, (long)DIM * SEQ, 0, 0, 2, 0);

    // T = X @ M'^T : mode 1 -> oh
    gemm_bf16x3<<<gProj, thr128, SMEM_TOTAL>>>(xh, xl, mh, ml,
        nullptr, oh, ol, DIM, DIM, DIM, DIM,
        0, 0, 0, 0, 0, 1, 0);

    // scores = T @ X^T per batch (causal tile skip), fp32 out
    dim3 gScore(SEQ / 128, SEQ / 128, BATCH);
    gemm_bf16x3<<<gScore, thr128, SMEM_TOTAL>>>(oh, ol, xh, xl,
        sc, nullptr, nullptr, DIM, DIM, DIM, SEQ,
        (long)SEQ * DIM, (long)SEQ * DIM, (long)SEQ * SEQ, 1, 0, 0, 0);

    // softmax -> bf16 hi/lo probs
    softmax_causal<<<BATCH * SEQ, thr256>>>(sc, ph, pl);

    // out = P @ V^T per batch (causal k clamp), fp32 out
    dim3 gAV(DIM / 128, SEQ / 128, BATCH);
    gemm_bf16x3<<<gAV, thr128, SMEM_TOTAL>>>(ph, pl, oh + 2 * nX, ol + 2 * nX,
        out, nullptr, nullptr, SEQ, SEQ, SEQ, DIM,
        (long)SEQ * SEQ, (long)DIM * SEQ, (long)SEQ * DIM, 0, 1, 0, 0);
}

// round 10
// speedup vs baseline: 1.3743x; 1.1629x over previous
#include <cuda_runtime.h>
#include <cuda_fp16.h>
#include <cstdint>

#define BATCH 4
#define SEQ   2048
#define DIM   1024

typedef __half f16;

static const long NX = (long)BATCH * SEQ * DIM;   // 8388608
static const long NW = (long)DIM * DIM;           // 1048576

// ---------------- scratch (device globals; allocation-free) ----------------
__device__ __align__(128) f16   g_xh[(long)BATCH*SEQ*DIM];
__device__ __align__(128) f16   g_xl[(long)BATCH*SEQ*DIM];
// [0]=Wq^T, [1]=Wk^T, [2]=Wv (row-major as given)
__device__ __align__(128) f16   g_wh[3][(long)DIM*DIM];
__device__ __align__(128) f16   g_wl[3][(long)DIM*DIM];
// M' split-K fp32 partials and final f16 hi/lo
__device__ __align__(128) float g_mpart[8*(long)DIM*DIM];
__device__ __align__(128) f16   g_mh[(long)DIM*DIM];
__device__ __align__(128) f16   g_ml[(long)DIM*DIM];
// stacked outputs: [0]=T, [2]=V^T ([b][e][s])
__device__ __align__(128) f16   g_oh[3*(long)BATCH*SEQ*DIM];
__device__ __align__(128) f16   g_ol[3*(long)BATCH*SEQ*DIM];
__device__ __align__(128) float g_sc [(long)BATCH*SEQ*SEQ];
__device__ __align__(128) f16   g_ph [(long)BATCH*SEQ*SEQ];
__device__ __align__(128) f16   g_pl [(long)BATCH*SEQ*SEQ];

// ---------------- PTX helpers (arch-generic; NO tcgen05) ----------------
__device__ __forceinline__ uint32_t smem_u32(const void* p) {
    uint32_t a;
    asm("{ .reg .u64 t; cvta.to.shared.u64 t, %1; cvt.u32.u64 %0, t; }" : "=r"(a) : "l"(p));
    return a;
}
__device__ __forceinline__ void cp16(uint32_t saddr, const void* g) {
    asm volatile("cp.async.cg.shared.global [%0], [%1], 16;" :: "r"(saddr), "l"(g) : "memory");
}
#define CP_COMMIT() asm volatile("cp.async.commit_group;" ::: "memory")

__device__ __forceinline__ void ldsm_x4(uint32_t* r, uint32_t addr) {
    asm volatile("ldmatrix.sync.aligned.m8n8.x4.shared.b16 {%0,%1,%2,%3}, [%4];"
        : "=r"(r[0]), "=r"(r[1]), "=r"(r[2]), "=r"(r[3]) : "r"(addr));
}
__device__ __forceinline__ void mma16816(float* c, const uint32_t* a, const uint32_t* b) {
    asm volatile("mma.sync.aligned.m16n8k16.row.col.f32.f16.f16.f32 "
        "{%0,%1,%2,%3}, {%4,%5,%6,%7}, {%8,%9}, {%0,%1,%2,%3};"
        : "+f"(c[0]), "+f"(c[1]), "+f"(c[2]), "+f"(c[3])
        : "r"(a[0]), "r"(a[1]), "r"(a[2]), "r"(a[3]), "r"(b[0]), "r"(b[1]));
}

__device__ __forceinline__ uint32_t swz(int row, int kc) {
    return (uint32_t)(row * 64 + ((kc ^ ((row >> 1) & 3)) << 4));
}

// fp16 hi/lo split of one float
__device__ __forceinline__ void fsplit(float f, f16& h, f16& l) {
    h = __float2half_rn(f);
    l = __float2half_rn(f - __half2float(h));
}

// ---------------- SMEM layout ----------------
#define STAGES 3
#define STAGE_BYTES 32768
#define EPI_LD 132
#define SMEM_TOTAL (STAGES * STAGE_BYTES)

// =====================================================================
// fp16 hi/lo NT GEMM via mma.sync: 128x128 CTA tile, 128 threads,
// 4 warps x (64x64) warp tile.
// npass=3: hh + hl + lh   (B_lo loaded)
// npass=2: hh + lh        (B_lo never touched)
// mode 0: fp32 C;  mode 1: f16 hi/lo C;  mode 2: f16 hi/lo C transposed
// ksplit: when 1, this block computes K-window [bz*K, (bz+1)*K)
// =====================================================================
__global__ void __launch_bounds__(128, 2) gemm_f16x(
    const f16* __restrict__ Ahi, const f16* __restrict__ Alo,
    const f16* __restrict__ Bhi, const f16* __restrict__ Blo,
    float* __restrict__ Cf, f16* __restrict__ Chi, f16* __restrict__ Clo,
    int K, int ldA, int ldB, int ldC,
    long strideA, long strideB, long strideC,
    int causal, int kclamp, int mode, int ksplit, int npass)
{
    const int bx = blockIdx.x, by = blockIdx.y, bz = blockIdx.z;
    if (causal && bx > by) return;

    extern __shared__ char smem[];
    const uint32_t sbase = smem_u32(smem);
    const int tid  = threadIdx.x;        // 0..127
    const int lane = tid & 31;
    const int wid  = tid >> 5;           // 0..3
    const int wm   = wid >> 1;           // 0..1 : 64 rows
    const int wn   = wid & 1;            // 0..1 : 64 cols

    const int kbase   = ksplit ? bz * K : 0;
    const int kmax    = kclamp ? min(K, (by + 1) * 128) : K;
    const int nchunks = kmax >> 5;       // BK = 32

    const f16* pAh = Ahi + bz * strideA + (long)by * 128 * ldA;
    const f16* pAl = Alo + bz * strideA + (long)by * 128 * ldA;
    const f16* pBh = Bhi + bz * strideB + (long)bx * 128 * ldB;
    const f16* pBl = Blo + bz * strideB + (long)bx * 128 * ldB;

    auto load_chunk = [&](int c) {
        const uint32_t st = sbase + (uint32_t)(c % STAGES) * STAGE_BYTES;
        const int k0 = kbase + (c << 5);
        #pragma unroll
        for (int i = 0; i < 4; i++) {
            int id  = tid + i * 128;       // 0..511
            int row = id >> 2, kc = id & 3;
            uint32_t so = swz(row, kc);
            long gA = (long)row * ldA + k0 + kc * 8;
            long gB = (long)row * ldB + k0 + kc * 8;
            cp16(st +         so, pAh + gA);
            cp16(st +  8192 + so, pAl + gA);
            cp16(st + 16384 + so, pBh + gB);
            if (npass == 3) cp16(st + 24576 + so, pBl + gB);
        }
        CP_COMMIT();
    };

    float acc[4][8][4];
    #pragma unroll
    for (int i = 0; i < 4; i++)
        #pragma unroll
        for (int j = 0; j < 8; j++)
            #pragma unroll
            for (int p = 0; p < 4; p++) acc[i][j][p] = 0.f;

    load_chunk(0);
    if (nchunks > 1) load_chunk(1);

    const int lrow = lane & 15;
    const int lsel = lane >> 4;
    const int arow = wm * 64 + lrow;
    const int brow = wn * 64 + lrow;

    for (int c = 0; c < nchunks; c++) {
        if (c + 1 < nchunks) asm volatile("cp.async.wait_group 1;" ::: "memory");
        else                 asm volatile("cp.async.wait_group 0;" ::: "memory");
        __syncthreads();

        if (c + 2 < nchunks) load_chunk(c + 2);

        const uint32_t st  = sbase + (uint32_t)(c % STAGES) * STAGE_BYTES;
        const uint32_t sAh = st, sAl = st + 8192, sBh = st + 16384, sBl = st + 24576;

        #pragma unroll
        for (int ks = 0; ks < 2; ks++) {
            const int kc = ks * 2 + lsel;
            uint32_t bh[8][2];
            #pragma unroll
            for (int np = 0; np < 4; np++) {
                int r = brow + np * 16;
                uint32_t t4[4];
                ldsm_x4(t4, sBh + swz(r, kc));
                bh[np*2][0] = t4[0]; bh[np*2][1] = t4[2];
                bh[np*2+1][0] = t4[1]; bh[np*2+1][1] = t4[3];
            }
            uint32_t aH[4][4];
            #pragma unroll
            for (int mt = 0; mt < 4; mt++)
                ldsm_x4(aH[mt], sAh + swz(arow + mt * 16, kc));

            // pass 1: aH x bh
            #pragma unroll
            for (int mt = 0; mt < 4; mt++)
                #pragma unroll
                for (int nt = 0; nt < 8; nt++)
                    mma16816(acc[mt][nt], aH[mt], bh[nt]);

            // pass 2 (npass==3 only): aH x bl
            if (npass == 3) {
                uint32_t bl[8][2];
                #pragma unroll
                for (int np = 0; np < 4; np++) {
                    int r = brow + np * 16;
                    uint32_t t4[4];
                    ldsm_x4(t4, sBl + swz(r, kc));
                    bl[np*2][0] = t4[0]; bl[np*2][1] = t4[2];
                    bl[np*2+1][0] = t4[1]; bl[np*2+1][1] = t4[3];
                }
                #pragma unroll
                for (int mt = 0; mt < 4; mt++)
                    #pragma unroll
                    for (int nt = 0; nt < 8; nt++)
                        mma16816(acc[mt][nt], aH[mt], bl[nt]);
            }

            // pass 3: aL x bh (aL streamed)
            uint32_t aL[2][4];
            ldsm_x4(aL[0], sAl + swz(arow, kc));
            #pragma unroll
            for (int mt = 0; mt < 4; mt++) {
                const int cur = mt & 1;
                if (mt < 3)
                    ldsm_x4(aL[cur ^ 1], sAl + swz(arow + (mt + 1) * 16, kc));
                #pragma unroll
                for (int nt = 0; nt < 8; nt++)
                    mma16816(acc[mt][nt], aL[cur], bh[nt]);
            }
        }
    }

    // ---- epilogue: stage fp32 tile in smem, then coalesced global writes ----
    __syncthreads();
    float* buf = (float*)smem;
    {
        const int rq = lane >> 2;
        const int cq = (lane & 3) * 2;
        #pragma unroll
        for (int mt = 0; mt < 4; mt++)
            #pragma unroll
            for (int nt = 0; nt < 8; nt++) {
                int r0 = wm * 64 + mt * 16 + rq;
                int c0 = wn * 64 + nt * 8 + cq;
                *(float2*)&buf[r0 * EPI_LD + c0]       = make_float2(acc[mt][nt][0], acc[mt][nt][1]);
                *(float2*)&buf[(r0 + 8) * EPI_LD + c0] = make_float2(acc[mt][nt][2], acc[mt][nt][3]);
            }
    }
    __syncthreads();

    if (mode == 0) {
        int r = tid;
        long row = (long)by * 128 + r;
        float4* dst = (float4*)(Cf + bz * strideC + row * ldC + (long)bx * 128);
        #pragma unroll
        for (int i = 0; i < 32; i++)
            dst[i] = *(float4*)&buf[r * EPI_LD + i * 4];
    } else if (mode == 1) {
        int r = tid;
        long row = (long)by * 128 + r;
        f16* dh = Chi + bz * strideC + row * ldC + (long)bx * 128;
        f16* dl = Clo + bz * strideC + row * ldC + (long)bx * 128;
        #pragma unroll
        for (int v = 0; v < 16; v++) {
            uint4 uh, ul;
            uint32_t* ph = (uint32_t*)&uh; uint32_t* pl = (uint32_t*)&ul;
            #pragma unroll
            for (int p = 0; p < 4; p++) {
                float f0 = buf[r * EPI_LD + v * 8 + p * 2];
                float f1 = buf[r * EPI_LD + v * 8 + p * 2 + 1];
                f16 h0, l0, h1, l1;
                fsplit(f0, h0, l0); fsplit(f1, h1, l1);
                ph[p] = (uint32_t)*(uint16_t*)&h0 | ((uint32_t)*(uint16_t*)&h1 << 16);
                pl[p] = (uint32_t)*(uint16_t*)&l0 | ((uint32_t)*(uint16_t*)&l1 << 16);
            }
            *(uint4*)(dh + v * 8) = uh;
            *(uint4*)(dl + v * 8) = ul;
        }
    } else {
        // transposed hi/lo out: Ct[e][s_local], batch derived from global row
        int cc = tid;
        int rowbase = by * 128;
        int b = rowbase / SEQ;
        int sloc = rowbase % SEQ;
        long e = (long)bx * 128 + cc;
        f16* dh = Chi + b * strideC + e * ldC + sloc;
        f16* dl = Clo + b * strideC + e * ldC + sloc;
        #pragma unroll
        for (int v = 0; v < 16; v++) {
            uint4 uh, ul;
            uint32_t* ph = (uint32_t*)&uh; uint32_t* pl = (uint32_t*)&ul;
            #pragma unroll
            for (int p = 0; p < 4; p++) {
                float f0 = buf[(v * 8 + p * 2)     * EPI_LD + cc];
                float f1 = buf[(v * 8 + p * 2 + 1) * EPI_LD + cc];
                f16 h0, l0, h1, l1;
                fsplit(f0, h0, l0); fsplit(f1, h1, l1);
                ph[p] = (uint32_t)*(uint16_t*)&h0 | ((uint32_t)*(uint16_t*)&h1 << 16);
                pl[p] = (uint32_t)*(uint16_t*)&l0 | ((uint32_t)*(uint16_t*)&l1 << 16);
            }
            *(uint4*)(dh + v * 8) = uh;
            *(uint4*)(dl + v * 8) = ul;
        }
    }
}

// ---------------- fp32 -> f16 hi/lo split ----------------
__device__ __forceinline__ void split4(const float* __restrict__ src,
                                       f16* __restrict__ hi, f16* __restrict__ lo, long i)
{
    float4 v = *(const float4*)(src + i);
    float f[4] = {v.x, v.y, v.z, v.w};
    uint32_t h2[2], l2[2];
    #pragma unroll
    for (int p = 0; p < 2; p++) {
        f16 h0, l0, h1, l1;
        fsplit(f[p*2],   h0, l0);
        fsplit(f[p*2+1], h1, l1);
        h2[p] = (uint32_t)*(uint16_t*)&h0 | ((uint32_t)*(uint16_t*)&h1 << 16);
        l2[p] = (uint32_t)*(uint16_t*)&l0 | ((uint32_t)*(uint16_t*)&l1 << 16);
    }
    *(uint2*)(hi + i) = make_uint2(h2[0], h2[1]);
    *(uint2*)(lo + i) = make_uint2(l2[0], l2[1]);
}

__global__ void __launch_bounds__(256) split_f32(
    const float* __restrict__ src, f16* __restrict__ hi, f16* __restrict__ lo, long n)
{
    long i = ((long)blockIdx.x * 256 + threadIdx.x) * 4;
    if (i >= n) return;
    split4(src, hi, lo, i);
}

// transpose + split for Wq (z=0) and Wk (z=1): out[d][e] = in[e][d]
__global__ void __launch_bounds__(256) tsplit_w(
    const float* __restrict__ w0, const float* __restrict__ w1,
    f16* __restrict__ hi, f16* __restrict__ lo)
{
    const float* src = (blockIdx.z == 0) ? w0 : w1;
    f16* dh = hi + (long)blockIdx.z * NW;
    f16* dl = lo + (long)blockIdx.z * NW;

    __shared__ float t[32][33];
    const int tx = threadIdx.x & 31;
    const int ty = threadIdx.x >> 5;   // 0..7
    int x = blockIdx.x * 32 + tx;
    #pragma unroll
    for (int j = 0; j < 4; j++) {
        int y = blockIdx.y * 32 + ty + j * 8;
        t[ty + j * 8][tx] = src[(long)y * DIM + x];
    }
    __syncthreads();
    int xo = blockIdx.y * 32 + tx;
    #pragma unroll
    for (int j = 0; j < 4; j++) {
        int yo = blockIdx.x * 32 + ty + j * 8;
        float f = t[tx][ty + j * 8];
        f16 h, l;
        fsplit(f, h, l);
        dh[(long)yo * DIM + xo] = h;
        dl[(long)yo * DIM + xo] = l;
    }
}

// reduce 8 fp32 partials -> f16 hi/lo
__global__ void __launch_bounds__(256) reduce8_split(
    const float* __restrict__ part, f16* __restrict__ hi, f16* __restrict__ lo)
{
    long i = ((long)blockIdx.x * 256 + threadIdx.x) * 4;
    if (i >= NW) return;
    float4 s = *(const float4*)(part + i);
    #pragma unroll
    for (int j = 1; j < 8; j++) {
        float4 v = *(const float4*)(part + j * NW + i);
        s.x += v.x; s.y += v.y; s.z += v.z; s.w += v.w;
    }
    float f[4] = {s.x, s.y, s.z, s.w};
    uint32_t h2[2], l2[2];
    #pragma unroll
    for (int p = 0; p < 2; p++) {
        f16 h0, l0, h1, l1;
        fsplit(f[p*2],   h0, l0);
        fsplit(f[p*2+1], h1, l1);
        h2[p] = (uint32_t)*(uint16_t*)&h0 | ((uint32_t)*(uint16_t*)&h1 << 16);
        l2[p] = (uint32_t)*(uint16_t*)&l0 | ((uint32_t)*(uint16_t*)&l1 << 16);
    }
    *(uint2*)(hi + i) = make_uint2(h2[0], h2[1]);
    *(uint2*)(lo + i) = make_uint2(l2[0], l2[1]);
}

// ---------------- causal softmax: fp32 scores -> f16 hi/lo probs ----------------
__global__ void __launch_bounds__(256) softmax_causal(
    const float* __restrict__ Sc, f16* __restrict__ Ph, f16* __restrict__ Pl)
{
    const long r = blockIdx.x;
    const int  q = (int)(r & (SEQ - 1));
    const float* row = Sc + r * SEQ;
    f16* ph = Ph + r * SEQ;
    f16* pl = Pl + r * SEQ;

    __shared__ float bufr[SEQ];
    __shared__ float red[256];

    const int tid = threadIdx.x;
    const int len = q + 1;
    const float scale = 0.03125f;  // 1/sqrt(1024)

    float m = -1e30f;
    for (int k = tid; k < len; k += 256) {
        float v = row[k] * scale;
        bufr[k] = v;
        m = fmaxf(m, v);
    }
    red[tid] = m;
    __syncthreads();
    #pragma unroll
    for (int s = 128; s > 0; s >>= 1) {
        if (tid < s) red[tid] = fmaxf(red[tid], red[tid + s]);
        __syncthreads();
    }
    m = red[0];
    __syncthreads();

    float sum = 0.f;
    for (int k = tid; k < len; k += 256) {
        float e = __expf(bufr[k] - m);
        bufr[k] = e;
        sum += e;
    }
    red[tid] = sum;
    __syncthreads();
    #pragma unroll
    for (int s = 128; s > 0; s >>= 1) {
        if (tid < s) red[tid] += red[tid + s];
        __syncthreads();
    }
    const float inv = 1.0f / red[0];
    __syncthreads();

    for (int k = tid; k < len; k += 256) {
        float p = bufr[k] * inv;
        f16 h, l;
        fsplit(p, h, l);
        ph[k] = h; pl[k] = l;
    }
    const f16 z = __float2half(0.f);
    for (int k = len + tid; k < SEQ; k += 256) { ph[k] = z; pl[k] = z; }
}

// ---------------------------------------------------------------------------
extern "C" void kernel_launch(void* const* d_in, const int* in_sizes, int n_in,
                              void* d_out, int out_size)
{
    const float* X  = (const float*)d_in[0];
    const float* Wq = (const float*)d_in[1];
    const float* Wk = (const float*)d_in[2];
    const float* Wv = (const float*)d_in[3];
    float* out = (float*)d_out;

    f16 *xh, *xl, *wh, *wl, *mh, *ml, *oh, *ol, *ph, *pl;
    float *mpart, *sc;
    cudaGetSymbolAddress((void**)&xh, g_xh);  cudaGetSymbolAddress((void**)&xl, g_xl);
    cudaGetSymbolAddress((void**)&wh, g_wh);  cudaGetSymbolAddress((void**)&wl, g_wl);
    cudaGetSymbolAddress((void**)&mh, g_mh);  cudaGetSymbolAddress((void**)&ml, g_ml);
    cudaGetSymbolAddress((void**)&mpart, g_mpart);
    cudaGetSymbolAddress((void**)&oh, g_oh);  cudaGetSymbolAddress((void**)&ol, g_ol);
    cudaGetSymbolAddress((void**)&sc, g_sc);
    cudaGetSymbolAddress((void**)&ph, g_ph);  cudaGetSymbolAddress((void**)&pl, g_pl);

    cudaFuncSetAttribute(gemm_f16x, cudaFuncAttributeMaxDynamicSharedMemorySize, SMEM_TOTAL);

    const long nX = NX, nW = NW;
    const int M = BATCH * SEQ;  // 8192

    dim3 thr256(256);
    dim3 thr128(128);

    // splits: X (hi/lo), Wq^T -> wh[0], Wk^T -> wh[1], Wv -> wh[2]
    split_f32<<<(unsigned)(nX / 1024), thr256>>>(X, xh, xl, nX);
    dim3 gT(DIM / 32, DIM / 32, 2);
    tsplit_w<<<gT, thr256>>>(Wq, Wk, wh, wl);
    split_f32<<<(unsigned)(nW / 1024), thr256>>>(Wv, wh + 2 * nW, wl + 2 * nW, nW);

    // M' = Wk^T-rows x Wq^T-rows (NT), split-K over z=8, fp32 partials; 3-pass
    dim3 gM(DIM / 128, DIM / 128, 8);
    gemm_f16x<<<gM, thr128, SMEM_TOTAL>>>(wh + nW, wl + nW, wh, wl,
        mpart, nullptr, nullptr, DIM / 8, DIM, DIM, DIM,
        0, 0, nW, 0, 0, 0, 1, 3);
    reduce8_split<<<(unsigned)(nW / 1024), thr256>>>(mpart, mh, ml);

    // V^T projection: mode 2 -> oh+2nX  ([b][e][s]); 2-pass (Wv_lo unused)
    dim3 gProj(DIM / 128, M / 128, 1);
    gemm_f16x<<<gProj, thr128, SMEM_TOTAL>>>(xh, xl, wh + 2 * nW, wl + 2 * nW,
        nullptr, oh + 2 * nX, ol + 2 * nX, DIM, DIM, DIM, SEQ,
        0, 0, (long)DIM * SEQ, 0, 0, 2, 0, 2);

    // T = X @ M'^T : mode 1 -> oh; 2-pass (M'_lo unused)
    gemm_f16x<<<gProj, thr128, SMEM_TOTAL>>>(xh, xl, mh, ml,
        nullptr, oh, ol, DIM, DIM, DIM, DIM,
        0, 0, 0, 0, 0, 1, 0, 2);

    // scores = T @ X^T per batch (causal tile skip), fp32 out; 2-pass
    dim3 gScore(SEQ / 128, SEQ / 128, BATCH);
    gemm_f16x<<<gScore, thr128, SMEM_TOTAL>>>(oh, ol, xh, xl,
        sc, nullptr, nullptr, DIM, DIM, DIM, SEQ,
        (long)SEQ * DIM, (long)SEQ * DIM, (long)SEQ * SEQ, 1, 0, 0, 0, 2);

    // softmax -> f16 hi/lo probs
    softmax_causal<<<BATCH * SEQ, thr256>>>(sc, ph, pl);

    // out = P @ V^T per batch (causal k clamp), fp32 out; 3-pass (accuracy-critical)
    dim3 gAV(DIM / 128, SEQ / 128, BATCH);
    gemm_f16x<<<gAV, thr128, SMEM_TOTAL>>>(ph, pl, oh + 2 * nX, ol + 2 * nX,
        out, nullptr, nullptr, SEQ, SEQ, SEQ, DIM,
        (long)SEQ * SEQ, (long)DIM * SEQ, (long)SEQ * DIM, 0, 1, 0, 0, 3);
}

// round 11
// speedup vs baseline: 1.6639x; 1.2107x over previous
#include <cuda_runtime.h>
#include <cuda_fp16.h>
#include <cstdint>

#define BATCH 4
#define SEQ   2048
#define DIM   1024

typedef __half f16;

static const long NX = (long)BATCH * SEQ * DIM;   // 8388608
static const long NW = (long)DIM * DIM;           // 1048576
#define DNX ((long)BATCH * SEQ * DIM)

// ---------------- scratch (device globals; allocation-free) ----------------
__device__ __align__(128) f16   g_xh[(long)BATCH*SEQ*DIM];
__device__ __align__(128) f16   g_xl[(long)BATCH*SEQ*DIM];
// [0]=Wq^T, [1]=Wk^T, [2]=Wv (row-major as given)
__device__ __align__(128) f16   g_wh[3][(long)DIM*DIM];
__device__ __align__(128) f16   g_wl[3][(long)DIM*DIM];
// M' split-K fp32 partials and final f16 hi/lo
__device__ __align__(128) float g_mpart[4*(long)DIM*DIM];
__device__ __align__(128) f16   g_mh[(long)DIM*DIM];
__device__ __align__(128) f16   g_ml[(long)DIM*DIM];
// stacked outputs: [0]=T, [2]=V^T ([b][e][s]); lo of V^T unused
__device__ __align__(128) f16   g_oh[3*(long)BATCH*SEQ*DIM];
__device__ __align__(128) f16   g_ol[3*(long)BATCH*SEQ*DIM];
__device__ __align__(128) float g_sc [(long)BATCH*SEQ*SEQ];
__device__ __align__(128) f16   g_ph [(long)BATCH*SEQ*SEQ];
__device__ __align__(128) f16   g_pl [(long)BATCH*SEQ*SEQ];

// ---------------- PTX helpers (arch-generic; NO tcgen05) ----------------
__device__ __forceinline__ uint32_t smem_u32(const void* p) {
    uint32_t a;
    asm("{ .reg .u64 t; cvta.to.shared.u64 t, %1; cvt.u32.u64 %0, t; }" : "=r"(a) : "l"(p));
    return a;
}
__device__ __forceinline__ void cp16(uint32_t saddr, const void* g) {
    asm volatile("cp.async.cg.shared.global [%0], [%1], 16;" :: "r"(saddr), "l"(g) : "memory");
}
#define CP_COMMIT() asm volatile("cp.async.commit_group;" ::: "memory")

__device__ __forceinline__ void ldsm_x4(uint32_t* r, uint32_t addr) {
    asm volatile("ldmatrix.sync.aligned.m8n8.x4.shared.b16 {%0,%1,%2,%3}, [%4];"
        : "=r"(r[0]), "=r"(r[1]), "=r"(r[2]), "=r"(r[3]) : "r"(addr));
}
__device__ __forceinline__ void mma16816(float* c, const uint32_t* a, const uint32_t* b) {
    asm volatile("mma.sync.aligned.m16n8k16.row.col.f32.f16.f16.f32 "
        "{%0,%1,%2,%3}, {%4,%5,%6,%7}, {%8,%9}, {%0,%1,%2,%3};"
        : "+f"(c[0]), "+f"(c[1]), "+f"(c[2]), "+f"(c[3])
        : "r"(a[0]), "r"(a[1]), "r"(a[2]), "r"(a[3]), "r"(b[0]), "r"(b[1]));
}

__device__ __forceinline__ uint32_t swz(int row, int kc) {
    return (uint32_t)(row * 64 + ((kc ^ ((row >> 1) & 3)) << 4));
}

// fp16 hi/lo split of one float
__device__ __forceinline__ void fsplit(float f, f16& h, f16& l) {
    h = __float2half_rn(f);
    l = __float2half_rn(f - __half2float(h));
}

// ---------------- SMEM layout ----------------
#define STAGES 3
#define STAGE_BYTES 32768
#define EPI_LD 132
#define SMEM_TOTAL (STAGES * STAGE_BYTES)

// =====================================================================
// fp16 hi/lo NT GEMM via mma.sync: 128x128 CTA tile, 128 threads,
// 4 warps x (64x64) warp tile.
// npass=3: hh + hl + lh   (B_lo loaded)
// npass=2: hh + lh        (B_lo never touched)
// mode 0: fp32 C;  mode 1: f16 hi/lo C;  mode 2: f16 hi/lo C transposed
// mode 4: fused — bz=0: B pair 1, mode-1 epilogue (T);
//                 bz=1: B pair 2 (B2hi/B2lo), mode-2 epilogue, hi only (V^T)
// ksplit: when 1, this block computes K-window [bz*K, (bz+1)*K)
// =====================================================================
__global__ void __launch_bounds__(128, 2) gemm_f16x(
    const f16* __restrict__ Ahi, const f16* __restrict__ Alo,
    const f16* __restrict__ Bhi, const f16* __restrict__ Blo,
    const f16* __restrict__ B2hi, const f16* __restrict__ B2lo,
    float* __restrict__ Cf, f16* __restrict__ Chi, f16* __restrict__ Clo,
    int K, int ldA, int ldB, int ldC,
    long strideA, long strideB, long strideC,
    int causal, int kclamp, int mode, int ksplit, int npass)
{
    const int bx = blockIdx.x, by = blockIdx.y, bz = blockIdx.z;
    if (causal && bx > by) return;

    // resolve fused submode
    const f16* Bh_ = Bhi;
    const f16* Bl_ = Blo;
    int  emode = mode, ldc = ldC;
    long sC = strideC, coff = 0;
    int  wlo = 1;
    if (mode == 4) {
        if (bz == 0) { emode = 1; ldc = DIM; sC = 0; }
        else {
            Bh_ = B2hi; Bl_ = B2lo;
            emode = 2; ldc = SEQ; sC = (long)DIM * SEQ;
            coff = 2 * DNX; wlo = 0;
        }
    }

    extern __shared__ char smem[];
    const uint32_t sbase = smem_u32(smem);
    const int tid  = threadIdx.x;        // 0..127
    const int lane = tid & 31;
    const int wid  = tid >> 5;           // 0..3
    const int wm   = wid >> 1;           // 0..1 : 64 rows
    const int wn   = wid & 1;            // 0..1 : 64 cols

    const int kbase   = ksplit ? bz * K : 0;
    const int kmax    = kclamp ? min(K, (by + 1) * 128) : K;
    const int nchunks = kmax >> 5;       // BK = 32

    const f16* pAh = Ahi + bz * strideA + (long)by * 128 * ldA;
    const f16* pAl = Alo + bz * strideA + (long)by * 128 * ldA;
    const f16* pBh = Bh_ + bz * strideB + (long)bx * 128 * ldB;
    const f16* pBl = Bl_ ? (Bl_ + bz * strideB + (long)bx * 128 * ldB) : nullptr;

    auto load_chunk = [&](int c) {
        const uint32_t st = sbase + (uint32_t)(c % STAGES) * STAGE_BYTES;
        const int k0 = kbase + (c << 5);
        #pragma unroll
        for (int i = 0; i < 4; i++) {
            int id  = tid + i * 128;       // 0..511
            int row = id >> 2, kc = id & 3;
            uint32_t so = swz(row, kc);
            long gA = (long)row * ldA + k0 + kc * 8;
            long gB = (long)row * ldB + k0 + kc * 8;
            cp16(st +         so, pAh + gA);
            cp16(st +  8192 + so, pAl + gA);
            cp16(st + 16384 + so, pBh + gB);
            if (npass == 3) cp16(st + 24576 + so, pBl + gB);
        }
        CP_COMMIT();
    };

    float acc[4][8][4];
    #pragma unroll
    for (int i = 0; i < 4; i++)
        #pragma unroll
        for (int j = 0; j < 8; j++)
            #pragma unroll
            for (int p = 0; p < 4; p++) acc[i][j][p] = 0.f;

    load_chunk(0);
    if (nchunks > 1) load_chunk(1);

    const int lrow = lane & 15;
    const int lsel = lane >> 4;
    const int arow = wm * 64 + lrow;
    const int brow = wn * 64 + lrow;

    for (int c = 0; c < nchunks; c++) {
        if (c + 1 < nchunks) asm volatile("cp.async.wait_group 1;" ::: "memory");
        else                 asm volatile("cp.async.wait_group 0;" ::: "memory");
        __syncthreads();

        if (c + 2 < nchunks) load_chunk(c + 2);

        const uint32_t st  = sbase + (uint32_t)(c % STAGES) * STAGE_BYTES;
        const uint32_t sAh = st, sAl = st + 8192, sBh = st + 16384, sBl = st + 24576;

        #pragma unroll
        for (int ks = 0; ks < 2; ks++) {
            const int kc = ks * 2 + lsel;
            uint32_t bh[8][2];
            #pragma unroll
            for (int np = 0; np < 4; np++) {
                int r = brow + np * 16;
                uint32_t t4[4];
                ldsm_x4(t4, sBh + swz(r, kc));
                bh[np*2][0] = t4[0]; bh[np*2][1] = t4[2];
                bh[np*2+1][0] = t4[1]; bh[np*2+1][1] = t4[3];
            }
            uint32_t aH[4][4];
            #pragma unroll
            for (int mt = 0; mt < 4; mt++)
                ldsm_x4(aH[mt], sAh + swz(arow + mt * 16, kc));

            // pass 1: aH x bh
            #pragma unroll
            for (int mt = 0; mt < 4; mt++)
                #pragma unroll
                for (int nt = 0; nt < 8; nt++)
                    mma16816(acc[mt][nt], aH[mt], bh[nt]);

            // pass 2 (npass==3 only): aH x bl
            if (npass == 3) {
                uint32_t bl[8][2];
                #pragma unroll
                for (int np = 0; np < 4; np++) {
                    int r = brow + np * 16;
                    uint32_t t4[4];
                    ldsm_x4(t4, sBl + swz(r, kc));
                    bl[np*2][0] = t4[0]; bl[np*2][1] = t4[2];
                    bl[np*2+1][0] = t4[1]; bl[np*2+1][1] = t4[3];
                }
                #pragma unroll
                for (int mt = 0; mt < 4; mt++)
                    #pragma unroll
                    for (int nt = 0; nt < 8; nt++)
                        mma16816(acc[mt][nt], aH[mt], bl[nt]);
            }

            // pass 3: aL x bh (aL streamed)
            uint32_t aL[2][4];
            ldsm_x4(aL[0], sAl + swz(arow, kc));
            #pragma unroll
            for (int mt = 0; mt < 4; mt++) {
                const int cur = mt & 1;
                if (mt < 3)
                    ldsm_x4(aL[cur ^ 1], sAl + swz(arow + (mt + 1) * 16, kc));
                #pragma unroll
                for (int nt = 0; nt < 8; nt++)
                    mma16816(acc[mt][nt], aL[cur], bh[nt]);
            }
        }
    }

    // ---- epilogue: stage fp32 tile in smem, then coalesced global writes ----
    __syncthreads();
    float* buf = (float*)smem;
    {
        const int rq = lane >> 2;
        const int cq = (lane & 3) * 2;
        #pragma unroll
        for (int mt = 0; mt < 4; mt++)
            #pragma unroll
            for (int nt = 0; nt < 8; nt++) {
                int r0 = wm * 64 + mt * 16 + rq;
                int c0 = wn * 64 + nt * 8 + cq;
                *(float2*)&buf[r0 * EPI_LD + c0]       = make_float2(acc[mt][nt][0], acc[mt][nt][1]);
                *(float2*)&buf[(r0 + 8) * EPI_LD + c0] = make_float2(acc[mt][nt][2], acc[mt][nt][3]);
            }
    }
    __syncthreads();

    if (emode == 0) {
        int r = tid;
        long row = (long)by * 128 + r;
        float4* dst = (float4*)(Cf + bz * sC + row * ldc + (long)bx * 128);
        #pragma unroll
        for (int i = 0; i < 32; i++)
            dst[i] = *(float4*)&buf[r * EPI_LD + i * 4];
    } else if (emode == 1) {
        int r = tid;
        long row = (long)by * 128 + r;
        f16* dh = Chi + coff + bz * sC + row * ldc + (long)bx * 128;
        f16* dl = Clo + coff + bz * sC + row * ldc + (long)bx * 128;
        #pragma unroll
        for (int v = 0; v < 16; v++) {
            uint4 uh, ul;
            uint32_t* ph = (uint32_t*)&uh; uint32_t* pl = (uint32_t*)&ul;
            #pragma unroll
            for (int p = 0; p < 4; p++) {
                float f0 = buf[r * EPI_LD + v * 8 + p * 2];
                float f1 = buf[r * EPI_LD + v * 8 + p * 2 + 1];
                f16 h0, l0, h1, l1;
                fsplit(f0, h0, l0); fsplit(f1, h1, l1);
                ph[p] = (uint32_t)*(uint16_t*)&h0 | ((uint32_t)*(uint16_t*)&h1 << 16);
                pl[p] = (uint32_t)*(uint16_t*)&l0 | ((uint32_t)*(uint16_t*)&l1 << 16);
            }
            *(uint4*)(dh + v * 8) = uh;
            *(uint4*)(dl + v * 8) = ul;
        }
    } else {
        // transposed out: Ct[e][s_local], batch derived from global row
        int cc = tid;
        int rowbase = by * 128;
        int b = rowbase / SEQ;
        int sloc = rowbase % SEQ;
        long e = (long)bx * 128 + cc;
        f16* dh = Chi + coff + b * sC + e * ldc + sloc;
        f16* dl = Clo + coff + b * sC + e * ldc + sloc;
        #pragma unroll
        for (int v = 0; v < 16; v++) {
            uint4 uh, ul;
            uint32_t* ph = (uint32_t*)&uh; uint32_t* pl = (uint32_t*)&ul;
            #pragma unroll
            for (int p = 0; p < 4; p++) {
                float f0 = buf[(v * 8 + p * 2)     * EPI_LD + cc];
                float f1 = buf[(v * 8 + p * 2 + 1) * EPI_LD + cc];
                f16 h0, l0, h1, l1;
                fsplit(f0, h0, l0); fsplit(f1, h1, l1);
                ph[p] = (uint32_t)*(uint16_t*)&h0 | ((uint32_t)*(uint16_t*)&h1 << 16);
                pl[p] = (uint32_t)*(uint16_t*)&l0 | ((uint32_t)*(uint16_t*)&l1 << 16);
            }
            *(uint4*)(dh + v * 8) = uh;
            if (wlo) *(uint4*)(dl + v * 8) = ul;
        }
    }
}

// ---------------- fp32 -> f16 hi/lo split ----------------
__device__ __forceinline__ void split4(const float* __restrict__ src,
                                       f16* __restrict__ hi, f16* __restrict__ lo, long i)
{
    float4 v = *(const float4*)(src + i);
    float f[4] = {v.x, v.y, v.z, v.w};
    uint32_t h2[2], l2[2];
    #pragma unroll
    for (int p = 0; p < 2; p++) {
        f16 h0, l0, h1, l1;
        fsplit(f[p*2],   h0, l0);
        fsplit(f[p*2+1], h1, l1);
        h2[p] = (uint32_t)*(uint16_t*)&h0 | ((uint32_t)*(uint16_t*)&h1 << 16);
        l2[p] = (uint32_t)*(uint16_t*)&l0 | ((uint32_t)*(uint16_t*)&l1 << 16);
    }
    *(uint2*)(hi + i) = make_uint2(h2[0], h2[1]);
    *(uint2*)(lo + i) = make_uint2(l2[0], l2[1]);
}

__global__ void __launch_bounds__(256) split_f32(
    const float* __restrict__ src, f16* __restrict__ hi, f16* __restrict__ lo, long n)
{
    long i = ((long)blockIdx.x * 256 + threadIdx.x) * 4;
    if (i >= n) return;
    split4(src, hi, lo, i);
}

// transpose + split for Wq (z=0) and Wk (z=1): out[d][e] = in[e][d]
__global__ void __launch_bounds__(256) tsplit_w(
    const float* __restrict__ w0, const float* __restrict__ w1,
    f16* __restrict__ hi, f16* __restrict__ lo)
{
    const float* src = (blockIdx.z == 0) ? w0 : w1;
    f16* dh = hi + (long)blockIdx.z * NW;
    f16* dl = lo + (long)blockIdx.z * NW;

    __shared__ float t[32][33];
    const int tx = threadIdx.x & 31;
    const int ty = threadIdx.x >> 5;   // 0..7
    int x = blockIdx.x * 32 + tx;
    #pragma unroll
    for (int j = 0; j < 4; j++) {
        int y = blockIdx.y * 32 + ty + j * 8;
        t[ty + j * 8][tx] = src[(long)y * DIM + x];
    }
    __syncthreads();
    int xo = blockIdx.y * 32 + tx;
    #pragma unroll
    for (int j = 0; j < 4; j++) {
        int yo = blockIdx.x * 32 + ty + j * 8;
        float f = t[tx][ty + j * 8];
        f16 h, l;
        fsplit(f, h, l);
        dh[(long)yo * DIM + xo] = h;
        dl[(long)yo * DIM + xo] = l;
    }
}

// reduce 4 fp32 partials -> f16 hi/lo
__global__ void __launch_bounds__(256) reduce4_split(
    const float* __restrict__ part, f16* __restrict__ hi, f16* __restrict__ lo)
{
    long i = ((long)blockIdx.x * 256 + threadIdx.x) * 4;
    if (i >= NW) return;
    float4 s = *(const float4*)(part + i);
    #pragma unroll
    for (int j = 1; j < 4; j++) {
        float4 v = *(const float4*)(part + j * NW + i);
        s.x += v.x; s.y += v.y; s.z += v.z; s.w += v.w;
    }
    float f[4] = {s.x, s.y, s.z, s.w};
    uint32_t h2[2], l2[2];
    #pragma unroll
    for (int p = 0; p < 2; p++) {
        f16 h0, l0, h1, l1;
        fsplit(f[p*2],   h0, l0);
        fsplit(f[p*2+1], h1, l1);
        h2[p] = (uint32_t)*(uint16_t*)&h0 | ((uint32_t)*(uint16_t*)&h1 << 16);
        l2[p] = (uint32_t)*(uint16_t*)&l0 | ((uint32_t)*(uint16_t*)&l1 << 16);
    }
    *(uint2*)(hi + i) = make_uint2(h2[0], h2[1]);
    *(uint2*)(lo + i) = make_uint2(l2[0], l2[1]);
}

// ---------------- causal softmax: fp32 scores -> f16 hi/lo probs ----------------
__global__ void __launch_bounds__(256) softmax_causal(
    const float* __restrict__ Sc, f16* __restrict__ Ph, f16* __restrict__ Pl)
{
    const long r = blockIdx.x;
    const int  q = (int)(r & (SEQ - 1));
    const float* row = Sc + r * SEQ;
    f16* ph = Ph + r * SEQ;
    f16* pl = Pl + r * SEQ;

    __shared__ float bufr[SEQ];
    __shared__ float red[256];

    const int tid = threadIdx.x;
    const int len = q + 1;
    const float scale = 0.03125f;  // 1/sqrt(1024)

    float m = -1e30f;
    for (int k = tid; k < len; k += 256) {
        float v = row[k] * scale;
        bufr[k] = v;
        m = fmaxf(m, v);
    }
    red[tid] = m;
    __syncthreads();
    #pragma unroll
    for (int s = 128; s > 0; s >>= 1) {
        if (tid < s) red[tid] = fmaxf(red[tid], red[tid + s]);
        __syncthreads();
    }
    m = red[0];
    __syncthreads();

    float sum = 0.f;
    for (int k = tid; k < len; k += 256) {
        float e = __expf(bufr[k] - m);
        bufr[k] = e;
        sum += e;
    }
    red[tid] = sum;
    __syncthreads();
    #pragma unroll
    for (int s = 128; s > 0; s >>= 1) {
        if (tid < s) red[tid] += red[tid + s];
        __syncthreads();
    }
    const float inv = 1.0f / red[0];
    __syncthreads();

    for (int k = tid; k < len; k += 256) {
        float p = bufr[k] * inv;
        f16 h, l;
        fsplit(p, h, l);
        ph[k] = h; pl[k] = l;
    }
    const f16 z = __float2half(0.f);
    for (int k = len + tid; k < SEQ; k += 256) { ph[k] = z; pl[k] = z; }
}

// ---------------------------------------------------------------------------
extern "C" void kernel_launch(void* const* d_in, const int* in_sizes, int n_in,
                              void* d_out, int out_size)
{
    const float* X  = (const float*)d_in[0];
    const float* Wq = (const float*)d_in[1];
    const float* Wk = (const float*)d_in[2];
    const float* Wv = (const float*)d_in[3];
    float* out = (float*)d_out;

    f16 *xh, *xl, *wh, *wl, *mh, *ml, *oh, *ol, *ph, *pl;
    float *mpart, *sc;
    cudaGetSymbolAddress((void**)&xh, g_xh);  cudaGetSymbolAddress((void**)&xl, g_xl);
    cudaGetSymbolAddress((void**)&wh, g_wh);  cudaGetSymbolAddress((void**)&wl, g_wl);
    cudaGetSymbolAddress((void**)&mh, g_mh);  cudaGetSymbolAddress((void**)&ml, g_ml);
    cudaGetSymbolAddress((void**)&mpart, g_mpart);
    cudaGetSymbolAddress((void**)&oh, g_oh);  cudaGetSymbolAddress((void**)&ol, g_ol);
    cudaGetSymbolAddress((void**)&sc, g_sc);
    cudaGetSymbolAddress((void**)&ph, g_ph);  cudaGetSymbolAddress((void**)&pl, g_pl);

    cudaFuncSetAttribute(gemm_f16x, cudaFuncAttributeMaxDynamicSharedMemorySize, SMEM_TOTAL);

    const long nX = NX, nW = NW;
    const int M = BATCH * SEQ;  // 8192

    dim3 thr256(256);
    dim3 thr128(128);

    // splits: X (hi/lo), Wq^T -> wh[0], Wk^T -> wh[1], Wv -> wh[2]
    split_f32<<<(unsigned)(nX / 1024), thr256>>>(X, xh, xl, nX);
    dim3 gT(DIM / 32, DIM / 32, 2);
    tsplit_w<<<gT, thr256>>>(Wq, Wk, wh, wl);
    split_f32<<<(unsigned)(nW / 1024), thr256>>>(Wv, wh + 2 * nW, wl + 2 * nW, nW);

    // M' = Wk^T-rows x Wq^T-rows (NT), split-K over z=4, fp32 partials; 3-pass
    dim3 gM(DIM / 128, DIM / 128, 4);
    gemm_f16x<<<gM, thr128, SMEM_TOTAL>>>(wh + nW, wl + nW, wh, wl,
        nullptr, nullptr,
        mpart, nullptr, nullptr, DIM / 4, DIM, DIM, DIM,
        0, 0, nW, 0, 0, 0, 1, 3);
    reduce4_split<<<(unsigned)(nW / 1024), thr256>>>(mpart, mh, ml);

    // fused: z=0 -> T = X @ M'^T (mode-1 out oh), z=1 -> V^T (mode-2, hi only)
    dim3 gVT(DIM / 128, M / 128, 2);
    gemm_f16x<<<gVT, thr128, SMEM_TOTAL>>>(xh, xl, mh, ml,
        wh + 2 * nW, wl + 2 * nW,
        nullptr, oh, ol, DIM, DIM, DIM, DIM,
        0, 0, 0, 0, 0, 4, 0, 2);

    // scores = T @ X^T per batch (causal tile skip), fp32 out; 2-pass
    dim3 gScore(SEQ / 128, SEQ / 128, BATCH);
    gemm_f16x<<<gScore, thr128, SMEM_TOTAL>>>(oh, ol, xh, xl,
        nullptr, nullptr,
        sc, nullptr, nullptr, DIM, DIM, DIM, SEQ,
        (long)SEQ * DIM, (long)SEQ * DIM, (long)SEQ * SEQ, 1, 0, 0, 0, 2);

    // softmax -> f16 hi/lo probs
    softmax_causal<<<BATCH * SEQ, thr256>>>(sc, ph, pl);

    // out = P @ V^T per batch (causal k clamp), fp32 out; 2-pass (V_lo dropped)
    dim3 gAV(DIM / 128, SEQ / 128, BATCH);
    gemm_f16x<<<gAV, thr128, SMEM_TOTAL>>>(ph, pl, oh + 2 * nX, nullptr,
        nullptr, nullptr,
        out, nullptr, nullptr, SEQ, SEQ, SEQ, DIM,
        (long)SEQ * SEQ, (long)DIM * SEQ, (long)SEQ * DIM, 0, 1, 0, 0, 2);
}

// round 12
// speedup vs baseline: 1.9558x; 1.1754x over previous
#include <cuda_runtime.h>
#include <cuda_fp16.h>
#include <cstdint>

#define BATCH 4
#define SEQ   2048
#define DIM   1024

typedef __half f16;

static const long NX = (long)BATCH * SEQ * DIM;   // 8388608
static const long NW = (long)DIM * DIM;           // 1048576
#define DNX ((long)BATCH * SEQ * DIM)

// ---------------- scratch (device globals; allocation-free) ----------------
__device__ __align__(128) f16   g_xh[(long)BATCH*SEQ*DIM];
__device__ __align__(128) f16   g_xl[(long)BATCH*SEQ*DIM];
// [0]=Wq^T, [1]=Wk^T, [2]=Wv (row-major as given)
__device__ __align__(128) f16   g_wh[3][(long)DIM*DIM];
__device__ __align__(128) f16   g_wl[3][(long)DIM*DIM];
// M' split-K fp32 partials and final f16 hi/lo
__device__ __align__(128) float g_mpart[4*(long)DIM*DIM];
__device__ __align__(128) f16   g_mh[(long)DIM*DIM];
__device__ __align__(128) f16   g_ml[(long)DIM*DIM];
// stacked outputs: [0]=T (hi only), [2]=V^T (hi only, [b][e][s])
__device__ __align__(128) f16   g_oh[3*(long)BATCH*SEQ*DIM];
__device__ __align__(128) f16   g_ol[3*(long)BATCH*SEQ*DIM];
__device__ __align__(128) float g_sc [(long)BATCH*SEQ*SEQ];
__device__ __align__(128) f16   g_ph [(long)BATCH*SEQ*SEQ];
__device__ __align__(128) f16   g_pl [(long)BATCH*SEQ*SEQ];

// ---------------- PTX helpers (arch-generic; NO tcgen05) ----------------
__device__ __forceinline__ uint32_t smem_u32(const void* p) {
    uint32_t a;
    asm("{ .reg .u64 t; cvta.to.shared.u64 t, %1; cvt.u32.u64 %0, t; }" : "=r"(a) : "l"(p));
    return a;
}
__device__ __forceinline__ void cp16(uint32_t saddr, const void* g) {
    asm volatile("cp.async.cg.shared.global [%0], [%1], 16;" :: "r"(saddr), "l"(g) : "memory");
}
#define CP_COMMIT() asm volatile("cp.async.commit_group;" ::: "memory")

__device__ __forceinline__ void ldsm_x4(uint32_t* r, uint32_t addr) {
    asm volatile("ldmatrix.sync.aligned.m8n8.x4.shared.b16 {%0,%1,%2,%3}, [%4];"
        : "=r"(r[0]), "=r"(r[1]), "=r"(r[2]), "=r"(r[3]) : "r"(addr));
}
__device__ __forceinline__ void mma16816(float* c, const uint32_t* a, const uint32_t* b) {
    asm volatile("mma.sync.aligned.m16n8k16.row.col.f32.f16.f16.f32 "
        "{%0,%1,%2,%3}, {%4,%5,%6,%7}, {%8,%9}, {%0,%1,%2,%3};"
        : "+f"(c[0]), "+f"(c[1]), "+f"(c[2]), "+f"(c[3])
        : "r"(a[0]), "r"(a[1]), "r"(a[2]), "r"(a[3]), "r"(b[0]), "r"(b[1]));
}

__device__ __forceinline__ uint32_t swz(int row, int kc) {
    return (uint32_t)(row * 64 + ((kc ^ ((row >> 1) & 3)) << 4));
}

// fp16 hi/lo split of one float
__device__ __forceinline__ void fsplit(float f, f16& h, f16& l) {
    h = __float2half_rn(f);
    l = __float2half_rn(f - __half2float(h));
}

// ---------------- SMEM layout ----------------
#define STAGES 3
#define STAGE_BYTES 32768
#define EPI_LD 132
#define SMEM_TOTAL (STAGES * STAGE_BYTES)

// =====================================================================
// fp16 hi/lo NT GEMM via mma.sync: 128x128 CTA tile, 128 threads,
// 4 warps x (64x64) warp tile.
// npass=3: hh + hl + lh ; npass=2: hh + lh ; npass=1: hh only
// mode 0: fp32 C;  mode 1: f16 hi(/lo) C;  mode 2: f16 hi(/lo) C transposed
// mode 4: fused — bz=0: B pair 1, mode-1 epilogue hi-only, 1-pass (T);
//                 bz=1: B pair 2, mode-2 epilogue hi-only, 2-pass (V^T)
// ksplit: when 1, this block computes K-window [bz*K, (bz+1)*K)
// =====================================================================
__global__ void __launch_bounds__(128, 2) gemm_f16x(
    const f16* __restrict__ Ahi, const f16* __restrict__ Alo,
    const f16* __restrict__ Bhi, const f16* __restrict__ Blo,
    const f16* __restrict__ B2hi, const f16* __restrict__ B2lo,
    float* __restrict__ Cf, f16* __restrict__ Chi, f16* __restrict__ Clo,
    int K, int ldA, int ldB, int ldC,
    long strideA, long strideB, long strideC,
    int causal, int kclamp, int mode, int ksplit, int npass)
{
    const int bx = blockIdx.x, bz = blockIdx.z;
    // heavy-tile-first dispatch when k-clamped (big kmax scheduled in wave 1)
    const int by = kclamp ? (gridDim.y - 1 - blockIdx.y) : blockIdx.y;
    if (causal && bx > by) return;

    // resolve fused submode
    const f16* Bh_ = Bhi;
    const f16* Bl_ = Blo;
    int  emode = mode, ldc = ldC, np = npass;
    long sC = strideC, coff = 0;
    int  wlo = 1;
    if (mode == 4) {
        if (bz == 0) { emode = 1; ldc = DIM; sC = 0; wlo = 0; np = 1; }
        else {
            Bh_ = B2hi; Bl_ = B2lo;
            emode = 2; ldc = SEQ; sC = (long)DIM * SEQ;
            coff = 2 * DNX; wlo = 0; np = 2;
        }
    }

    extern __shared__ char smem[];
    const uint32_t sbase = smem_u32(smem);
    const int tid  = threadIdx.x;        // 0..127
    const int lane = tid & 31;
    const int wid  = tid >> 5;           // 0..3
    const int wm   = wid >> 1;           // 0..1 : 64 rows
    const int wn   = wid & 1;            // 0..1 : 64 cols

    const int kbase   = ksplit ? bz * K : 0;
    const int kmax    = kclamp ? min(K, (by + 1) * 128) : K;
    const int nchunks = kmax >> 5;       // BK = 32

    const f16* pAh = Ahi + bz * strideA + (long)by * 128 * ldA;
    const f16* pAl = Alo ? (Alo + bz * strideA + (long)by * 128 * ldA) : nullptr;
    const f16* pBh = Bh_ + bz * strideB + (long)bx * 128 * ldB;
    const f16* pBl = Bl_ ? (Bl_ + bz * strideB + (long)bx * 128 * ldB) : nullptr;

    auto load_chunk = [&](int c) {
        const uint32_t st = sbase + (uint32_t)(c % STAGES) * STAGE_BYTES;
        const int k0 = kbase + (c << 5);
        #pragma unroll
        for (int i = 0; i < 4; i++) {
            int id  = tid + i * 128;       // 0..511
            int row = id >> 2, kc = id & 3;
            uint32_t so = swz(row, kc);
            long gA = (long)row * ldA + k0 + kc * 8;
            long gB = (long)row * ldB + k0 + kc * 8;
            cp16(st +         so, pAh + gA);
            if (np >= 2) cp16(st +  8192 + so, pAl + gA);
            cp16(st + 16384 + so, pBh + gB);
            if (np == 3)  cp16(st + 24576 + so, pBl + gB);
        }
        CP_COMMIT();
    };

    float acc[4][8][4];
    #pragma unroll
    for (int i = 0; i < 4; i++)
        #pragma unroll
        for (int j = 0; j < 8; j++)
            #pragma unroll
            for (int p = 0; p < 4; p++) acc[i][j][p] = 0.f;

    load_chunk(0);
    if (nchunks > 1) load_chunk(1);

    const int lrow = lane & 15;
    const int lsel = lane >> 4;
    const int arow = wm * 64 + lrow;
    const int brow = wn * 64 + lrow;

    for (int c = 0; c < nchunks; c++) {
        if (c + 1 < nchunks) asm volatile("cp.async.wait_group 1;" ::: "memory");
        else                 asm volatile("cp.async.wait_group 0;" ::: "memory");
        __syncthreads();

        if (c + 2 < nchunks) load_chunk(c + 2);

        const uint32_t st  = sbase + (uint32_t)(c % STAGES) * STAGE_BYTES;
        const uint32_t sAh = st, sAl = st + 8192, sBh = st + 16384, sBl = st + 24576;

        #pragma unroll
        for (int ks = 0; ks < 2; ks++) {
            const int kc = ks * 2 + lsel;
            uint32_t bh[8][2];
            #pragma unroll
            for (int nq = 0; nq < 4; nq++) {
                int r = brow + nq * 16;
                uint32_t t4[4];
                ldsm_x4(t4, sBh + swz(r, kc));
                bh[nq*2][0] = t4[0]; bh[nq*2][1] = t4[2];
                bh[nq*2+1][0] = t4[1]; bh[nq*2+1][1] = t4[3];
            }
            uint32_t aH[4][4];
            #pragma unroll
            for (int mt = 0; mt < 4; mt++)
                ldsm_x4(aH[mt], sAh + swz(arow + mt * 16, kc));

            // pass 1: aH x bh
            #pragma unroll
            for (int mt = 0; mt < 4; mt++)
                #pragma unroll
                for (int nt = 0; nt < 8; nt++)
                    mma16816(acc[mt][nt], aH[mt], bh[nt]);

            // pass 2 (npass==3 only): aH x bl
            if (np == 3) {
                uint32_t bl[8][2];
                #pragma unroll
                for (int nq = 0; nq < 4; nq++) {
                    int r = brow + nq * 16;
                    uint32_t t4[4];
                    ldsm_x4(t4, sBl + swz(r, kc));
                    bl[nq*2][0] = t4[0]; bl[nq*2][1] = t4[2];
                    bl[nq*2+1][0] = t4[1]; bl[nq*2+1][1] = t4[3];
                }
                #pragma unroll
                for (int mt = 0; mt < 4; mt++)
                    #pragma unroll
                    for (int nt = 0; nt < 8; nt++)
                        mma16816(acc[mt][nt], aH[mt], bl[nt]);
            }

            // pass 3 (npass>=2): aL x bh (aL streamed)
            if (np >= 2) {
                uint32_t aL[2][4];
                ldsm_x4(aL[0], sAl + swz(arow, kc));
                #pragma unroll
                for (int mt = 0; mt < 4; mt++) {
                    const int cur = mt & 1;
                    if (mt < 3)
                        ldsm_x4(aL[cur ^ 1], sAl + swz(arow + (mt + 1) * 16, kc));
                    #pragma unroll
                    for (int nt = 0; nt < 8; nt++)
                        mma16816(acc[mt][nt], aL[cur], bh[nt]);
                }
            }
        }
    }

    // ---- epilogue: stage fp32 tile in smem, then coalesced global writes ----
    __syncthreads();
    float* buf = (float*)smem;
    {
        const int rq = lane >> 2;
        const int cq = (lane & 3) * 2;
        #pragma unroll
        for (int mt = 0; mt < 4; mt++)
            #pragma unroll
            for (int nt = 0; nt < 8; nt++) {
                int r0 = wm * 64 + mt * 16 + rq;
                int c0 = wn * 64 + nt * 8 + cq;
                *(float2*)&buf[r0 * EPI_LD + c0]       = make_float2(acc[mt][nt][0], acc[mt][nt][1]);
                *(float2*)&buf[(r0 + 8) * EPI_LD + c0] = make_float2(acc[mt][nt][2], acc[mt][nt][3]);
            }
    }
    __syncthreads();

    if (emode == 0) {
        int r = tid;
        long row = (long)by * 128 + r;
        float4* dst = (float4*)(Cf + bz * sC + row * ldc + (long)bx * 128);
        #pragma unroll
        for (int i = 0; i < 32; i++)
            dst[i] = *(float4*)&buf[r * EPI_LD + i * 4];
    } else if (emode == 1) {
        int r = tid;
        long row = (long)by * 128 + r;
        f16* dh = Chi + coff + bz * sC + row * ldc + (long)bx * 128;
        f16* dl = Clo + coff + bz * sC + row * ldc + (long)bx * 128;
        #pragma unroll
        for (int v = 0; v < 16; v++) {
            uint4 uh, ul;
            uint32_t* ph = (uint32_t*)&uh; uint32_t* pl = (uint32_t*)&ul;
            #pragma unroll
            for (int p = 0; p < 4; p++) {
                float f0 = buf[r * EPI_LD + v * 8 + p * 2];
                float f1 = buf[r * EPI_LD + v * 8 + p * 2 + 1];
                f16 h0, l0, h1, l1;
                fsplit(f0, h0, l0); fsplit(f1, h1, l1);
                ph[p] = (uint32_t)*(uint16_t*)&h0 | ((uint32_t)*(uint16_t*)&h1 << 16);
                pl[p] = (uint32_t)*(uint16_t*)&l0 | ((uint32_t)*(uint16_t*)&l1 << 16);
            }
            *(uint4*)(dh + v * 8) = uh;
            if (wlo) *(uint4*)(dl + v * 8) = ul;
        }
    } else {
        // transposed out: Ct[e][s_local], batch derived from global row
        int cc = tid;
        int rowbase = by * 128;
        int b = rowbase / SEQ;
        int sloc = rowbase % SEQ;
        long e = (long)bx * 128 + cc;
        f16* dh = Chi + coff + b * sC + e * ldc + sloc;
        f16* dl = Clo + coff + b * sC + e * ldc + sloc;
        #pragma unroll
        for (int v = 0; v < 16; v++) {
            uint4 uh, ul;
            uint32_t* ph = (uint32_t*)&uh; uint32_t* pl = (uint32_t*)&ul;
            #pragma unroll
            for (int p = 0; p < 4; p++) {
                float f0 = buf[(v * 8 + p * 2)     * EPI_LD + cc];
                float f1 = buf[(v * 8 + p * 2 + 1) * EPI_LD + cc];
                f16 h0, l0, h1, l1;
                fsplit(f0, h0, l0); fsplit(f1, h1, l1);
                ph[p] = (uint32_t)*(uint16_t*)&h0 | ((uint32_t)*(uint16_t*)&h1 << 16);
                pl[p] = (uint32_t)*(uint16_t*)&l0 | ((uint32_t)*(uint16_t*)&l1 << 16);
            }
            *(uint4*)(dh + v * 8) = uh;
            if (wlo) *(uint4*)(dl + v * 8) = ul;
        }
    }
}

// ---------------- fp32 -> f16 hi/lo split ----------------
__device__ __forceinline__ void split4(const float* __restrict__ src,
                                       f16* __restrict__ hi, f16* __restrict__ lo, long i)
{
    float4 v = *(const float4*)(src + i);
    float f[4] = {v.x, v.y, v.z, v.w};
    uint32_t h2[2], l2[2];
    #pragma unroll
    for (int p = 0; p < 2; p++) {
        f16 h0, l0, h1, l1;
        fsplit(f[p*2],   h0, l0);
        fsplit(f[p*2+1], h1, l1);
        h2[p] = (uint32_t)*(uint16_t*)&h0 | ((uint32_t)*(uint16_t*)&h1 << 16);
        l2[p] = (uint32_t)*(uint16_t*)&l0 | ((uint32_t)*(uint16_t*)&l1 << 16);
    }
    *(uint2*)(hi + i) = make_uint2(h2[0], h2[1]);
    *(uint2*)(lo + i) = make_uint2(l2[0], l2[1]);
}

__global__ void __launch_bounds__(256) split_f32(
    const float* __restrict__ src, f16* __restrict__ hi, f16* __restrict__ lo, long n)
{
    long i = ((long)blockIdx.x * 256 + threadIdx.x) * 4;
    if (i >= n) return;
    split4(src, hi, lo, i);
}

// transpose + split for Wq (z=0) and Wk (z=1): out[d][e] = in[e][d]
__global__ void __launch_bounds__(256) tsplit_w(
    const float* __restrict__ w0, const float* __restrict__ w1,
    f16* __restrict__ hi, f16* __restrict__ lo)
{
    const float* src = (blockIdx.z == 0) ? w0 : w1;
    f16* dh = hi + (long)blockIdx.z * NW;
    f16* dl = lo + (long)blockIdx.z * NW;

    __shared__ float t[32][33];
    const int tx = threadIdx.x & 31;
    const int ty = threadIdx.x >> 5;   // 0..7
    int x = blockIdx.x * 32 + tx;
    #pragma unroll
    for (int j = 0; j < 4; j++) {
        int y = blockIdx.y * 32 + ty + j * 8;
        t[ty + j * 8][tx] = src[(long)y * DIM + x];
    }
    __syncthreads();
    int xo = blockIdx.y * 32 + tx;
    #pragma unroll
    for (int j = 0; j < 4; j++) {
        int yo = blockIdx.x * 32 + ty + j * 8;
        float f = t[tx][ty + j * 8];
        f16 h, l;
        fsplit(f, h, l);
        dh[(long)yo * DIM + xo] = h;
        dl[(long)yo * DIM + xo] = l;
    }
}

// reduce 4 fp32 partials -> f16 hi/lo
__global__ void __launch_bounds__(256) reduce4_split(
    const float* __restrict__ part, f16* __restrict__ hi, f16* __restrict__ lo)
{
    long i = ((long)blockIdx.x * 256 + threadIdx.x) * 4;
    if (i >= NW) return;
    float4 s = *(const float4*)(part + i);
    #pragma unroll
    for (int j = 1; j < 4; j++) {
        float4 v = *(const float4*)(part + j * NW + i);
        s.x += v.x; s.y += v.y; s.z += v.z; s.w += v.w;
    }
    float f[4] = {s.x, s.y, s.z, s.w};
    uint32_t h2[2], l2[2];
    #pragma unroll
    for (int p = 0; p < 2; p++) {
        f16 h0, l0, h1, l1;
        fsplit(f[p*2],   h0, l0);
        fsplit(f[p*2+1], h1, l1);
        h2[p] = (uint32_t)*(uint16_t*)&h0 | ((uint32_t)*(uint16_t*)&h1 << 16);
        l2[p] = (uint32_t)*(uint16_t*)&l0 | ((uint32_t)*(uint16_t*)&l1 << 16);
    }
    *(uint2*)(hi + i) = make_uint2(h2[0], h2[1]);
    *(uint2*)(lo + i) = make_uint2(l2[0], l2[1]);
}

// ---------------- causal softmax: fp32 scores -> f16 hi/lo probs ----------------
__global__ void __launch_bounds__(256) softmax_causal(
    const float* __restrict__ Sc, f16* __restrict__ Ph, f16* __restrict__ Pl)
{
    const long r = blockIdx.x;
    const int  q = (int)(r & (SEQ - 1));
    const float* row = Sc + r * SEQ;
    f16* ph = Ph + r * SEQ;
    f16* pl = Pl + r * SEQ;

    __shared__ float bufr[SEQ];
    __shared__ float red[256];

    const int tid = threadIdx.x;
    const int len = q + 1;
    const float scale = 0.03125f;  // 1/sqrt(1024)

    float m = -1e30f;
    for (int k = tid; k < len; k += 256) {
        float v = row[k] * scale;
        bufr[k] = v;
        m = fmaxf(m, v);
    }
    red[tid] = m;
    __syncthreads();
    #pragma unroll
    for (int s = 128; s > 0; s >>= 1) {
        if (tid < s) red[tid] = fmaxf(red[tid], red[tid + s]);
        __syncthreads();
    }
    m = red[0];
    __syncthreads();

    float sum = 0.f;
    for (int k = tid; k < len; k += 256) {
        float e = __expf(bufr[k] - m);
        bufr[k] = e;
        sum += e;
    }
    red[tid] = sum;
    __syncthreads();
    #pragma unroll
    for (int s = 128; s > 0; s >>= 1) {
        if (tid < s) red[tid] += red[tid + s];
        __syncthreads();
    }
    const float inv = 1.0f / red[0];
    __syncthreads();

    for (int k = tid; k < len; k += 256) {
        float p = bufr[k] * inv;
        f16 h, l;
        fsplit(p, h, l);
        ph[k] = h; pl[k] = l;
    }
    const f16 z = __float2half(0.f);
    for (int k = len + tid; k < SEQ; k += 256) { ph[k] = z; pl[k] = z; }
}

// ---------------------------------------------------------------------------
extern "C" void kernel_launch(void* const* d_in, const int* in_sizes, int n_in,
                              void* d_out, int out_size)
{
    const float* X  = (const float*)d_in[0];
    const float* Wq = (const float*)d_in[1];
    const float* Wk = (const float*)d_in[2];
    const float* Wv = (const float*)d_in[3];
    float* out = (float*)d_out;

    f16 *xh, *xl, *wh, *wl, *mh, *ml, *oh, *ol, *ph, *pl;
    float *mpart, *sc;
    cudaGetSymbolAddress((void**)&xh, g_xh);  cudaGetSymbolAddress((void**)&xl, g_xl);
    cudaGetSymbolAddress((void**)&wh, g_wh);  cudaGetSymbolAddress((void**)&wl, g_wl);
    cudaGetSymbolAddress((void**)&mh, g_mh);  cudaGetSymbolAddress((void**)&ml, g_ml);
    cudaGetSymbolAddress((void**)&mpart, g_mpart);
    cudaGetSymbolAddress((void**)&oh, g_oh);  cudaGetSymbolAddress((void**)&ol, g_ol);
    cudaGetSymbolAddress((void**)&sc, g_sc);
    cudaGetSymbolAddress((void**)&ph, g_ph);  cudaGetSymbolAddress((void**)&pl, g_pl);

    cudaFuncSetAttribute(gemm_f16x, cudaFuncAttributeMaxDynamicSharedMemorySize, SMEM_TOTAL);

    const long nX = NX, nW = NW;
    const int M = BATCH * SEQ;  // 8192

    dim3 thr256(256);
    dim3 thr128(128);

    // splits: X (hi/lo), Wq^T -> wh[0], Wk^T -> wh[1], Wv -> wh[2]
    split_f32<<<(unsigned)(nX / 1024), thr256>>>(X, xh, xl, nX);
    dim3 gT(DIM / 32, DIM / 32, 2);
    tsplit_w<<<gT, thr256>>>(Wq, Wk, wh, wl);
    split_f32<<<(unsigned)(nW / 1024), thr256>>>(Wv, wh + 2 * nW, wl + 2 * nW, nW);

    // M' = Wk^T-rows x Wq^T-rows (NT), split-K over z=4, fp32 partials; 3-pass
    dim3 gM(DIM / 128, DIM / 128, 4);
    gemm_f16x<<<gM, thr128, SMEM_TOTAL>>>(wh + nW, wl + nW, wh, wl,
        nullptr, nullptr,
        mpart, nullptr, nullptr, DIM / 4, DIM, DIM, DIM,
        0, 0, nW, 0, 0, 0, 1, 3);
    reduce4_split<<<(unsigned)(nW / 1024), thr256>>>(mpart, mh, ml);

    // fused: z=0 -> T = X_hi @ M'_hi^T (1-pass, hi-only out), z=1 -> V^T (2-pass, hi-only)
    dim3 gVT(DIM / 128, M / 128, 2);
    gemm_f16x<<<gVT, thr128, SMEM_TOTAL>>>(xh, xl, mh, ml,
        wh + 2 * nW, wl + 2 * nW,
        nullptr, oh, ol, DIM, DIM, DIM, DIM,
        0, 0, 0, 0, 0, 4, 0, 2);

    // scores = T_hi @ X_hi^T per batch (causal tile skip), fp32 out; 1-pass
    dim3 gScore(SEQ / 128, SEQ / 128, BATCH);
    gemm_f16x<<<gScore, thr128, SMEM_TOTAL>>>(oh, nullptr, xh, nullptr,
        nullptr, nullptr,
        sc, nullptr, nullptr, DIM, DIM, DIM, SEQ,
        (long)SEQ * DIM, (long)SEQ * DIM, (long)SEQ * SEQ, 1, 0, 0, 0, 1);

    // softmax -> f16 hi/lo probs
    softmax_causal<<<BATCH * SEQ, thr256>>>(sc, ph, pl);

    // out = P @ V^T per batch (causal k clamp, heavy-first), fp32 out; 2-pass
    dim3 gAV(DIM / 128, SEQ / 128, BATCH);
    gemm_f16x<<<gAV, thr128, SMEM_TOTAL>>>(ph, pl, oh + 2 * nX, nullptr,
        nullptr, nullptr,
        out, nullptr, nullptr, SEQ, SEQ, SEQ, DIM,
        (long)SEQ * SEQ, (long)DIM * SEQ, (long)SEQ * DIM, 0, 1, 0, 0, 2);
}

// round 13
// speedup vs baseline: 2.3225x; 1.1875x over previous
#include <cuda_runtime.h>
#include <cuda_fp16.h>
#include <cstdint>

#define BATCH 4
#define SEQ   2048
#define DIM   1024

typedef __half f16;

static const long NX = (long)BATCH * SEQ * DIM;   // 8388608
static const long NW = (long)DIM * DIM;           // 1048576
#define DNX ((long)BATCH * SEQ * DIM)

// ---------------- scratch (device globals; allocation-free) ----------------
__device__ __align__(128) f16   g_xh[(long)BATCH*SEQ*DIM];
__device__ __align__(128) f16   g_xl[(long)BATCH*SEQ*DIM];
// [0]=Wq^T, [1]=Wk^T, [2]=Wv (hi only for Wv)
__device__ __align__(128) f16   g_wh[3][(long)DIM*DIM];
__device__ __align__(128) f16   g_wl[2][(long)DIM*DIM];
// M' split-K fp32 partials and final f16 hi
__device__ __align__(128) float g_mpart[4*(long)DIM*DIM];
__device__ __align__(128) f16   g_mh[(long)DIM*DIM];
// stacked outputs: [0]=T (hi), [1]=V^T (hi, [b][e][s])
__device__ __align__(128) f16   g_oh[2*(long)BATCH*SEQ*DIM];
// logits then probs (in-place softmax)
__device__ __align__(128) f16   g_ph[(long)BATCH*SEQ*SEQ];

// ---------------- PTX helpers (arch-generic; NO tcgen05) ----------------
__device__ __forceinline__ uint32_t smem_u32(const void* p) {
    uint32_t a;
    asm("{ .reg .u64 t; cvta.to.shared.u64 t, %1; cvt.u32.u64 %0, t; }" : "=r"(a) : "l"(p));
    return a;
}
__device__ __forceinline__ void cp16(uint32_t saddr, const void* g) {
    asm volatile("cp.async.cg.shared.global [%0], [%1], 16;" :: "r"(saddr), "l"(g) : "memory");
}
#define CP_COMMIT() asm volatile("cp.async.commit_group;" ::: "memory")

__device__ __forceinline__ void ldsm_x4(uint32_t* r, uint32_t addr) {
    asm volatile("ldmatrix.sync.aligned.m8n8.x4.shared.b16 {%0,%1,%2,%3}, [%4];"
        : "=r"(r[0]), "=r"(r[1]), "=r"(r[2]), "=r"(r[3]) : "r"(addr));
}
__device__ __forceinline__ void mma16816(float* c, const uint32_t* a, const uint32_t* b) {
    asm volatile("mma.sync.aligned.m16n8k16.row.col.f32.f16.f16.f32 "
        "{%0,%1,%2,%3}, {%4,%5,%6,%7}, {%8,%9}, {%0,%1,%2,%3};"
        : "+f"(c[0]), "+f"(c[1]), "+f"(c[2]), "+f"(c[3])
        : "r"(a[0]), "r"(a[1]), "r"(a[2]), "r"(a[3]), "r"(b[0]), "r"(b[1]));
}

__device__ __forceinline__ uint32_t swz(int row, int kc) {
    return (uint32_t)(row * 64 + ((kc ^ ((row >> 1) & 3)) << 4));
}

__device__ __forceinline__ void fsplit(float f, f16& h, f16& l) {
    h = __float2half_rn(f);
    l = __float2half_rn(f - __half2float(h));
}

// ---------------- SMEM layout ----------------
#define STAGES 3
#define STAGE_BYTES 32768
#define EPI_LD 132
#define SMEM_TOTAL (STAGES * STAGE_BYTES)

// =====================================================================
// fp16 hi/lo NT GEMM via mma.sync: 128x128 CTA tile, 128 threads,
// 4 warps x (64x64) warp tile.
// npass=3: hh + hl + lh ; npass=2: hh + lh ; npass=1: hh only
// mode 0: fp32 C
// mode 1: f16 C (hi; lo iff Clo != nullptr)
// mode 2: f16 C transposed (hi; lo iff Clo)
// mode 5: f16 C, scaled by 1/32, hi only  (scores -> logits)
// mode 6: fused (operands from device globals):
//         bz==0   -> V^T = X @ Wv^T (2-pass, mode-2 hi into g_oh+DNX)
//         bz=1..4 -> M' split-K slice bz-1 (3-pass, fp32 into g_mpart)
// =====================================================================
__global__ void __launch_bounds__(128, 2) gemm_f16x(
    const f16* __restrict__ Ahi, const f16* __restrict__ Alo,
    const f16* __restrict__ Bhi, const f16* __restrict__ Blo,
    float* __restrict__ Cf, f16* __restrict__ Chi, f16* __restrict__ Clo,
    int K, int ldA, int ldB, int ldC,
    long strideA, long strideB, long strideC,
    int causal, int kclamp, int mode, int npass)
{
    const int bx = blockIdx.x, bz = blockIdx.z;
    // heavy-tile-first dispatch when k-clamped
    const int by = kclamp ? ((int)gridDim.y - 1 - (int)blockIdx.y) : (int)blockIdx.y;
    if (causal && bx > by) return;

    // ---- resolve operands / submode ----
    const f16 *Ah = Ahi, *Al = Alo, *Bh = Bhi, *Bl = Blo;
    float* cf = Cf; f16 *chi = Chi, *clo = Clo;
    int emode = mode, ldc = ldC, np = npass, lda = ldA, ldb = ldB;
    long sA = strideA, sB = strideB, sC = strideC;
    int kk = K, kbase = 0, zi = bz;

    if (mode == 6) {
        if (bz == 0) {
            // V^T projection
            Ah = g_xh; Al = g_xl; Bh = g_wh[2]; Bl = nullptr;
            np = 2; emode = 2; ldc = SEQ; sC = (long)DIM * SEQ;
            chi = g_oh + DNX; clo = nullptr;
            lda = DIM; ldb = DIM; sA = 0; sB = 0; kk = DIM; zi = 0;
        } else {
            if (by >= DIM / 128) return;
            int zz = bz - 1;
            Ah = g_wh[1]; Al = g_wl[1]; Bh = g_wh[0]; Bl = g_wl[0];
            np = 3; emode = 0; cf = g_mpart + (long)zz * NW;
            ldc = DIM; sC = 0; lda = DIM; ldb = DIM; sA = 0; sB = 0;
            kk = DIM / 4; kbase = zz * (DIM / 4); zi = 0;
        }
    }

    extern __shared__ char smem[];
    const uint32_t sbase = smem_u32(smem);
    const int tid  = threadIdx.x;        // 0..127
    const int lane = tid & 31;
    const int wid  = tid >> 5;           // 0..3
    const int wm   = wid >> 1;           // 0..1 : 64 rows
    const int wn   = wid & 1;            // 0..1 : 64 cols

    const int kmax    = kclamp ? min(kk, (by + 1) * 128) : kk;
    const int nchunks = kmax >> 5;       // BK = 32

    const f16* pAh = Ah + zi * sA + (long)by * 128 * lda;
    const f16* pAl = Al ? (Al + zi * sA + (long)by * 128 * lda) : nullptr;
    const f16* pBh = Bh + zi * sB + (long)bx * 128 * ldb;
    const f16* pBl = Bl ? (Bl + zi * sB + (long)bx * 128 * ldb) : nullptr;

    auto load_chunk = [&](int c) {
        const uint32_t st = sbase + (uint32_t)(c % STAGES) * STAGE_BYTES;
        const int k0 = kbase + (c << 5);
        #pragma unroll
        for (int i = 0; i < 4; i++) {
            int id  = tid + i * 128;       // 0..511
            int row = id >> 2, kc = id & 3;
            uint32_t so = swz(row, kc);
            long gA = (long)row * lda + k0 + kc * 8;
            long gB = (long)row * ldb + k0 + kc * 8;
            cp16(st +         so, pAh + gA);
            if (np >= 2) cp16(st +  8192 + so, pAl + gA);
            cp16(st + 16384 + so, pBh + gB);
            if (np == 3)  cp16(st + 24576 + so, pBl + gB);
        }
        CP_COMMIT();
    };

    float acc[4][8][4];
    #pragma unroll
    for (int i = 0; i < 4; i++)
        #pragma unroll
        for (int j = 0; j < 8; j++)
            #pragma unroll
            for (int p = 0; p < 4; p++) acc[i][j][p] = 0.f;

    load_chunk(0);
    if (nchunks > 1) load_chunk(1);

    const int lrow = lane & 15;
    const int lsel = lane >> 4;
    const int arow = wm * 64 + lrow;
    const int brow = wn * 64 + lrow;

    for (int c = 0; c < nchunks; c++) {
        if (c + 1 < nchunks) asm volatile("cp.async.wait_group 1;" ::: "memory");
        else                 asm volatile("cp.async.wait_group 0;" ::: "memory");
        __syncthreads();

        if (c + 2 < nchunks) load_chunk(c + 2);

        const uint32_t st  = sbase + (uint32_t)(c % STAGES) * STAGE_BYTES;
        const uint32_t sAh = st, sAl = st + 8192, sBh = st + 16384, sBl = st + 24576;

        #pragma unroll
        for (int ks = 0; ks < 2; ks++) {
            const int kc = ks * 2 + lsel;
            uint32_t bh[8][2];
            #pragma unroll
            for (int nq = 0; nq < 4; nq++) {
                int r = brow + nq * 16;
                uint32_t t4[4];
                ldsm_x4(t4, sBh + swz(r, kc));
                bh[nq*2][0] = t4[0]; bh[nq*2][1] = t4[2];
                bh[nq*2+1][0] = t4[1]; bh[nq*2+1][1] = t4[3];
            }
            uint32_t aH[4][4];
            #pragma unroll
            for (int mt = 0; mt < 4; mt++)
                ldsm_x4(aH[mt], sAh + swz(arow + mt * 16, kc));

            // pass 1: aH x bh
            #pragma unroll
            for (int mt = 0; mt < 4; mt++)
                #pragma unroll
                for (int nt = 0; nt < 8; nt++)
                    mma16816(acc[mt][nt], aH[mt], bh[nt]);

            // pass 2 (np==3): aH x bl
            if (np == 3) {
                uint32_t bl[8][2];
                #pragma unroll
                for (int nq = 0; nq < 4; nq++) {
                    int r = brow + nq * 16;
                    uint32_t t4[4];
                    ldsm_x4(t4, sBl + swz(r, kc));
                    bl[nq*2][0] = t4[0]; bl[nq*2][1] = t4[2];
                    bl[nq*2+1][0] = t4[1]; bl[nq*2+1][1] = t4[3];
                }
                #pragma unroll
                for (int mt = 0; mt < 4; mt++)
                    #pragma unroll
                    for (int nt = 0; nt < 8; nt++)
                        mma16816(acc[mt][nt], aH[mt], bl[nt]);
            }

            // pass 3 (np>=2): aL x bh (aL streamed)
            if (np >= 2) {
                uint32_t aL[2][4];
                ldsm_x4(aL[0], sAl + swz(arow, kc));
                #pragma unroll
                for (int mt = 0; mt < 4; mt++) {
                    const int cur = mt & 1;
                    if (mt < 3)
                        ldsm_x4(aL[cur ^ 1], sAl + swz(arow + (mt + 1) * 16, kc));
                    #pragma unroll
                    for (int nt = 0; nt < 8; nt++)
                        mma16816(acc[mt][nt], aL[cur], bh[nt]);
                }
            }
        }
    }

    // ---- epilogue: stage fp32 tile in smem, then coalesced global writes ----
    __syncthreads();
    float* buf = (float*)smem;
    {
        const int rq = lane >> 2;
        const int cq = (lane & 3) * 2;
        #pragma unroll
        for (int mt = 0; mt < 4; mt++)
            #pragma unroll
            for (int nt = 0; nt < 8; nt++) {
                int r0 = wm * 64 + mt * 16 + rq;
                int c0 = wn * 64 + nt * 8 + cq;
                *(float2*)&buf[r0 * EPI_LD + c0]       = make_float2(acc[mt][nt][0], acc[mt][nt][1]);
                *(float2*)&buf[(r0 + 8) * EPI_LD + c0] = make_float2(acc[mt][nt][2], acc[mt][nt][3]);
            }
    }
    __syncthreads();

    if (emode == 0) {
        int r = tid;
        long row = (long)by * 128 + r;
        float4* dst = (float4*)(cf + zi * sC + row * ldc + (long)bx * 128);
        #pragma unroll
        for (int i = 0; i < 32; i++)
            dst[i] = *(float4*)&buf[r * EPI_LD + i * 4];
    } else if (emode == 1) {
        int r = tid;
        long row = (long)by * 128 + r;
        f16* dh = chi + zi * sC + row * ldc + (long)bx * 128;
        f16* dl = clo ? (clo + zi * sC + row * ldc + (long)bx * 128) : nullptr;
        #pragma unroll
        for (int v = 0; v < 16; v++) {
            uint4 uh, ul;
            uint32_t* phh = (uint32_t*)&uh; uint32_t* pll = (uint32_t*)&ul;
            #pragma unroll
            for (int p = 0; p < 4; p++) {
                float f0 = buf[r * EPI_LD + v * 8 + p * 2];
                float f1 = buf[r * EPI_LD + v * 8 + p * 2 + 1];
                f16 h0, l0, h1, l1;
                fsplit(f0, h0, l0); fsplit(f1, h1, l1);
                phh[p] = (uint32_t)*(uint16_t*)&h0 | ((uint32_t)*(uint16_t*)&h1 << 16);
                pll[p] = (uint32_t)*(uint16_t*)&l0 | ((uint32_t)*(uint16_t*)&l1 << 16);
            }
            *(uint4*)(dh + v * 8) = uh;
            if (dl) *(uint4*)(dl + v * 8) = ul;
        }
    } else if (emode == 5) {
        // scaled f16 logits, hi only
        int r = tid;
        long row = (long)by * 128 + r;
        f16* dh = chi + zi * sC + row * ldc + (long)bx * 128;
        #pragma unroll
        for (int v = 0; v < 16; v++) {
            uint4 uh; uint32_t* phh = (uint32_t*)&uh;
            #pragma unroll
            for (int p = 0; p < 4; p++) {
                f16 h0 = __float2half_rn(buf[r * EPI_LD + v * 8 + p * 2]     * 0.03125f);
                f16 h1 = __float2half_rn(buf[r * EPI_LD + v * 8 + p * 2 + 1] * 0.03125f);
                phh[p] = (uint32_t)*(uint16_t*)&h0 | ((uint32_t)*(uint16_t*)&h1 << 16);
            }
            *(uint4*)(dh + v * 8) = uh;
        }
    } else {
        // emode 2: transposed out: Ct[e][s_local], batch derived from global row
        int cc = tid;
        int rowbase = by * 128;
        int b = rowbase / SEQ;
        int sloc = rowbase % SEQ;
        long e = (long)bx * 128 + cc;
        f16* dh = chi + b * sC + e * ldc + sloc;
        f16* dl = clo ? (clo + b * sC + e * ldc + sloc) : nullptr;
        #pragma unroll
        for (int v = 0; v < 16; v++) {
            uint4 uh, ul;
            uint32_t* phh = (uint32_t*)&uh; uint32_t* pll = (uint32_t*)&ul;
            #pragma unroll
            for (int p = 0; p < 4; p++) {
                float f0 = buf[(v * 8 + p * 2)     * EPI_LD + cc];
                float f1 = buf[(v * 8 + p * 2 + 1) * EPI_LD + cc];
                f16 h0, l0, h1, l1;
                fsplit(f0, h0, l0); fsplit(f1, h1, l1);
                phh[p] = (uint32_t)*(uint16_t*)&h0 | ((uint32_t)*(uint16_t*)&h1 << 16);
                pll[p] = (uint32_t)*(uint16_t*)&l0 | ((uint32_t)*(uint16_t*)&l1 << 16);
            }
            *(uint4*)(dh + v * 8) = uh;
            if (dl) *(uint4*)(dl + v * 8) = ul;
        }
    }
}

// ---------------- fp32 -> f16 hi/lo split ----------------
__device__ __forceinline__ void split4(const float* __restrict__ src,
                                       f16* __restrict__ hi, f16* __restrict__ lo, long i)
{
    float4 v = *(const float4*)(src + i);
    float f[4] = {v.x, v.y, v.z, v.w};
    uint32_t h2[2], l2[2];
    #pragma unroll
    for (int p = 0; p < 2; p++) {
        f16 h0, l0, h1, l1;
        fsplit(f[p*2],   h0, l0);
        fsplit(f[p*2+1], h1, l1);
        h2[p] = (uint32_t)*(uint16_t*)&h0 | ((uint32_t)*(uint16_t*)&h1 << 16);
        l2[p] = (uint32_t)*(uint16_t*)&l0 | ((uint32_t)*(uint16_t*)&l1 << 16);
    }
    *(uint2*)(hi + i) = make_uint2(h2[0], h2[1]);
    *(uint2*)(lo + i) = make_uint2(l2[0], l2[1]);
}

__global__ void __launch_bounds__(256) split_f32(
    const float* __restrict__ src, f16* __restrict__ hi, f16* __restrict__ lo, long n)
{
    long i = ((long)blockIdx.x * 256 + threadIdx.x) * 4;
    if (i >= n) return;
    split4(src, hi, lo, i);
}

// hi-only split (Wv)
__global__ void __launch_bounds__(256) split_hi(
    const float* __restrict__ src, f16* __restrict__ hi, long n)
{
    long i = ((long)blockIdx.x * 256 + threadIdx.x) * 4;
    if (i >= n) return;
    float4 v = *(const float4*)(src + i);
    float f[4] = {v.x, v.y, v.z, v.w};
    uint32_t h2[2];
    #pragma unroll
    for (int p = 0; p < 2; p++) {
        f16 h0 = __float2half_rn(f[p*2]);
        f16 h1 = __float2half_rn(f[p*2+1]);
        h2[p] = (uint32_t)*(uint16_t*)&h0 | ((uint32_t)*(uint16_t*)&h1 << 16);
    }
    *(uint2*)(hi + i) = make_uint2(h2[0], h2[1]);
}

// transpose + split for Wq (z=0) and Wk (z=1): out[d][e] = in[e][d]
__global__ void __launch_bounds__(256) tsplit_w(
    const float* __restrict__ w0, const float* __restrict__ w1,
    f16* __restrict__ hi, f16* __restrict__ lo)
{
    const float* src = (blockIdx.z == 0) ? w0 : w1;
    f16* dh = hi + (long)blockIdx.z * NW;
    f16* dl = lo + (long)blockIdx.z * NW;

    __shared__ float t[32][33];
    const int tx = threadIdx.x & 31;
    const int ty = threadIdx.x >> 5;   // 0..7
    int x = blockIdx.x * 32 + tx;
    #pragma unroll
    for (int j = 0; j < 4; j++) {
        int y = blockIdx.y * 32 + ty + j * 8;
        t[ty + j * 8][tx] = src[(long)y * DIM + x];
    }
    __syncthreads();
    int xo = blockIdx.y * 32 + tx;
    #pragma unroll
    for (int j = 0; j < 4; j++) {
        int yo = blockIdx.x * 32 + ty + j * 8;
        float f = t[tx][ty + j * 8];
        f16 h, l;
        fsplit(f, h, l);
        dh[(long)yo * DIM + xo] = h;
        dl[(long)yo * DIM + xo] = l;
    }
}

// reduce 4 fp32 partials -> f16 hi only
__global__ void __launch_bounds__(256) reduce4_hi(
    const float* __restrict__ part, f16* __restrict__ hi)
{
    long i = ((long)blockIdx.x * 256 + threadIdx.x) * 4;
    if (i >= NW) return;
    float4 s = *(const float4*)(part + i);
    #pragma unroll
    for (int j = 1; j < 4; j++) {
        float4 v = *(const float4*)(part + j * NW + i);
        s.x += v.x; s.y += v.y; s.z += v.z; s.w += v.w;
    }
    float f[4] = {s.x, s.y, s.z, s.w};
    uint32_t h2[2];
    #pragma unroll
    for (int p = 0; p < 2; p++) {
        f16 h0 = __float2half_rn(f[p*2]);
        f16 h1 = __float2half_rn(f[p*2+1]);
        h2[p] = (uint32_t)*(uint16_t*)&h0 | ((uint32_t)*(uint16_t*)&h1 << 16);
    }
    *(uint2*)(hi + i) = make_uint2(h2[0], h2[1]);
}

// ---------------- causal softmax IN PLACE on f16 logits ----------------
__global__ void __launch_bounds__(256) softmax_causal(f16* __restrict__ P)
{
    const long r = blockIdx.x;
    const int  q = (int)(r & (SEQ - 1));
    f16* row = P + r * SEQ;

    __shared__ float bufr[SEQ];
    __shared__ float red[256];

    const int tid = threadIdx.x;
    const int len = q + 1;

    float m = -1e30f;
    for (int k = tid; k < len; k += 256) {
        float v = __half2float(row[k]);      // pre-scaled logits
        bufr[k] = v;
        m = fmaxf(m, v);
    }
    red[tid] = m;
    __syncthreads();
    #pragma unroll
    for (int s = 128; s > 0; s >>= 1) {
        if (tid < s) red[tid] = fmaxf(red[tid], red[tid + s]);
        __syncthreads();
    }
    m = red[0];
    __syncthreads();

    float sum = 0.f;
    for (int k = tid; k < len; k += 256) {
        float e = __expf(bufr[k] - m);
        bufr[k] = e;
        sum += e;
    }
    red[tid] = sum;
    __syncthreads();
    #pragma unroll
    for (int s = 128; s > 0; s >>= 1) {
        if (tid < s) red[tid] += red[tid + s];
        __syncthreads();
    }
    const float inv = 1.0f / red[0];
    __syncthreads();

    for (int k = tid; k < len; k += 256)
        row[k] = __float2half_rn(bufr[k] * inv);
    const f16 z = __float2half(0.f);
    for (int k = len + tid; k < SEQ; k += 256) row[k] = z;
}

// ---------------------------------------------------------------------------
extern "C" void kernel_launch(void* const* d_in, const int* in_sizes, int n_in,
                              void* d_out, int out_size)
{
    const float* X  = (const float*)d_in[0];
    const float* Wq = (const float*)d_in[1];
    const float* Wk = (const float*)d_in[2];
    const float* Wv = (const float*)d_in[3];
    float* out = (float*)d_out;

    f16 *xh, *xl, *wh, *wl, *mh, *oh, *ph;
    float *mpart;
    cudaGetSymbolAddress((void**)&xh, g_xh);  cudaGetSymbolAddress((void**)&xl, g_xl);
    cudaGetSymbolAddress((void**)&wh, g_wh);  cudaGetSymbolAddress((void**)&wl, g_wl);
    cudaGetSymbolAddress((void**)&mh, g_mh);
    cudaGetSymbolAddress((void**)&mpart, g_mpart);
    cudaGetSymbolAddress((void**)&oh, g_oh);
    cudaGetSymbolAddress((void**)&ph, g_ph);

    cudaFuncSetAttribute(gemm_f16x, cudaFuncAttributeMaxDynamicSharedMemorySize, SMEM_TOTAL);

    const long nX = NX, nW = NW;
    const int M = BATCH * SEQ;  // 8192

    dim3 thr256(256);
    dim3 thr128(128);

    // splits
    split_f32<<<(unsigned)(nX / 1024), thr256>>>(X, xh, xl, nX);
    dim3 gT(DIM / 32, DIM / 32, 2);
    tsplit_w<<<gT, thr256>>>(Wq, Wk, wh, wl);
    split_hi<<<(unsigned)(nW / 1024), thr256>>>(Wv, wh + 2 * nW, nW);

    // fused: z=0 -> V^T proj, z=1..4 -> M' split-K slices (all from globals)
    dim3 gF(DIM / 128, M / 128, 5);
    gemm_f16x<<<gF, thr128, SMEM_TOTAL>>>(
        nullptr, nullptr, nullptr, nullptr, nullptr, nullptr, nullptr,
        0, 0, 0, 0, 0, 0, 0, 0, 0, 6, 0);

    reduce4_hi<<<(unsigned)(nW / 1024), thr256>>>(mpart, mh);

    // T = X_hi @ M'_hi^T (1-pass, hi-only out)
    dim3 gTT(DIM / 128, M / 128, 1);
    gemm_f16x<<<gTT, thr128, SMEM_TOTAL>>>(xh, nullptr, mh, nullptr,
        nullptr, oh, nullptr, DIM, DIM, DIM, DIM,
        0, 0, 0, 0, 0, 1, 1);

    // scores -> pre-scaled f16 logits into ph (causal tile skip), 1-pass
    dim3 gScore(SEQ / 128, SEQ / 128, BATCH);
    gemm_f16x<<<gScore, thr128, SMEM_TOTAL>>>(oh, nullptr, xh, nullptr,
        nullptr, ph, nullptr, DIM, DIM, DIM, SEQ,
        (long)SEQ * DIM, (long)SEQ * DIM, (long)SEQ * SEQ, 1, 0, 5, 1);

    // softmax in place (f16 logits -> f16 probs, hi only)
    softmax_causal<<<BATCH * SEQ, thr256>>>(ph);

    // out = P_hi @ V^T_hi per batch (k clamp, heavy-first), fp32 out; 1-pass
    dim3 gAV(DIM / 128, SEQ / 128, BATCH);
    gemm_f16x<<<gAV, thr128, SMEM_TOTAL>>>(ph, nullptr, oh + nX, nullptr,
        out, nullptr, nullptr, SEQ, SEQ, SEQ, DIM,
        (long)SEQ * SEQ, (long)DIM * SEQ, (long)SEQ * DIM, 0, 1, 0, 1);
}

// round 14
// speedup vs baseline: 2.5537x; 1.0995x over previous
#include <cuda_runtime.h>
#include <cuda_fp16.h>
#include <cstdint>

#define BATCH 4
#define SEQ   2048
#define DIM   1024

typedef __half f16;

static const long NX = (long)BATCH * SEQ * DIM;   // 8388608
static const long NW = (long)DIM * DIM;           // 1048576
#define DNX ((long)BATCH * SEQ * DIM)

// ---------------- scratch (device globals; allocation-free) ----------------
__device__ __align__(128) f16   g_xh[(long)BATCH*SEQ*DIM];
// [0]=Wq^T, [1]=Wk^T, [2]=Wv (hi only for Wv)
__device__ __align__(128) f16   g_wh[3][(long)DIM*DIM];
__device__ __align__(128) f16   g_wl[2][(long)DIM*DIM];
// M' split-K fp32 partials and final f16 hi
__device__ __align__(128) float g_mpart[4*(long)DIM*DIM];
__device__ __align__(128) f16   g_mh[(long)DIM*DIM];
// stacked outputs: [0]=T (hi), [1]=V^T (hi, [b][e][s])
__device__ __align__(128) f16   g_oh[2*(long)BATCH*SEQ*DIM];
// logits then probs (in-place softmax)
__device__ __align__(128) f16   g_ph[(long)BATCH*SEQ*SEQ];

// ---------------- PTX helpers (arch-generic; NO tcgen05) ----------------
__device__ __forceinline__ uint32_t smem_u32(const void* p) {
    uint32_t a;
    asm("{ .reg .u64 t; cvta.to.shared.u64 t, %1; cvt.u32.u64 %0, t; }" : "=r"(a) : "l"(p));
    return a;
}
__device__ __forceinline__ void cp16(uint32_t saddr, const void* g) {
    asm volatile("cp.async.cg.shared.global [%0], [%1], 16;" :: "r"(saddr), "l"(g) : "memory");
}
#define CP_COMMIT() asm volatile("cp.async.commit_group;" ::: "memory")

__device__ __forceinline__ void ldsm_x4(uint32_t* r, uint32_t addr) {
    asm volatile("ldmatrix.sync.aligned.m8n8.x4.shared.b16 {%0,%1,%2,%3}, [%4];"
        : "=r"(r[0]), "=r"(r[1]), "=r"(r[2]), "=r"(r[3]) : "r"(addr));
}
__device__ __forceinline__ void mma16816(float* c, const uint32_t* a, const uint32_t* b) {
    asm volatile("mma.sync.aligned.m16n8k16.row.col.f32.f16.f16.f32 "
        "{%0,%1,%2,%3}, {%4,%5,%6,%7}, {%8,%9}, {%0,%1,%2,%3};"
        : "+f"(c[0]), "+f"(c[1]), "+f"(c[2]), "+f"(c[3])
        : "r"(a[0]), "r"(a[1]), "r"(a[2]), "r"(a[3]), "r"(b[0]), "r"(b[1]));
}

__device__ __forceinline__ uint32_t swz(int row, int kc) {
    return (uint32_t)(row * 64 + ((kc ^ ((row >> 1) & 3)) << 4));
}

__device__ __forceinline__ void fsplit(float f, f16& h, f16& l) {
    h = __float2half_rn(f);
    l = __float2half_rn(f - __half2float(h));
}

// ---------------- SMEM layout ----------------
#define STAGES 3
#define STAGE_BYTES 32768
#define EPI_LD 132
#define SMEM_TOTAL (STAGES * STAGE_BYTES)

// =====================================================================
// fp16 hi/lo NT GEMM via mma.sync: 128x128 CTA tile, 128 threads,
// 4 warps x (64x64) warp tile.
// npass=3: hh + hl + lh ; npass=2: hh + lh ; npass=1: hh only
// mode 0: fp32 C
// mode 1: f16 C (hi; lo iff Clo != nullptr)
// mode 2: f16 C transposed (hi; lo iff Clo)
// mode 5: f16 C, scaled by 1/32, hi only  (scores -> logits)
// mode 6: fused (operands from device globals):
//         bz==0   -> V^T = X_hi @ Wv_hi^T (1-pass, mode-2 hi into g_oh+DNX)
//         bz=1..4 -> M' split-K slice bz-1 (3-pass, fp32 into g_mpart)
// =====================================================================
__global__ void __launch_bounds__(128, 2) gemm_f16x(
    const f16* __restrict__ Ahi, const f16* __restrict__ Alo,
    const f16* __restrict__ Bhi, const f16* __restrict__ Blo,
    float* __restrict__ Cf, f16* __restrict__ Chi, f16* __restrict__ Clo,
    int K, int ldA, int ldB, int ldC,
    long strideA, long strideB, long strideC,
    int causal, int kclamp, int mode, int npass)
{
    const int bx = blockIdx.x, bz = blockIdx.z;
    // heavy-tile-first dispatch when k-clamped
    const int by = kclamp ? ((int)gridDim.y - 1 - (int)blockIdx.y) : (int)blockIdx.y;
    if (causal && bx > by) return;

    // ---- resolve operands / submode ----
    const f16 *Ah = Ahi, *Al = Alo, *Bh = Bhi, *Bl = Blo;
    float* cf = Cf; f16 *chi = Chi, *clo = Clo;
    int emode = mode, ldc = ldC, np = npass, lda = ldA, ldb = ldB;
    long sA = strideA, sB = strideB, sC = strideC;
    int kk = K, kbase = 0, zi = bz;

    if (mode == 6) {
        if (bz == 0) {
            // V^T projection (1-pass, hi only)
            Ah = g_xh; Al = nullptr; Bh = g_wh[2]; Bl = nullptr;
            np = 1; emode = 2; ldc = SEQ; sC = (long)DIM * SEQ;
            chi = g_oh + DNX; clo = nullptr;
            lda = DIM; ldb = DIM; sA = 0; sB = 0; kk = DIM; zi = 0;
        } else {
            if (by >= DIM / 128) return;
            int zz = bz - 1;
            Ah = g_wh[1]; Al = g_wl[1]; Bh = g_wh[0]; Bl = g_wl[0];
            np = 3; emode = 0; cf = g_mpart + (long)zz * NW;
            ldc = DIM; sC = 0; lda = DIM; ldb = DIM; sA = 0; sB = 0;
            kk = DIM / 4; kbase = zz * (DIM / 4); zi = 0;
        }
    }

    extern __shared__ char smem[];
    const uint32_t sbase = smem_u32(smem);
    const int tid  = threadIdx.x;        // 0..127
    const int lane = tid & 31;
    const int wid  = tid >> 5;           // 0..3
    const int wm   = wid >> 1;           // 0..1 : 64 rows
    const int wn   = wid & 1;            // 0..1 : 64 cols

    const int kmax    = kclamp ? min(kk, (by + 1) * 128) : kk;
    const int nchunks = kmax >> 5;       // BK = 32

    const f16* pAh = Ah + zi * sA + (long)by * 128 * lda;
    const f16* pAl = Al ? (Al + zi * sA + (long)by * 128 * lda) : nullptr;
    const f16* pBh = Bh + zi * sB + (long)bx * 128 * ldb;
    const f16* pBl = Bl ? (Bl + zi * sB + (long)bx * 128 * ldb) : nullptr;

    auto load_chunk = [&](int c) {
        const uint32_t st = sbase + (uint32_t)(c % STAGES) * STAGE_BYTES;
        const int k0 = kbase + (c << 5);
        #pragma unroll
        for (int i = 0; i < 4; i++) {
            int id  = tid + i * 128;       // 0..511
            int row = id >> 2, kc = id & 3;
            uint32_t so = swz(row, kc);
            long gA = (long)row * lda + k0 + kc * 8;
            long gB = (long)row * ldb + k0 + kc * 8;
            cp16(st +         so, pAh + gA);
            if (np >= 2) cp16(st +  8192 + so, pAl + gA);
            cp16(st + 16384 + so, pBh + gB);
            if (np == 3)  cp16(st + 24576 + so, pBl + gB);
        }
        CP_COMMIT();
    };

    float acc[4][8][4];
    #pragma unroll
    for (int i = 0; i < 4; i++)
        #pragma unroll
        for (int j = 0; j < 8; j++)
            #pragma unroll
            for (int p = 0; p < 4; p++) acc[i][j][p] = 0.f;

    load_chunk(0);
    if (nchunks > 1) load_chunk(1);

    const int lrow = lane & 15;
    const int lsel = lane >> 4;
    const int arow = wm * 64 + lrow;
    const int brow = wn * 64 + lrow;

    for (int c = 0; c < nchunks; c++) {
        if (c + 1 < nchunks) asm volatile("cp.async.wait_group 1;" ::: "memory");
        else                 asm volatile("cp.async.wait_group 0;" ::: "memory");
        __syncthreads();

        if (c + 2 < nchunks) load_chunk(c + 2);

        const uint32_t st  = sbase + (uint32_t)(c % STAGES) * STAGE_BYTES;
        const uint32_t sAh = st, sAl = st + 8192, sBh = st + 16384, sBl = st + 24576;

        #pragma unroll
        for (int ks = 0; ks < 2; ks++) {
            const int kc = ks * 2 + lsel;
            uint32_t bh[8][2];
            #pragma unroll
            for (int nq = 0; nq < 4; nq++) {
                int r = brow + nq * 16;
                uint32_t t4[4];
                ldsm_x4(t4, sBh + swz(r, kc));
                bh[nq*2][0] = t4[0]; bh[nq*2][1] = t4[2];
                bh[nq*2+1][0] = t4[1]; bh[nq*2+1][1] = t4[3];
            }
            uint32_t aH[4][4];
            #pragma unroll
            for (int mt = 0; mt < 4; mt++)
                ldsm_x4(aH[mt], sAh + swz(arow + mt * 16, kc));

            // pass 1: aH x bh
            #pragma unroll
            for (int mt = 0; mt < 4; mt++)
                #pragma unroll
                for (int nt = 0; nt < 8; nt++)
                    mma16816(acc[mt][nt], aH[mt], bh[nt]);

            // pass 2 (np==3): aH x bl
            if (np == 3) {
                uint32_t bl[8][2];
                #pragma unroll
                for (int nq = 0; nq < 4; nq++) {
                    int r = brow + nq * 16;
                    uint32_t t4[4];
                    ldsm_x4(t4, sBl + swz(r, kc));
                    bl[nq*2][0] = t4[0]; bl[nq*2][1] = t4[2];
                    bl[nq*2+1][0] = t4[1]; bl[nq*2+1][1] = t4[3];
                }
                #pragma unroll
                for (int mt = 0; mt < 4; mt++)
                    #pragma unroll
                    for (int nt = 0; nt < 8; nt++)
                        mma16816(acc[mt][nt], aH[mt], bl[nt]);
            }

            // pass 3 (np>=2): aL x bh (aL streamed)
            if (np >= 2) {
                uint32_t aL[2][4];
                ldsm_x4(aL[0], sAl + swz(arow, kc));
                #pragma unroll
                for (int mt = 0; mt < 4; mt++) {
                    const int cur = mt & 1;
                    if (mt < 3)
                        ldsm_x4(aL[cur ^ 1], sAl + swz(arow + (mt + 1) * 16, kc));
                    #pragma unroll
                    for (int nt = 0; nt < 8; nt++)
                        mma16816(acc[mt][nt], aL[cur], bh[nt]);
                }
            }
        }
    }

    // ---- epilogue: stage fp32 tile in smem, then coalesced global writes ----
    __syncthreads();
    float* buf = (float*)smem;
    {
        const int rq = lane >> 2;
        const int cq = (lane & 3) * 2;
        #pragma unroll
        for (int mt = 0; mt < 4; mt++)
            #pragma unroll
            for (int nt = 0; nt < 8; nt++) {
                int r0 = wm * 64 + mt * 16 + rq;
                int c0 = wn * 64 + nt * 8 + cq;
                *(float2*)&buf[r0 * EPI_LD + c0]       = make_float2(acc[mt][nt][0], acc[mt][nt][1]);
                *(float2*)&buf[(r0 + 8) * EPI_LD + c0] = make_float2(acc[mt][nt][2], acc[mt][nt][3]);
            }
    }
    __syncthreads();

    if (emode == 0) {
        int r = tid;
        long row = (long)by * 128 + r;
        float4* dst = (float4*)(cf + zi * sC + row * ldc + (long)bx * 128);
        #pragma unroll
        for (int i = 0; i < 32; i++)
            dst[i] = *(float4*)&buf[r * EPI_LD + i * 4];
    } else if (emode == 1) {
        int r = tid;
        long row = (long)by * 128 + r;
        f16* dh = chi + zi * sC + row * ldc + (long)bx * 128;
        f16* dl = clo ? (clo + zi * sC + row * ldc + (long)bx * 128) : nullptr;
        #pragma unroll
        for (int v = 0; v < 16; v++) {
            uint4 uh, ul;
            uint32_t* phh = (uint32_t*)&uh; uint32_t* pll = (uint32_t*)&ul;
            #pragma unroll
            for (int p = 0; p < 4; p++) {
                float f0 = buf[r * EPI_LD + v * 8 + p * 2];
                float f1 = buf[r * EPI_LD + v * 8 + p * 2 + 1];
                f16 h0, l0, h1, l1;
                fsplit(f0, h0, l0); fsplit(f1, h1, l1);
                phh[p] = (uint32_t)*(uint16_t*)&h0 | ((uint32_t)*(uint16_t*)&h1 << 16);
                pll[p] = (uint32_t)*(uint16_t*)&l0 | ((uint32_t)*(uint16_t*)&l1 << 16);
            }
            *(uint4*)(dh + v * 8) = uh;
            if (dl) *(uint4*)(dl + v * 8) = ul;
        }
    } else if (emode == 5) {
        // scaled f16 logits, hi only
        int r = tid;
        long row = (long)by * 128 + r;
        f16* dh = chi + zi * sC + row * ldc + (long)bx * 128;
        #pragma unroll
        for (int v = 0; v < 16; v++) {
            uint4 uh; uint32_t* phh = (uint32_t*)&uh;
            #pragma unroll
            for (int p = 0; p < 4; p++) {
                f16 h0 = __float2half_rn(buf[r * EPI_LD + v * 8 + p * 2]     * 0.03125f);
                f16 h1 = __float2half_rn(buf[r * EPI_LD + v * 8 + p * 2 + 1] * 0.03125f);
                phh[p] = (uint32_t)*(uint16_t*)&h0 | ((uint32_t)*(uint16_t*)&h1 << 16);
            }
            *(uint4*)(dh + v * 8) = uh;
        }
    } else {
        // emode 2: transposed out: Ct[e][s_local], batch derived from global row
        int cc = tid;
        int rowbase = by * 128;
        int b = rowbase / SEQ;
        int sloc = rowbase % SEQ;
        long e = (long)bx * 128 + cc;
        f16* dh = chi + b * sC + e * ldc + sloc;
        #pragma unroll
        for (int v = 0; v < 16; v++) {
            uint4 uh;
            uint32_t* phh = (uint32_t*)&uh;
            #pragma unroll
            for (int p = 0; p < 4; p++) {
                f16 h0 = __float2half_rn(buf[(v * 8 + p * 2)     * EPI_LD + cc]);
                f16 h1 = __float2half_rn(buf[(v * 8 + p * 2 + 1) * EPI_LD + cc]);
                phh[p] = (uint32_t)*(uint16_t*)&h0 | ((uint32_t)*(uint16_t*)&h1 << 16);
            }
            *(uint4*)(dh + v * 8) = uh;
        }
    }
}

// ---------------- fp32 -> f16 splits ----------------
__global__ void __launch_bounds__(256) split_hi(
    const float* __restrict__ src, f16* __restrict__ hi, long n)
{
    long i = ((long)blockIdx.x * 256 + threadIdx.x) * 4;
    if (i >= n) return;
    float4 v = *(const float4*)(src + i);
    float f[4] = {v.x, v.y, v.z, v.w};
    uint32_t h2[2];
    #pragma unroll
    for (int p = 0; p < 2; p++) {
        f16 h0 = __float2half_rn(f[p*2]);
        f16 h1 = __float2half_rn(f[p*2+1]);
        h2[p] = (uint32_t)*(uint16_t*)&h0 | ((uint32_t)*(uint16_t*)&h1 << 16);
    }
    *(uint2*)(hi + i) = make_uint2(h2[0], h2[1]);
}

// transpose + split for Wq (z=0) and Wk (z=1): out[d][e] = in[e][d]
__global__ void __launch_bounds__(256) tsplit_w(
    const float* __restrict__ w0, const float* __restrict__ w1,
    f16* __restrict__ hi, f16* __restrict__ lo)
{
    const float* src = (blockIdx.z == 0) ? w0 : w1;
    f16* dh = hi + (long)blockIdx.z * NW;
    f16* dl = lo + (long)blockIdx.z * NW;

    __shared__ float t[32][33];
    const int tx = threadIdx.x & 31;
    const int ty = threadIdx.x >> 5;   // 0..7
    int x = blockIdx.x * 32 + tx;
    #pragma unroll
    for (int j = 0; j < 4; j++) {
        int y = blockIdx.y * 32 + ty + j * 8;
        t[ty + j * 8][tx] = src[(long)y * DIM + x];
    }
    __syncthreads();
    int xo = blockIdx.y * 32 + tx;
    #pragma unroll
    for (int j = 0; j < 4; j++) {
        int yo = blockIdx.x * 32 + ty + j * 8;
        float f = t[tx][ty + j * 8];
        f16 h, l;
        fsplit(f, h, l);
        dh[(long)yo * DIM + xo] = h;
        dl[(long)yo * DIM + xo] = l;
    }
}

// reduce 4 fp32 partials -> f16 hi only
__global__ void __launch_bounds__(256) reduce4_hi(
    const float* __restrict__ part, f16* __restrict__ hi)
{
    long i = ((long)blockIdx.x * 256 + threadIdx.x) * 4;
    if (i >= NW) return;
    float4 s = *(const float4*)(part + i);
    #pragma unroll
    for (int j = 1; j < 4; j++) {
        float4 v = *(const float4*)(part + j * NW + i);
        s.x += v.x; s.y += v.y; s.z += v.z; s.w += v.w;
    }
    float f[4] = {s.x, s.y, s.z, s.w};
    uint32_t h2[2];
    #pragma unroll
    for (int p = 0; p < 2; p++) {
        f16 h0 = __float2half_rn(f[p*2]);
        f16 h1 = __float2half_rn(f[p*2+1]);
        h2[p] = (uint32_t)*(uint16_t*)&h0 | ((uint32_t)*(uint16_t*)&h1 << 16);
    }
    *(uint2*)(hi + i) = make_uint2(h2[0], h2[1]);
}

// ---------------- causal softmax IN PLACE on f16 logits ----------------
// zero-fill only up to end of the row's own 128-block (AV k-clamp never
// reads beyond it)
__global__ void __launch_bounds__(256) softmax_causal(f16* __restrict__ P)
{
    const long r = blockIdx.x;
    const int  q = (int)(r & (SEQ - 1));
    f16* row = P + r * SEQ;

    __shared__ float bufr[SEQ];
    __shared__ float red[256];

    const int tid = threadIdx.x;
    const int len = q + 1;
    const int zend = ((q >> 7) + 1) << 7;   // round up to 128

    float m = -1e30f;
    for (int k = tid; k < len; k += 256) {
        float v = __half2float(row[k]);      // pre-scaled logits
        bufr[k] = v;
        m = fmaxf(m, v);
    }
    red[tid] = m;
    __syncthreads();
    #pragma unroll
    for (int s = 128; s > 0; s >>= 1) {
        if (tid < s) red[tid] = fmaxf(red[tid], red[tid + s]);
        __syncthreads();
    }
    m = red[0];
    __syncthreads();

    float sum = 0.f;
    for (int k = tid; k < len; k += 256) {
        float e = __expf(bufr[k] - m);
        bufr[k] = e;
        sum += e;
    }
    red[tid] = sum;
    __syncthreads();
    #pragma unroll
    for (int s = 128; s > 0; s >>= 1) {
        if (tid < s) red[tid] += red[tid + s];
        __syncthreads();
    }
    const float inv = 1.0f / red[0];
    __syncthreads();

    for (int k = tid; k < len; k += 256)
        row[k] = __float2half_rn(bufr[k] * inv);
    const f16 z = __float2half(0.f);
    for (int k = len + tid; k < zend; k += 256) row[k] = z;
}

// ---------------------------------------------------------------------------
extern "C" void kernel_launch(void* const* d_in, const int* in_sizes, int n_in,
                              void* d_out, int out_size)
{
    const float* X  = (const float*)d_in[0];
    const float* Wq = (const float*)d_in[1];
    const float* Wk = (const float*)d_in[2];
    const float* Wv = (const float*)d_in[3];
    float* out = (float*)d_out;

    f16 *xh, *wh, *wl, *mh, *oh, *ph;
    float *mpart;
    cudaGetSymbolAddress((void**)&xh, g_xh);
    cudaGetSymbolAddress((void**)&wh, g_wh);  cudaGetSymbolAddress((void**)&wl, g_wl);
    cudaGetSymbolAddress((void**)&mh, g_mh);
    cudaGetSymbolAddress((void**)&mpart, g_mpart);
    cudaGetSymbolAddress((void**)&oh, g_oh);
    cudaGetSymbolAddress((void**)&ph, g_ph);

    cudaFuncSetAttribute(gemm_f16x, cudaFuncAttributeMaxDynamicSharedMemorySize, SMEM_TOTAL);

    const long nX = NX, nW = NW;
    const int M = BATCH * SEQ;  // 8192

    dim3 thr256(256);
    dim3 thr128(128);

    // splits (X hi-only; Wq/Wk transpose hi+lo; Wv hi-only)
    split_hi<<<(unsigned)(nX / 1024), thr256>>>(X, xh, nX);
    dim3 gT(DIM / 32, DIM / 32, 2);
    tsplit_w<<<gT, thr256>>>(Wq, Wk, wh, wl);
    split_hi<<<(unsigned)(nW / 1024), thr256>>>(Wv, wh + 2 * nW, nW);

    // fused: z=0 -> V^T proj (1-pass), z=1..4 -> M' split-K slices (3-pass)
    dim3 gF(DIM / 128, M / 128, 5);
    gemm_f16x<<<gF, thr128, SMEM_TOTAL>>>(
        nullptr, nullptr, nullptr, nullptr, nullptr, nullptr, nullptr,
        0, 0, 0, 0, 0, 0, 0, 0, 0, 6, 0);

    reduce4_hi<<<(unsigned)(nW / 1024), thr256>>>(mpart, mh);

    // T = X_hi @ M'_hi^T (1-pass, hi-only out)
    dim3 gTT(DIM / 128, M / 128, 1);
    gemm_f16x<<<gTT, thr128, SMEM_TOTAL>>>(xh, nullptr, mh, nullptr,
        nullptr, oh, nullptr, DIM, DIM, DIM, DIM,
        0, 0, 0, 0, 0, 1, 1);

    // scores -> pre-scaled f16 logits into ph (causal tile skip), 1-pass
    dim3 gScore(SEQ / 128, SEQ / 128, BATCH);
    gemm_f16x<<<gScore, thr128, SMEM_TOTAL>>>(oh, nullptr, xh, nullptr,
        nullptr, ph, nullptr, DIM, DIM, DIM, SEQ,
        (long)SEQ * DIM, (long)SEQ * DIM, (long)SEQ * SEQ, 1, 0, 5, 1);

    // softmax in place (f16 logits -> f16 probs)
    softmax_causal<<<BATCH * SEQ, thr256>>>(ph);

    // out = P_hi @ V^T_hi per batch (k clamp, heavy-first), fp32 out; 1-pass
    dim3 gAV(DIM / 128, SEQ / 128, BATCH);
    gemm_f16x<<<gAV, thr128, SMEM_TOTAL>>>(ph, nullptr, oh + nX, nullptr,
        out, nullptr, nullptr, SEQ, SEQ, SEQ, DIM,
        (long)SEQ * SEQ, (long)DIM * SEQ, (long)SEQ * DIM, 0, 1, 0, 1);
}